// round 1
// baseline (speedup 1.0000x reference)
#include <cuda_runtime.h>

#define NN      50000
#define EE      800000
#define INDIM   256
#define HIDC    32
#define NHEADS  8
#define OUTDIM  64
#define C1      (NHEADS * HIDC)   // 256
#define NEGSLOPE 0.2f

// ---------------- scratch (device globals; no allocation at run time) -----
__device__ float g_xl1[(size_t)NN * C1];
__device__ float g_xr1[(size_t)NN * C1];
__device__ float g_score1[(size_t)EE * NHEADS];
__device__ float g_smax1[(size_t)NN * NHEADS];
__device__ float g_den1[(size_t)NN * NHEADS];
__device__ float g_agg1[(size_t)NN * C1];     // becomes h1 in place
__device__ float g_xl2[(size_t)NN * HIDC];
__device__ float g_xr2[(size_t)NN * HIDC];
__device__ float g_score2[EE];
__device__ float g_smax2[NN];
__device__ float g_den2[NN];
__device__ float g_agg2[(size_t)NN * HIDC];   // becomes h2 in place

// ---------------- helpers --------------------------------------------------
__device__ __forceinline__ float lrelu(float v) { return v > 0.f ? v : NEGSLOPE * v; }

__device__ __forceinline__ void atomicMaxFloat(float* addr, float v)
{
    if (v >= 0.f) atomicMax((int*)addr, __float_as_int(v));
    else          atomicMin((unsigned int*)addr, __float_as_uint(v));
}

__device__ __forceinline__ void red_add_v4(float* ptr, float4 v)
{
    asm volatile("red.global.add.v4.f32 [%0], {%1,%2,%3,%4};"
                 :: "l"(ptr), "f"(v.x), "f"(v.y), "f"(v.z), "f"(v.w)
                 : "memory");
}

// ---------------- generic register-tiled SGEMM + bias ----------------------
// BM=BN=64, BK=16, 256 threads, 4x4 per-thread microtile.
__global__ void sgemm_bias(const float* __restrict__ A, const float* __restrict__ B,
                           const float* __restrict__ bias, float* __restrict__ C,
                           int M, int N, int K)
{
    const int BM = 64, BN = 64, BK = 16;
    __shared__ float As[BK][BM + 1];
    __shared__ float Bs[BK][BN + 1];
    const int tid = threadIdx.x;
    const int tx = tid % 16;            // col group
    const int ty = tid / 16;            // row group
    const int rowBase = blockIdx.y * BM;
    const int colBase = blockIdx.x * BN;

    float acc[4][4] = {};

    for (int k0 = 0; k0 < K; k0 += BK) {
        {   // A tile: 64 rows x 16 cols, float4 along K
            int r = tid >> 2;                 // 0..63
            int c = (tid & 3) * 4;            // 0..12
            float4 v = make_float4(0.f, 0.f, 0.f, 0.f);
            if (rowBase + r < M)
                v = *reinterpret_cast<const float4*>(
                        &A[(size_t)(rowBase + r) * K + k0 + c]);
            As[c + 0][r] = v.x; As[c + 1][r] = v.y;
            As[c + 2][r] = v.z; As[c + 3][r] = v.w;
        }
        {   // B tile: 16 rows x 64 cols
            int r = tid >> 4;                 // 0..15
            int c = (tid & 15) * 4;           // 0..60
            float4 v = make_float4(0.f, 0.f, 0.f, 0.f);
            if (colBase + c + 3 < N)
                v = *reinterpret_cast<const float4*>(
                        &B[(size_t)(k0 + r) * N + colBase + c]);
            Bs[r][c + 0] = v.x; Bs[r][c + 1] = v.y;
            Bs[r][c + 2] = v.z; Bs[r][c + 3] = v.w;
        }
        __syncthreads();
#pragma unroll
        for (int kk = 0; kk < BK; kk++) {
            float a[4], b[4];
#pragma unroll
            for (int i = 0; i < 4; i++) a[i] = As[kk][ty * 4 + i];
#pragma unroll
            for (int j = 0; j < 4; j++) b[j] = Bs[kk][tx * 4 + j];
#pragma unroll
            for (int i = 0; i < 4; i++)
#pragma unroll
                for (int j = 0; j < 4; j++)
                    acc[i][j] = fmaf(a[i], b[j], acc[i][j]);
        }
        __syncthreads();
    }

#pragma unroll
    for (int i = 0; i < 4; i++) {
        int row = rowBase + ty * 4 + i;
        if (row >= M) continue;
#pragma unroll
        for (int j = 0; j < 4; j++) {
            int col = colBase + tx * 4 + j;
            if (col < N)
                C[(size_t)row * N + col] = acc[i][j] + bias[col];
        }
    }
}

// ---------------- init -----------------------------------------------------
__global__ void init1_k(float* __restrict__ smax, float* __restrict__ den,
                        float* __restrict__ agg)
{
    int i = blockIdx.x * blockDim.x + threadIdx.x;
    if (i < NN * NHEADS) { smax[i] = __int_as_float(0xff800000); den[i] = 0.f; }
    if (i < NN * C1)     agg[i] = 0.f;
}

__global__ void init2_k(float* __restrict__ smax, float* __restrict__ den,
                        float* __restrict__ agg)
{
    int i = blockIdx.x * blockDim.x + threadIdx.x;
    if (i < NN) { smax[i] = __int_as_float(0xff800000); den[i] = 0.f; }
    if (i < NN * HIDC) agg[i] = 0.f;
}

// ---------------- layer 1 edge kernels (8 heads x 32 ch) -------------------
// warp per edge; lane handles 8 channels; head = lane>>2
__global__ void edge_score1_k(const int* __restrict__ ei,
                              const float* __restrict__ xl, const float* __restrict__ xr,
                              const float* __restrict__ att,
                              float* __restrict__ score, float* __restrict__ smax)
{
    int gt = blockIdx.x * blockDim.x + threadIdx.x;
    int e = gt >> 5;
    if (e >= EE) return;
    int lane = threadIdx.x & 31;
    int s = ei[e];
    int d = ei[EE + e];
    const float4* pa = reinterpret_cast<const float4*>(xl + (size_t)s * C1) + lane * 2;
    const float4* pb = reinterpret_cast<const float4*>(xr + (size_t)d * C1) + lane * 2;
    float4 a0 = pa[0], a1 = pa[1];
    float4 b0 = pb[0], b1 = pb[1];
    int h = lane >> 2;
    const float4* pt = reinterpret_cast<const float4*>(att + h * HIDC + (lane & 3) * 8);
    float4 t0 = pt[0], t1 = pt[1];
    float p = lrelu(a0.x + b0.x) * t0.x + lrelu(a0.y + b0.y) * t0.y
            + lrelu(a0.z + b0.z) * t0.z + lrelu(a0.w + b0.w) * t0.w
            + lrelu(a1.x + b1.x) * t1.x + lrelu(a1.y + b1.y) * t1.y
            + lrelu(a1.z + b1.z) * t1.z + lrelu(a1.w + b1.w) * t1.w;
    p += __shfl_xor_sync(0xffffffffu, p, 1);
    p += __shfl_xor_sync(0xffffffffu, p, 2);
    if ((lane & 3) == 0) {
        score[(size_t)e * NHEADS + h] = p;
        atomicMaxFloat(&smax[(size_t)d * NHEADS + h], p);
    }
}

__global__ void edge_exp1_k(const int* __restrict__ ei, float* __restrict__ score,
                            const float* __restrict__ smax, float* __restrict__ den)
{
    int idx = blockIdx.x * blockDim.x + threadIdx.x;
    if (idx >= EE * NHEADS) return;
    int e = idx >> 3;
    int h = idx & 7;
    int d = ei[EE + e];
    float ex = expf(score[idx] - smax[(size_t)d * NHEADS + h]);
    score[idx] = ex;
    atomicAdd(&den[(size_t)d * NHEADS + h], ex);
}

__global__ void edge_agg1_k(const int* __restrict__ ei,
                            const float* __restrict__ xl,
                            const float* __restrict__ score, const float* __restrict__ den,
                            float* __restrict__ agg)
{
    int gt = blockIdx.x * blockDim.x + threadIdx.x;
    int e = gt >> 5;
    if (e >= EE) return;
    int lane = threadIdx.x & 31;
    int s = ei[e];
    int d = ei[EE + e];
    int h = lane >> 2;
    float alpha = score[(size_t)e * NHEADS + h] /
                  (den[(size_t)d * NHEADS + h] + 1e-16f);
    const float4* pa = reinterpret_cast<const float4*>(xl + (size_t)s * C1) + lane * 2;
    float4 a0 = pa[0], a1 = pa[1];
    a0.x *= alpha; a0.y *= alpha; a0.z *= alpha; a0.w *= alpha;
    a1.x *= alpha; a1.y *= alpha; a1.z *= alpha; a1.w *= alpha;
    float* dst = agg + (size_t)d * C1 + lane * 8;
    red_add_v4(dst, a0);
    red_add_v4(dst + 4, a1);
}

__global__ void finalize1_k(float* __restrict__ agg, const float* __restrict__ bias)
{
    int i = blockIdx.x * blockDim.x + threadIdx.x;
    if (i >= NN * C1) return;
    float v = agg[i] + bias[i & (C1 - 1)];
    agg[i] = v > 0.f ? v : expm1f(v);          // ELU, alpha = 1
}

// ---------------- layer 2 edge kernels (1 head x 32 ch) --------------------
__global__ void edge_score2_k(const int* __restrict__ ei,
                              const float* __restrict__ xl, const float* __restrict__ xr,
                              const float* __restrict__ att,
                              float* __restrict__ score, float* __restrict__ smax)
{
    int gt = blockIdx.x * blockDim.x + threadIdx.x;
    int e = gt >> 5;
    if (e >= EE) return;
    int lane = threadIdx.x & 31;
    int s = ei[e];
    int d = ei[EE + e];
    float v = lrelu(xl[(size_t)s * HIDC + lane] + xr[(size_t)d * HIDC + lane]);
    float p = v * att[lane];
    p += __shfl_xor_sync(0xffffffffu, p, 16);
    p += __shfl_xor_sync(0xffffffffu, p, 8);
    p += __shfl_xor_sync(0xffffffffu, p, 4);
    p += __shfl_xor_sync(0xffffffffu, p, 2);
    p += __shfl_xor_sync(0xffffffffu, p, 1);
    if (lane == 0) {
        score[e] = p;
        atomicMaxFloat(&smax[d], p);
    }
}

__global__ void edge_exp2_k(const int* __restrict__ ei, float* __restrict__ score,
                            const float* __restrict__ smax, float* __restrict__ den)
{
    int e = blockIdx.x * blockDim.x + threadIdx.x;
    if (e >= EE) return;
    int d = ei[EE + e];
    float ex = expf(score[e] - smax[d]);
    score[e] = ex;
    atomicAdd(&den[d], ex);
}

__global__ void edge_agg2_k(const int* __restrict__ ei,
                            const float* __restrict__ xl,
                            const float* __restrict__ score, const float* __restrict__ den,
                            float* __restrict__ agg)
{
    int gt = blockIdx.x * blockDim.x + threadIdx.x;
    int e = gt >> 5;
    if (e >= EE) return;
    int lane = threadIdx.x & 31;
    int s = ei[e];
    int d = ei[EE + e];
    float alpha = score[e] / (den[d] + 1e-16f);
    float v = alpha * xl[(size_t)s * HIDC + lane];
    atomicAdd(&agg[(size_t)d * HIDC + lane], v);
}

__global__ void finalize2_k(float* __restrict__ agg, const float* __restrict__ bias)
{
    int i = blockIdx.x * blockDim.x + threadIdx.x;
    if (i >= NN * HIDC) return;
    float v = agg[i] + bias[i & (HIDC - 1)];
    agg[i] = v > 0.f ? v : expm1f(v);
}

// ---------------- launch ----------------------------------------------------
extern "C" void kernel_launch(void* const* d_in, const int* in_sizes, int n_in,
                              void* d_out, int out_size)
{
    const float* x     = (const float*)d_in[0];
    const int*   ei    = (const int*)d_in[1];
    const float* W1l   = (const float*)d_in[2];
    const float* b1l   = (const float*)d_in[3];
    const float* W1r   = (const float*)d_in[4];
    const float* b1r   = (const float*)d_in[5];
    const float* att1  = (const float*)d_in[6];
    const float* bias1 = (const float*)d_in[7];
    const float* W2l   = (const float*)d_in[8];
    const float* b2l   = (const float*)d_in[9];
    const float* W2r   = (const float*)d_in[10];
    const float* b2r   = (const float*)d_in[11];
    const float* att2  = (const float*)d_in[12];
    const float* bias2 = (const float*)d_in[13];
    const float* Wlin  = (const float*)d_in[14];
    const float* blin  = (const float*)d_in[15];
    float* out = (float*)d_out;

    float *xl1, *xr1, *sc1, *sm1, *dn1, *ag1;
    float *xl2, *xr2, *sc2, *sm2, *dn2, *ag2;
    cudaGetSymbolAddress((void**)&xl1, g_xl1);
    cudaGetSymbolAddress((void**)&xr1, g_xr1);
    cudaGetSymbolAddress((void**)&sc1, g_score1);
    cudaGetSymbolAddress((void**)&sm1, g_smax1);
    cudaGetSymbolAddress((void**)&dn1, g_den1);
    cudaGetSymbolAddress((void**)&ag1, g_agg1);
    cudaGetSymbolAddress((void**)&xl2, g_xl2);
    cudaGetSymbolAddress((void**)&xr2, g_xr2);
    cudaGetSymbolAddress((void**)&sc2, g_score2);
    cudaGetSymbolAddress((void**)&sm2, g_smax2);
    cudaGetSymbolAddress((void**)&dn2, g_den2);
    cudaGetSymbolAddress((void**)&ag2, g_agg2);

    const int TPB = 256;
    dim3 blk(TPB);

    // ---- layer 1: dense transforms ----
    dim3 gg1((C1 + 63) / 64, (NN + 63) / 64);
    sgemm_bias<<<gg1, blk>>>(x, W1l, b1l, xl1, NN, C1, INDIM);
    sgemm_bias<<<gg1, blk>>>(x, W1r, b1r, xr1, NN, C1, INDIM);

    init1_k<<<(NN * C1 + TPB - 1) / TPB, blk>>>(sm1, dn1, ag1);

    int eblocks = (EE * 32 + TPB - 1) / TPB;
    edge_score1_k<<<eblocks, blk>>>(ei, xl1, xr1, att1, sc1, sm1);
    edge_exp1_k<<<(EE * NHEADS + TPB - 1) / TPB, blk>>>(ei, sc1, sm1, dn1);
    edge_agg1_k<<<eblocks, blk>>>(ei, xl1, sc1, dn1, ag1);
    finalize1_k<<<(NN * C1 + TPB - 1) / TPB, blk>>>(ag1, bias1);   // ag1 = h1

    // ---- layer 2: dense transforms ----
    dim3 gg2((HIDC + 63) / 64, (NN + 63) / 64);
    sgemm_bias<<<gg2, blk>>>(ag1, W2l, b2l, xl2, NN, HIDC, C1);
    sgemm_bias<<<gg2, blk>>>(ag1, W2r, b2r, xr2, NN, HIDC, C1);

    init2_k<<<(NN * HIDC + TPB - 1) / TPB, blk>>>(sm2, dn2, ag2);

    edge_score2_k<<<eblocks, blk>>>(ei, xl2, xr2, att2, sc2, sm2);
    edge_exp2_k<<<(EE + TPB - 1) / TPB, blk>>>(ei, sc2, sm2, dn2);
    edge_agg2_k<<<eblocks, blk>>>(ei, xl2, sc2, dn2, ag2);
    finalize2_k<<<(NN * HIDC + TPB - 1) / TPB, blk>>>(ag2, bias2); // ag2 = h2

    // ---- final linear head ----
    dim3 gg3((OUTDIM + 63) / 64, (NN + 63) / 64);
    sgemm_bias<<<gg3, blk>>>(ag2, Wlin, blin, out, NN, OUTDIM, HIDC);
}

// round 2
// speedup vs baseline: 1.8349x; 1.8349x over previous
#include <cuda_runtime.h>

#define NN      50000
#define EE      800000
#define INDIM   256
#define HIDC    32
#define NHEADS  8
#define OUTDIM  64
#define C1      (NHEADS * HIDC)   // 256
#define NEGSLOPE 0.2f

// ---------------- scratch (device globals) ---------------------------------
__device__ float g_xlr1[(size_t)NN * 512];   // [xl1 | xr1] per row
__device__ float g_h1  [(size_t)NN * C1];
__device__ float g_xlr2[(size_t)NN * 64];    // [xl2 | xr2] per row
__device__ float g_h2  [(size_t)NN * HIDC];
__device__ int   g_deg   [NN];
__device__ int   g_rowptr[NN];
__device__ int   g_cursor[NN];
__device__ int   g_csrc  [EE];
__device__ int   g_bsums [256];              // (NN+255)/256 = 196 partials

// ---------------- helpers ---------------------------------------------------
__device__ __forceinline__ float lrelu(float v) { return v > 0.f ? v : NEGSLOPE * v; }
__device__ __forceinline__ float elu(float v)   { return v > 0.f ? v : expm1f(v); }

// ---------------- dual-output SGEMM: C = [A@Wl+bl | A@Wr+br] ----------------
// BM=BN=64, BK=16, 256 threads, 4x4 microtile. Ntot = 2*nc.
__global__ __launch_bounds__(256)
void sgemm_dual(const float* __restrict__ A,
                const float* __restrict__ Wl, const float* __restrict__ bl,
                const float* __restrict__ Wr, const float* __restrict__ br,
                float* __restrict__ C, int M, int nc, int K)
{
    const int BM = 64, BN = 64, BK = 16;
    const int Ntot = 2 * nc;
    __shared__ float As[BK][BM + 1];
    __shared__ float Bs[BK][BN + 1];
    const int tid = threadIdx.x;
    const int tx = tid % 16;
    const int ty = tid / 16;
    const int rowBase = blockIdx.y * BM;
    const int colBase = blockIdx.x * BN;

    float acc[4][4] = {};

    for (int k0 = 0; k0 < K; k0 += BK) {
        {   // A tile
            int r = tid >> 2;
            int c = (tid & 3) * 4;
            float4 v = make_float4(0.f, 0.f, 0.f, 0.f);
            if (rowBase + r < M)
                v = *reinterpret_cast<const float4*>(
                        &A[(size_t)(rowBase + r) * K + k0 + c]);
            As[c + 0][r] = v.x; As[c + 1][r] = v.y;
            As[c + 2][r] = v.z; As[c + 3][r] = v.w;
        }
        {   // B tile, split between Wl / Wr (boundary is a multiple of 4)
            int r = tid >> 4;
            int c = (tid & 15) * 4;
            int col = colBase + c;
            float4 v;
            if (col < nc)
                v = *reinterpret_cast<const float4*>(&Wl[(size_t)(k0 + r) * nc + col]);
            else
                v = *reinterpret_cast<const float4*>(&Wr[(size_t)(k0 + r) * nc + col - nc]);
            Bs[r][c + 0] = v.x; Bs[r][c + 1] = v.y;
            Bs[r][c + 2] = v.z; Bs[r][c + 3] = v.w;
        }
        __syncthreads();
#pragma unroll
        for (int kk = 0; kk < BK; kk++) {
            float a[4], b[4];
#pragma unroll
            for (int i = 0; i < 4; i++) a[i] = As[kk][ty * 4 + i];
#pragma unroll
            for (int j = 0; j < 4; j++) b[j] = Bs[kk][tx * 4 + j];
#pragma unroll
            for (int i = 0; i < 4; i++)
#pragma unroll
                for (int j = 0; j < 4; j++)
                    acc[i][j] = fmaf(a[i], b[j], acc[i][j]);
        }
        __syncthreads();
    }

#pragma unroll
    for (int i = 0; i < 4; i++) {
        int row = rowBase + ty * 4 + i;
        if (row >= M) continue;
#pragma unroll
        for (int j = 0; j < 4; j++) {
            int col = colBase + tx * 4 + j;
            float bv = (col < nc) ? bl[col] : br[col - nc];
            C[(size_t)row * Ntot + col] = acc[i][j] + bv;
        }
    }
}

// ---------------- plain SGEMM + bias (head) ---------------------------------
__global__ __launch_bounds__(256)
void sgemm_bias(const float* __restrict__ A, const float* __restrict__ B,
                const float* __restrict__ bias, float* __restrict__ C,
                int M, int N, int K)
{
    const int BM = 64, BN = 64, BK = 16;
    __shared__ float As[BK][BM + 1];
    __shared__ float Bs[BK][BN + 1];
    const int tid = threadIdx.x;
    const int tx = tid % 16;
    const int ty = tid / 16;
    const int rowBase = blockIdx.y * BM;
    const int colBase = blockIdx.x * BN;

    float acc[4][4] = {};

    for (int k0 = 0; k0 < K; k0 += BK) {
        {
            int r = tid >> 2;
            int c = (tid & 3) * 4;
            float4 v = make_float4(0.f, 0.f, 0.f, 0.f);
            if (rowBase + r < M)
                v = *reinterpret_cast<const float4*>(
                        &A[(size_t)(rowBase + r) * K + k0 + c]);
            As[c + 0][r] = v.x; As[c + 1][r] = v.y;
            As[c + 2][r] = v.z; As[c + 3][r] = v.w;
        }
        {
            int r = tid >> 4;
            int c = (tid & 15) * 4;
            float4 v = make_float4(0.f, 0.f, 0.f, 0.f);
            if (colBase + c + 3 < N)
                v = *reinterpret_cast<const float4*>(
                        &B[(size_t)(k0 + r) * N + colBase + c]);
            Bs[r][c + 0] = v.x; Bs[r][c + 1] = v.y;
            Bs[r][c + 2] = v.z; Bs[r][c + 3] = v.w;
        }
        __syncthreads();
#pragma unroll
        for (int kk = 0; kk < BK; kk++) {
            float a[4], b[4];
#pragma unroll
            for (int i = 0; i < 4; i++) a[i] = As[kk][ty * 4 + i];
#pragma unroll
            for (int j = 0; j < 4; j++) b[j] = Bs[kk][tx * 4 + j];
#pragma unroll
            for (int i = 0; i < 4; i++)
#pragma unroll
                for (int j = 0; j < 4; j++)
                    acc[i][j] = fmaf(a[i], b[j], acc[i][j]);
        }
        __syncthreads();
    }

#pragma unroll
    for (int i = 0; i < 4; i++) {
        int row = rowBase + ty * 4 + i;
        if (row >= M) continue;
#pragma unroll
        for (int j = 0; j < 4; j++) {
            int col = colBase + tx * 4 + j;
            if (col < N)
                C[(size_t)row * N + col] = acc[i][j] + bias[col];
        }
    }
}

// ---------------- CSR construction ------------------------------------------
__global__ void zero_deg_k(int* __restrict__ deg)
{
    int i = blockIdx.x * blockDim.x + threadIdx.x;
    if (i < NN) deg[i] = 0;
}

__global__ void hist_k(const int* __restrict__ ei, int* __restrict__ deg)
{
    int e = blockIdx.x * blockDim.x + threadIdx.x;
    if (e < EE) atomicAdd(&deg[ei[EE + e]], 1);
}

__global__ void scan1_k(const int* __restrict__ deg, int* __restrict__ rowptr,
                        int* __restrict__ bsums)
{
    __shared__ int sh[256];
    int tid = threadIdx.x;
    int i = blockIdx.x * 256 + tid;
    int v = (i < NN) ? deg[i] : 0;
    sh[tid] = v;
    __syncthreads();
#pragma unroll
    for (int off = 1; off < 256; off <<= 1) {
        int t = (tid >= off) ? sh[tid - off] : 0;
        __syncthreads();
        sh[tid] += t;
        __syncthreads();
    }
    if (i < NN) rowptr[i] = sh[tid] - v;            // block-local exclusive
    if (tid == 255) bsums[blockIdx.x] = sh[255];
}

__global__ void scan2_k(int* __restrict__ bsums, int nb)
{
    __shared__ int sh[256];
    int tid = threadIdx.x;
    int v = (tid < nb) ? bsums[tid] : 0;
    sh[tid] = v;
    __syncthreads();
#pragma unroll
    for (int off = 1; off < 256; off <<= 1) {
        int t = (tid >= off) ? sh[tid - off] : 0;
        __syncthreads();
        sh[tid] += t;
        __syncthreads();
    }
    if (tid < nb) bsums[tid] = sh[tid] - v;         // exclusive
}

__global__ void scan3_k(int* __restrict__ rowptr, const int* __restrict__ bsums,
                        int* __restrict__ cursor)
{
    int i = blockIdx.x * blockDim.x + threadIdx.x;
    if (i >= NN) return;
    int r = rowptr[i] + bsums[i >> 8];
    rowptr[i] = r;
    cursor[i] = r;
}

__global__ void scatter_k(const int* __restrict__ ei, int* __restrict__ cursor,
                          int* __restrict__ csrc)
{
    int e = blockIdx.x * blockDim.x + threadIdx.x;
    if (e >= EE) return;
    int d = ei[EE + e];
    int pos = atomicAdd(&cursor[d], 1);
    csrc[pos] = ei[e];
}

// ---------------- fused GATv2 edge phase, layer 1 (8 heads x 32 ch) ---------
// warp per dst node; lane covers 8 channels (lane*8 = head*32 + sub*8)
__global__ __launch_bounds__(256)
void edge_fused1_k(const int* __restrict__ rowptr, const int* __restrict__ deg,
                   const int* __restrict__ csrc, const float* __restrict__ xlr,
                   const float* __restrict__ att, const float* __restrict__ bias,
                   float* __restrict__ h1)
{
    int w = (blockIdx.x * blockDim.x + threadIdx.x) >> 5;
    if (w >= NN) return;
    int lane = threadIdx.x & 31;

    const float4* pb = reinterpret_cast<const float4*>(
        xlr + (size_t)w * 512 + 256 + lane * 8);
    float4 b0 = pb[0], b1 = pb[1];
    const float4* pt = reinterpret_cast<const float4*>(att + lane * 8);
    float4 t0 = pt[0], t1 = pt[1];

    float acc[8] = {};
    float den = 0.f;

    int start = rowptr[w];
    int dg    = deg[w];
    int s = (dg > 0) ? csrc[start] : 0;
    for (int i = 0; i < dg; i++) {
        int snext = (i + 1 < dg) ? csrc[start + i + 1] : s;
        const float4* pa = reinterpret_cast<const float4*>(
            xlr + (size_t)s * 512 + lane * 8);
        float4 a0 = pa[0], a1 = pa[1];
        float p = lrelu(a0.x + b0.x) * t0.x + lrelu(a0.y + b0.y) * t0.y
                + lrelu(a0.z + b0.z) * t0.z + lrelu(a0.w + b0.w) * t0.w
                + lrelu(a1.x + b1.x) * t1.x + lrelu(a1.y + b1.y) * t1.y
                + lrelu(a1.z + b1.z) * t1.z + lrelu(a1.w + b1.w) * t1.w;
        p += __shfl_xor_sync(0xffffffffu, p, 1);
        p += __shfl_xor_sync(0xffffffffu, p, 2);
        float ex = __expf(p);              // softmax shift dropped (scores O(1))
        den += ex;
        acc[0] += ex * a0.x; acc[1] += ex * a0.y;
        acc[2] += ex * a0.z; acc[3] += ex * a0.w;
        acc[4] += ex * a1.x; acc[5] += ex * a1.y;
        acc[6] += ex * a1.z; acc[7] += ex * a1.w;
        s = snext;
    }

    float inv = 1.f / (den + 1e-16f);
    const float* bi = bias + lane * 8;
    float4 o0, o1;
    o0.x = elu(acc[0] * inv + bi[0]); o0.y = elu(acc[1] * inv + bi[1]);
    o0.z = elu(acc[2] * inv + bi[2]); o0.w = elu(acc[3] * inv + bi[3]);
    o1.x = elu(acc[4] * inv + bi[4]); o1.y = elu(acc[5] * inv + bi[5]);
    o1.z = elu(acc[6] * inv + bi[6]); o1.w = elu(acc[7] * inv + bi[7]);
    float4* out = reinterpret_cast<float4*>(h1 + (size_t)w * C1 + lane * 8);
    out[0] = o0; out[1] = o1;
}

// ---------------- fused edge phase, layer 2 (1 head x 32 ch) ----------------
__global__ __launch_bounds__(256)
void edge_fused2_k(const int* __restrict__ rowptr, const int* __restrict__ deg,
                   const int* __restrict__ csrc, const float* __restrict__ xlr,
                   const float* __restrict__ att, const float* __restrict__ bias,
                   float* __restrict__ h2)
{
    int w = (blockIdx.x * blockDim.x + threadIdx.x) >> 5;
    if (w >= NN) return;
    int lane = threadIdx.x & 31;

    float b = xlr[(size_t)w * 64 + 32 + lane];
    float t = att[lane];

    float acc = 0.f, den = 0.f;
    int start = rowptr[w];
    int dg    = deg[w];
    int s = (dg > 0) ? csrc[start] : 0;
    for (int i = 0; i < dg; i++) {
        int snext = (i + 1 < dg) ? csrc[start + i + 1] : s;
        float a = xlr[(size_t)s * 64 + lane];
        float p = lrelu(a + b) * t;
        p += __shfl_xor_sync(0xffffffffu, p, 16);
        p += __shfl_xor_sync(0xffffffffu, p, 8);
        p += __shfl_xor_sync(0xffffffffu, p, 4);
        p += __shfl_xor_sync(0xffffffffu, p, 2);
        p += __shfl_xor_sync(0xffffffffu, p, 1);
        float ex = __expf(p);
        den += ex;
        acc += ex * a;
        s = snext;
    }
    float inv = 1.f / (den + 1e-16f);
    h2[(size_t)w * HIDC + lane] = elu(acc * inv + bias[lane]);
}

// ---------------- launch ------------------------------------------------------
extern "C" void kernel_launch(void* const* d_in, const int* in_sizes, int n_in,
                              void* d_out, int out_size)
{
    const float* x     = (const float*)d_in[0];
    const int*   ei    = (const int*)d_in[1];
    const float* W1l   = (const float*)d_in[2];
    const float* b1l   = (const float*)d_in[3];
    const float* W1r   = (const float*)d_in[4];
    const float* b1r   = (const float*)d_in[5];
    const float* att1  = (const float*)d_in[6];
    const float* bias1 = (const float*)d_in[7];
    const float* W2l   = (const float*)d_in[8];
    const float* b2l   = (const float*)d_in[9];
    const float* W2r   = (const float*)d_in[10];
    const float* b2r   = (const float*)d_in[11];
    const float* att2  = (const float*)d_in[12];
    const float* bias2 = (const float*)d_in[13];
    const float* Wlin  = (const float*)d_in[14];
    const float* blin  = (const float*)d_in[15];
    float* out = (float*)d_out;

    float *xlr1, *h1, *xlr2, *h2;
    int *deg, *rowptr, *cursor, *csrc, *bsums;
    cudaGetSymbolAddress((void**)&xlr1, g_xlr1);
    cudaGetSymbolAddress((void**)&h1,   g_h1);
    cudaGetSymbolAddress((void**)&xlr2, g_xlr2);
    cudaGetSymbolAddress((void**)&h2,   g_h2);
    cudaGetSymbolAddress((void**)&deg,    g_deg);
    cudaGetSymbolAddress((void**)&rowptr, g_rowptr);
    cudaGetSymbolAddress((void**)&cursor, g_cursor);
    cudaGetSymbolAddress((void**)&csrc,   g_csrc);
    cudaGetSymbolAddress((void**)&bsums,  g_bsums);

    const int TPB = 256;
    const int nScanBlocks = (NN + 255) / 256;       // 196

    // ---- CSR build (overlappable with GEMM1 in issue order) ----
    zero_deg_k<<<(NN + TPB - 1) / TPB, TPB>>>(deg);
    hist_k<<<(EE + TPB - 1) / TPB, TPB>>>(ei, deg);
    scan1_k<<<nScanBlocks, 256>>>(deg, rowptr, bsums);
    scan2_k<<<1, 256>>>(bsums, nScanBlocks);
    scan3_k<<<(NN + TPB - 1) / TPB, TPB>>>(rowptr, bsums, cursor);
    scatter_k<<<(EE + TPB - 1) / TPB, TPB>>>(ei, cursor, csrc);

    // ---- layer 1 ----
    dim3 gg1((512 + 63) / 64, (NN + 63) / 64);
    sgemm_dual<<<gg1, TPB>>>(x, W1l, b1l, W1r, b1r, xlr1, NN, C1, INDIM);

    int eblocks = (NN * 32 + TPB - 1) / TPB;
    edge_fused1_k<<<eblocks, TPB>>>(rowptr, deg, csrc, xlr1, att1, bias1, h1);

    // ---- layer 2 ----
    dim3 gg2(1, (NN + 63) / 64);
    sgemm_dual<<<gg2, TPB>>>(h1, W2l, b2l, W2r, b2r, xlr2, NN, HIDC, C1);

    edge_fused2_k<<<eblocks, TPB>>>(rowptr, deg, csrc, xlr2, att2, bias2, h2);

    // ---- head ----
    dim3 gg3((OUTDIM + 63) / 64, (NN + 63) / 64);
    sgemm_bias<<<gg3, TPB>>>(h2, Wlin, blin, out, NN, OUTDIM, HIDC);
}

// round 4
// speedup vs baseline: 2.4356x; 1.3274x over previous
#include <cuda_runtime.h>

#define NN      50000
#define EE      800000
#define INDIM   256
#define HIDC    32
#define NHEADS  8
#define OUTDIM  64
#define C1      (NHEADS * HIDC)   // 256
#define NEGSLOPE 0.2f

// ---------------- scratch (device globals) ---------------------------------
__device__ float g_xl1[(size_t)NN * C1];     // dense: 51.2 MB, L2-resident
__device__ float g_xr1[(size_t)NN * C1];
__device__ float g_h1 [(size_t)NN * C1];
__device__ float g_xl2[(size_t)NN * HIDC];
__device__ float g_xr2[(size_t)NN * HIDC];
__device__ float g_h2 [(size_t)NN * HIDC];
__device__ int   g_deg   [NN];
__device__ int   g_rowptr[NN];
__device__ int   g_cursor[NN];
__device__ int   g_csrc  [EE];
__device__ int   g_bsums [256];

// ---------------- helpers ---------------------------------------------------
__device__ __forceinline__ float lrelu(float v) { return v > 0.f ? v : NEGSLOPE * v; }
__device__ __forceinline__ float elu(float v)   { return v > 0.f ? v : expm1f(v); }

// ============================================================================
// Big dual SGEMM for layer 1: 128x128 tile, BK=16, double-buffered, 8x8 micro
// N_total = 512 (Wl|Wr), K = 256. Each 128-wide col block is entirely in one W.
// ============================================================================
__global__ __launch_bounds__(256, 2)
void sgemm128_dual(const float* __restrict__ A,
                   const float* __restrict__ Wl, const float* __restrict__ bl,
                   const float* __restrict__ Wr, const float* __restrict__ br,
                   float* __restrict__ Xl, float* __restrict__ Xr)
{
    const int M = NN, K = INDIM, NC = C1;
    __shared__ float As[2][16][128 + 4];
    __shared__ float Bs[2][16][128];

    const int tid = threadIdx.x;
    const int tx = tid & 15;          // 0..15 col group
    const int ty = tid >> 4;          // 0..15 row group
    const int rowBase = blockIdx.y * 128;
    int colBase = blockIdx.x * 128;

    const float* W;  const float* bias;  float* X;
    if (colBase < NC) { W = Wl; bias = bl; X = Xl; }
    else              { W = Wr; bias = br; X = Xr; colBase -= NC; }

    // global-load index split
    const int ar = tid >> 2;          // 0..63 (A row within tile, +64 second)
    const int ac = (tid & 3) * 4;     // 0,4,8,12 (A k-col)
    const int kr = tid >> 4;          // 0..15 (B k-row)
    const int bc = (tid & 15) * 4;    // 0..60 (B col, +64 second)

    const int r0 = min(rowBase + ar,      M - 1);
    const int r1 = min(rowBase + ar + 64, M - 1);

    float4 aR0, aR1, bR0, bR1;

    // stage 0
    aR0 = *reinterpret_cast<const float4*>(&A[(size_t)r0 * K + 0 + ac]);
    aR1 = *reinterpret_cast<const float4*>(&A[(size_t)r1 * K + 0 + ac]);
    bR0 = *reinterpret_cast<const float4*>(&W[(size_t)(0 + kr) * NC + colBase + bc]);
    bR1 = *reinterpret_cast<const float4*>(&W[(size_t)(0 + kr) * NC + colBase + bc + 64]);

    As[0][ac + 0][ar] = aR0.x; As[0][ac + 1][ar] = aR0.y;
    As[0][ac + 2][ar] = aR0.z; As[0][ac + 3][ar] = aR0.w;
    As[0][ac + 0][ar + 64] = aR1.x; As[0][ac + 1][ar + 64] = aR1.y;
    As[0][ac + 2][ar + 64] = aR1.z; As[0][ac + 3][ar + 64] = aR1.w;
    *reinterpret_cast<float4*>(&Bs[0][kr][bc])      = bR0;
    *reinterpret_cast<float4*>(&Bs[0][kr][bc + 64]) = bR1;
    __syncthreads();

    float acc[8][8] = {};
    int buf = 0;

    for (int k0 = 0; k0 < K; k0 += 16) {
        const bool more = (k0 + 16 < K);
        if (more) {
            int kn = k0 + 16;
            aR0 = *reinterpret_cast<const float4*>(&A[(size_t)r0 * K + kn + ac]);
            aR1 = *reinterpret_cast<const float4*>(&A[(size_t)r1 * K + kn + ac]);
            bR0 = *reinterpret_cast<const float4*>(&W[(size_t)(kn + kr) * NC + colBase + bc]);
            bR1 = *reinterpret_cast<const float4*>(&W[(size_t)(kn + kr) * NC + colBase + bc + 64]);
        }

#pragma unroll
        for (int kk = 0; kk < 16; kk++) {
            float4 a0 = *reinterpret_cast<const float4*>(&As[buf][kk][ty * 8]);
            float4 a1 = *reinterpret_cast<const float4*>(&As[buf][kk][ty * 8 + 4]);
            float4 b0 = *reinterpret_cast<const float4*>(&Bs[buf][kk][tx * 8]);
            float4 b1 = *reinterpret_cast<const float4*>(&Bs[buf][kk][tx * 8 + 4]);
            float a[8] = {a0.x, a0.y, a0.z, a0.w, a1.x, a1.y, a1.z, a1.w};
            float b[8] = {b0.x, b0.y, b0.z, b0.w, b1.x, b1.y, b1.z, b1.w};
#pragma unroll
            for (int i = 0; i < 8; i++)
#pragma unroll
                for (int j = 0; j < 8; j++)
                    acc[i][j] = fmaf(a[i], b[j], acc[i][j]);
        }

        if (more) {
            int nb = buf ^ 1;
            As[nb][ac + 0][ar] = aR0.x; As[nb][ac + 1][ar] = aR0.y;
            As[nb][ac + 2][ar] = aR0.z; As[nb][ac + 3][ar] = aR0.w;
            As[nb][ac + 0][ar + 64] = aR1.x; As[nb][ac + 1][ar + 64] = aR1.y;
            As[nb][ac + 2][ar + 64] = aR1.z; As[nb][ac + 3][ar + 64] = aR1.w;
            *reinterpret_cast<float4*>(&Bs[nb][kr][bc])      = bR0;
            *reinterpret_cast<float4*>(&Bs[nb][kr][bc + 64]) = bR1;
        }
        __syncthreads();
        buf ^= 1;
    }

    // epilogue: bias + store (float4)
#pragma unroll
    for (int i = 0; i < 8; i++) {
        int row = rowBase + ty * 8 + i;
        if (row >= M) continue;
        int col = colBase + tx * 8;
        float4 o0, o1;
        o0.x = acc[i][0] + bias[col + 0]; o0.y = acc[i][1] + bias[col + 1];
        o0.z = acc[i][2] + bias[col + 2]; o0.w = acc[i][3] + bias[col + 3];
        o1.x = acc[i][4] + bias[col + 4]; o1.y = acc[i][5] + bias[col + 5];
        o1.z = acc[i][6] + bias[col + 6]; o1.w = acc[i][7] + bias[col + 7];
        *reinterpret_cast<float4*>(&X[(size_t)row * NC + col])     = o0;
        *reinterpret_cast<float4*>(&X[(size_t)row * NC + col + 4]) = o1;
    }
}

// ---------------- dual-output 64x64 SGEMM (layer 2): split outputs ----------
__global__ __launch_bounds__(256)
void sgemm_dual64(const float* __restrict__ A,
                  const float* __restrict__ Wl, const float* __restrict__ bl,
                  const float* __restrict__ Wr, const float* __restrict__ br,
                  float* __restrict__ Xl, float* __restrict__ Xr,
                  int M, int nc, int K)
{
    const int BM = 64, BN = 64, BK = 16;
    __shared__ float As[BK][BM + 1];
    __shared__ float Bs[BK][BN + 1];
    const int tid = threadIdx.x;
    const int tx = tid % 16;
    const int ty = tid / 16;
    const int rowBase = blockIdx.y * BM;
    const int colBase = blockIdx.x * BN;

    float acc[4][4] = {};

    for (int k0 = 0; k0 < K; k0 += BK) {
        {
            int r = tid >> 2;
            int c = (tid & 3) * 4;
            float4 v = make_float4(0.f, 0.f, 0.f, 0.f);
            if (rowBase + r < M)
                v = *reinterpret_cast<const float4*>(
                        &A[(size_t)(rowBase + r) * K + k0 + c]);
            As[c + 0][r] = v.x; As[c + 1][r] = v.y;
            As[c + 2][r] = v.z; As[c + 3][r] = v.w;
        }
        {
            int r = tid >> 4;
            int c = (tid & 15) * 4;
            int col = colBase + c;
            float4 v;
            if (col < nc)
                v = *reinterpret_cast<const float4*>(&Wl[(size_t)(k0 + r) * nc + col]);
            else
                v = *reinterpret_cast<const float4*>(&Wr[(size_t)(k0 + r) * nc + col - nc]);
            Bs[r][c + 0] = v.x; Bs[r][c + 1] = v.y;
            Bs[r][c + 2] = v.z; Bs[r][c + 3] = v.w;
        }
        __syncthreads();
#pragma unroll
        for (int kk = 0; kk < BK; kk++) {
            float a[4], b[4];
#pragma unroll
            for (int i = 0; i < 4; i++) a[i] = As[kk][ty * 4 + i];
#pragma unroll
            for (int j = 0; j < 4; j++) b[j] = Bs[kk][tx * 4 + j];
#pragma unroll
            for (int i = 0; i < 4; i++)
#pragma unroll
                for (int j = 0; j < 4; j++)
                    acc[i][j] = fmaf(a[i], b[j], acc[i][j]);
        }
        __syncthreads();
    }

#pragma unroll
    for (int i = 0; i < 4; i++) {
        int row = rowBase + ty * 4 + i;
        if (row >= M) continue;
#pragma unroll
        for (int j = 0; j < 4; j++) {
            int col = colBase + tx * 4 + j;
            if (col < nc)
                Xl[(size_t)row * nc + col] = acc[i][j] + bl[col];
            else
                Xr[(size_t)row * nc + col - nc] = acc[i][j] + br[col - nc];
        }
    }
}

// ---------------- plain SGEMM + bias (head) ---------------------------------
__global__ __launch_bounds__(256)
void sgemm_bias(const float* __restrict__ A, const float* __restrict__ B,
                const float* __restrict__ bias, float* __restrict__ C,
                int M, int N, int K)
{
    const int BM = 64, BN = 64, BK = 16;
    __shared__ float As[BK][BM + 1];
    __shared__ float Bs[BK][BN + 1];
    const int tid = threadIdx.x;
    const int tx = tid % 16;
    const int ty = tid / 16;
    const int rowBase = blockIdx.y * BM;
    const int colBase = blockIdx.x * BN;

    float acc[4][4] = {};

    for (int k0 = 0; k0 < K; k0 += BK) {
        {
            int r = tid >> 2;
            int c = (tid & 3) * 4;
            float4 v = make_float4(0.f, 0.f, 0.f, 0.f);
            if (rowBase + r < M && c < K - k0)
                v = *reinterpret_cast<const float4*>(
                        &A[(size_t)(rowBase + r) * K + k0 + c]);
            As[c + 0][r] = v.x; As[c + 1][r] = v.y;
            As[c + 2][r] = v.z; As[c + 3][r] = v.w;
        }
        {
            int r = tid >> 4;
            int c = (tid & 15) * 4;
            float4 v = make_float4(0.f, 0.f, 0.f, 0.f);
            if (colBase + c + 3 < N && r < K - k0)
                v = *reinterpret_cast<const float4*>(
                        &B[(size_t)(k0 + r) * N + colBase + c]);
            Bs[r][c + 0] = v.x; Bs[r][c + 1] = v.y;
            Bs[r][c + 2] = v.z; Bs[r][c + 3] = v.w;
        }
        __syncthreads();
#pragma unroll
        for (int kk = 0; kk < BK; kk++) {
            float a[4], b[4];
#pragma unroll
            for (int i = 0; i < 4; i++) a[i] = As[kk][ty * 4 + i];
#pragma unroll
            for (int j = 0; j < 4; j++) b[j] = Bs[kk][tx * 4 + j];
#pragma unroll
            for (int i = 0; i < 4; i++)
#pragma unroll
                for (int j = 0; j < 4; j++)
                    acc[i][j] = fmaf(a[i], b[j], acc[i][j]);
        }
        __syncthreads();
    }

#pragma unroll
    for (int i = 0; i < 4; i++) {
        int row = rowBase + ty * 4 + i;
        if (row >= M) continue;
#pragma unroll
        for (int j = 0; j < 4; j++) {
            int col = colBase + tx * 4 + j;
            if (col < N)
                C[(size_t)row * N + col] = acc[i][j] + bias[col];
        }
    }
}

// ---------------- CSR construction ------------------------------------------
__global__ void zero_deg_k(int* __restrict__ deg)
{
    int i = blockIdx.x * blockDim.x + threadIdx.x;
    if (i < NN) deg[i] = 0;
}

__global__ void hist_k(const int* __restrict__ ei, int* __restrict__ deg)
{
    int e = blockIdx.x * blockDim.x + threadIdx.x;
    if (e < EE) atomicAdd(&deg[ei[EE + e]], 1);
}

__global__ void scan1_k(const int* __restrict__ deg, int* __restrict__ rowptr,
                        int* __restrict__ bsums)
{
    __shared__ int sh[256];
    int tid = threadIdx.x;
    int i = blockIdx.x * 256 + tid;
    int v = (i < NN) ? deg[i] : 0;
    sh[tid] = v;
    __syncthreads();
#pragma unroll
    for (int off = 1; off < 256; off <<= 1) {
        int t = (tid >= off) ? sh[tid - off] : 0;
        __syncthreads();
        sh[tid] += t;
        __syncthreads();
    }
    if (i < NN) rowptr[i] = sh[tid] - v;
    if (tid == 255) bsums[blockIdx.x] = sh[255];
}

__global__ void scan2_k(int* __restrict__ bsums, int nb)
{
    __shared__ int sh[256];
    int tid = threadIdx.x;
    int v = (tid < nb) ? bsums[tid] : 0;
    sh[tid] = v;
    __syncthreads();
#pragma unroll
    for (int off = 1; off < 256; off <<= 1) {
        int t = (tid >= off) ? sh[tid - off] : 0;
        __syncthreads();
        sh[tid] += t;
        __syncthreads();
    }
    if (tid < nb) bsums[tid] = sh[tid] - v;
}

__global__ void scan3_k(int* __restrict__ rowptr, const int* __restrict__ bsums,
                        int* __restrict__ cursor)
{
    int i = blockIdx.x * blockDim.x + threadIdx.x;
    if (i >= NN) return;
    int r = rowptr[i] + bsums[i >> 8];
    rowptr[i] = r;
    cursor[i] = r;
}

__global__ void scatter_k(const int* __restrict__ ei, int* __restrict__ cursor,
                          int* __restrict__ csrc)
{
    int e = blockIdx.x * blockDim.x + threadIdx.x;
    if (e >= EE) return;
    int d = ei[EE + e];
    int pos = atomicAdd(&cursor[d], 1);
    csrc[pos] = ei[e];
}

// ---------------- fused GATv2 edge phase, layer 1 ---------------------------
// warp per dst node; lane covers 8 channels; 2-stage software pipeline
__global__ __launch_bounds__(256)
void edge_fused1_k(const int* __restrict__ rowptr, const int* __restrict__ deg,
                   const int* __restrict__ csrc,
                   const float* __restrict__ xl, const float* __restrict__ xr,
                   const float* __restrict__ att, const float* __restrict__ bias,
                   float* __restrict__ h1)
{
    int w = (blockIdx.x * blockDim.x + threadIdx.x) >> 5;
    if (w >= NN) return;
    int lane = threadIdx.x & 31;

    const float4* pb = reinterpret_cast<const float4*>(xr + (size_t)w * C1 + lane * 8);
    float4 b0 = pb[0], b1 = pb[1];
    const float4* pt = reinterpret_cast<const float4*>(att + lane * 8);
    float4 t0 = pt[0], t1 = pt[1];

    float acc[8] = {};
    float den = 0.f;

    int start = rowptr[w];
    int dg    = deg[w];

    int s = (dg > 0) ? csrc[start] : 0;
    const float4* pa = reinterpret_cast<const float4*>(xl + (size_t)s * C1 + lane * 8);
    float4 a0 = pa[0], a1 = pa[1];

    for (int i = 0; i < dg; i++) {
        // prefetch next source row before the dependent shfl/exp chain
        int snext = (i + 1 < dg) ? csrc[start + i + 1] : s;
        const float4* pn = reinterpret_cast<const float4*>(
            xl + (size_t)snext * C1 + lane * 8);
        float4 n0 = pn[0], n1 = pn[1];

        float p = lrelu(a0.x + b0.x) * t0.x + lrelu(a0.y + b0.y) * t0.y
                + lrelu(a0.z + b0.z) * t0.z + lrelu(a0.w + b0.w) * t0.w
                + lrelu(a1.x + b1.x) * t1.x + lrelu(a1.y + b1.y) * t1.y
                + lrelu(a1.z + b1.z) * t1.z + lrelu(a1.w + b1.w) * t1.w;
        p += __shfl_xor_sync(0xffffffffu, p, 1);
        p += __shfl_xor_sync(0xffffffffu, p, 2);
        float ex = __expf(p);
        den += ex;
        acc[0] += ex * a0.x; acc[1] += ex * a0.y;
        acc[2] += ex * a0.z; acc[3] += ex * a0.w;
        acc[4] += ex * a1.x; acc[5] += ex * a1.y;
        acc[6] += ex * a1.z; acc[7] += ex * a1.w;

        a0 = n0; a1 = n1;
    }

    float inv = 1.f / (den + 1e-16f);
    const float* bi = bias + lane * 8;
    float4 o0, o1;
    o0.x = elu(acc[0] * inv + bi[0]); o0.y = elu(acc[1] * inv + bi[1]);
    o0.z = elu(acc[2] * inv + bi[2]); o0.w = elu(acc[3] * inv + bi[3]);
    o1.x = elu(acc[4] * inv + bi[4]); o1.y = elu(acc[5] * inv + bi[5]);
    o1.z = elu(acc[6] * inv + bi[6]); o1.w = elu(acc[7] * inv + bi[7]);
    float4* out = reinterpret_cast<float4*>(h1 + (size_t)w * C1 + lane * 8);
    out[0] = o0; out[1] = o1;
}

// ---------------- fused edge phase, layer 2 ---------------------------------
__global__ __launch_bounds__(256)
void edge_fused2_k(const int* __restrict__ rowptr, const int* __restrict__ deg,
                   const int* __restrict__ csrc,
                   const float* __restrict__ xl, const float* __restrict__ xr,
                   const float* __restrict__ att, const float* __restrict__ bias,
                   float* __restrict__ h2)
{
    int w = (blockIdx.x * blockDim.x + threadIdx.x) >> 5;
    if (w >= NN) return;
    int lane = threadIdx.x & 31;

    float b = xr[(size_t)w * HIDC + lane];
    float t = att[lane];

    float acc = 0.f, den = 0.f;
    int start = rowptr[w];
    int dg    = deg[w];

    int s = (dg > 0) ? csrc[start] : 0;
    float a = xl[(size_t)s * HIDC + lane];

    for (int i = 0; i < dg; i++) {
        int snext = (i + 1 < dg) ? csrc[start + i + 1] : s;
        float n = xl[(size_t)snext * HIDC + lane];

        float p = lrelu(a + b) * t;
        p += __shfl_xor_sync(0xffffffffu, p, 16);
        p += __shfl_xor_sync(0xffffffffu, p, 8);
        p += __shfl_xor_sync(0xffffffffu, p, 4);
        p += __shfl_xor_sync(0xffffffffu, p, 2);
        p += __shfl_xor_sync(0xffffffffu, p, 1);
        float ex = __expf(p);
        den += ex;
        acc += ex * a;

        a = n;
    }
    float inv = 1.f / (den + 1e-16f);
    h2[(size_t)w * HIDC + lane] = elu(acc * inv + bias[lane]);
}

// ---------------- launch ------------------------------------------------------
extern "C" void kernel_launch(void* const* d_in, const int* in_sizes, int n_in,
                              void* d_out, int out_size)
{
    const float* x     = (const float*)d_in[0];
    const int*   ei    = (const int*)d_in[1];
    const float* W1l   = (const float*)d_in[2];
    const float* b1l   = (const float*)d_in[3];
    const float* W1r   = (const float*)d_in[4];
    const float* b1r   = (const float*)d_in[5];
    const float* att1  = (const float*)d_in[6];
    const float* bias1 = (const float*)d_in[7];
    const float* W2l   = (const float*)d_in[8];
    const float* b2l   = (const float*)d_in[9];
    const float* W2r   = (const float*)d_in[10];
    const float* b2r   = (const float*)d_in[11];
    const float* att2  = (const float*)d_in[12];
    const float* bias2 = (const float*)d_in[13];
    const float* Wlin  = (const float*)d_in[14];
    const float* blin  = (const float*)d_in[15];
    float* out = (float*)d_out;

    float *xl1, *xr1, *h1, *xl2, *xr2, *h2;
    int *deg, *rowptr, *cursor, *csrc, *bsums;
    cudaGetSymbolAddress((void**)&xl1, g_xl1);
    cudaGetSymbolAddress((void**)&xr1, g_xr1);
    cudaGetSymbolAddress((void**)&h1,  g_h1);
    cudaGetSymbolAddress((void**)&xl2, g_xl2);
    cudaGetSymbolAddress((void**)&xr2, g_xr2);
    cudaGetSymbolAddress((void**)&h2,  g_h2);
    cudaGetSymbolAddress((void**)&deg,    g_deg);
    cudaGetSymbolAddress((void**)&rowptr, g_rowptr);
    cudaGetSymbolAddress((void**)&cursor, g_cursor);
    cudaGetSymbolAddress((void**)&csrc,   g_csrc);
    cudaGetSymbolAddress((void**)&bsums,  g_bsums);

    const int TPB = 256;
    const int nScanBlocks = (NN + 255) / 256;       // 196

    // ---- CSR build ----
    zero_deg_k<<<(NN + TPB - 1) / TPB, TPB>>>(deg);
    hist_k<<<(EE + TPB - 1) / TPB, TPB>>>(ei, deg);
    scan1_k<<<nScanBlocks, 256>>>(deg, rowptr, bsums);
    scan2_k<<<1, 256>>>(bsums, nScanBlocks);
    scan3_k<<<(NN + TPB - 1) / TPB, TPB>>>(rowptr, bsums, cursor);
    scatter_k<<<(EE + TPB - 1) / TPB, TPB>>>(ei, cursor, csrc);

    // ---- layer 1 ----
    dim3 gg1(4, (NN + 127) / 128);                  // 512 cols / 128
    sgemm128_dual<<<gg1, TPB>>>(x, W1l, b1l, W1r, b1r, xl1, xr1);

    int eblocks = (NN * 32 + TPB - 1) / TPB;
    edge_fused1_k<<<eblocks, TPB>>>(rowptr, deg, csrc, xl1, xr1, att1, bias1, h1);

    // ---- layer 2 ----
    dim3 gg2(1, (NN + 63) / 64);
    sgemm_dual64<<<gg2, TPB>>>(h1, W2l, b2l, W2r, b2r, xl2, xr2, NN, HIDC, C1);

    edge_fused2_k<<<eblocks, TPB>>>(rowptr, deg, csrc, xl2, xr2, att2, bias2, h2);

    // ---- head ----
    dim3 gg3(1, (NN + 63) / 64);
    sgemm_bias<<<gg3, TPB>>>(h2, Wlin, blin, out, NN, OUTDIM, HIDC);
}

// round 5
// speedup vs baseline: 2.5557x; 1.0493x over previous
#include <cuda_runtime.h>

#define NN      50000
#define EE      800000
#define INDIM   256
#define HIDC    32
#define NHEADS  8
#define OUTDIM  64
#define C1      (NHEADS * HIDC)   // 256
#define NEGSLOPE 0.2f

// ---------------- scratch (device globals) ---------------------------------
__device__ float g_xl1[(size_t)NN * C1];
__device__ float g_xr1[(size_t)NN * C1];
__device__ float g_h1 [(size_t)NN * C1];
__device__ float g_xl2[(size_t)NN * HIDC];
__device__ float g_xr2[(size_t)NN * HIDC];
__device__ int   g_deg   [NN];
__device__ int   g_rowptr[NN];
__device__ int   g_cursor[NN];
__device__ int   g_csrc  [EE];
__device__ int   g_bsums [256];

// ---------------- helpers ---------------------------------------------------
__device__ __forceinline__ float lrelu(float v) { return v > 0.f ? v : NEGSLOPE * v; }
__device__ __forceinline__ float elu(float v)   { return v > 0.f ? v : expm1f(v); }

// ============================================================================
// GEMM1: 128x128 tile, BK=16, double-buffered, 8x8 micro. Ntot=512 (Wl|Wr).
// ============================================================================
__global__ __launch_bounds__(256, 2)
void sgemm128_dual(const float* __restrict__ A,
                   const float* __restrict__ Wl, const float* __restrict__ bl,
                   const float* __restrict__ Wr, const float* __restrict__ br,
                   float* __restrict__ Xl, float* __restrict__ Xr)
{
    const int M = NN, K = INDIM, NC = C1;
    __shared__ float As[2][16][128 + 4];
    __shared__ float Bs[2][16][128];

    const int tid = threadIdx.x;
    const int tx = tid & 15;
    const int ty = tid >> 4;
    const int rowBase = blockIdx.y * 128;
    int colBase = blockIdx.x * 128;

    const float* W;  const float* bias;  float* X;
    if (colBase < NC) { W = Wl; bias = bl; X = Xl; }
    else              { W = Wr; bias = br; X = Xr; colBase -= NC; }

    const int ar = tid >> 2;
    const int ac = (tid & 3) * 4;
    const int kr = tid >> 4;
    const int bc = (tid & 15) * 4;

    const int r0 = min(rowBase + ar,      M - 1);
    const int r1 = min(rowBase + ar + 64, M - 1);

    float4 aR0, aR1, bR0, bR1;

    aR0 = *reinterpret_cast<const float4*>(&A[(size_t)r0 * K + ac]);
    aR1 = *reinterpret_cast<const float4*>(&A[(size_t)r1 * K + ac]);
    bR0 = *reinterpret_cast<const float4*>(&W[(size_t)kr * NC + colBase + bc]);
    bR1 = *reinterpret_cast<const float4*>(&W[(size_t)kr * NC + colBase + bc + 64]);

    As[0][ac + 0][ar] = aR0.x; As[0][ac + 1][ar] = aR0.y;
    As[0][ac + 2][ar] = aR0.z; As[0][ac + 3][ar] = aR0.w;
    As[0][ac + 0][ar + 64] = aR1.x; As[0][ac + 1][ar + 64] = aR1.y;
    As[0][ac + 2][ar + 64] = aR1.z; As[0][ac + 3][ar + 64] = aR1.w;
    *reinterpret_cast<float4*>(&Bs[0][kr][bc])      = bR0;
    *reinterpret_cast<float4*>(&Bs[0][kr][bc + 64]) = bR1;
    __syncthreads();

    float acc[8][8] = {};
    int buf = 0;

    for (int k0 = 0; k0 < K; k0 += 16) {
        const bool more = (k0 + 16 < K);
        if (more) {
            int kn = k0 + 16;
            aR0 = *reinterpret_cast<const float4*>(&A[(size_t)r0 * K + kn + ac]);
            aR1 = *reinterpret_cast<const float4*>(&A[(size_t)r1 * K + kn + ac]);
            bR0 = *reinterpret_cast<const float4*>(&W[(size_t)(kn + kr) * NC + colBase + bc]);
            bR1 = *reinterpret_cast<const float4*>(&W[(size_t)(kn + kr) * NC + colBase + bc + 64]);
        }

#pragma unroll
        for (int kk = 0; kk < 16; kk++) {
            float4 a0 = *reinterpret_cast<const float4*>(&As[buf][kk][ty * 8]);
            float4 a1 = *reinterpret_cast<const float4*>(&As[buf][kk][ty * 8 + 4]);
            float4 b0 = *reinterpret_cast<const float4*>(&Bs[buf][kk][tx * 8]);
            float4 b1 = *reinterpret_cast<const float4*>(&Bs[buf][kk][tx * 8 + 4]);
            float a[8] = {a0.x, a0.y, a0.z, a0.w, a1.x, a1.y, a1.z, a1.w};
            float b[8] = {b0.x, b0.y, b0.z, b0.w, b1.x, b1.y, b1.z, b1.w};
#pragma unroll
            for (int i = 0; i < 8; i++)
#pragma unroll
                for (int j = 0; j < 8; j++)
                    acc[i][j] = fmaf(a[i], b[j], acc[i][j]);
        }

        if (more) {
            int nb = buf ^ 1;
            As[nb][ac + 0][ar] = aR0.x; As[nb][ac + 1][ar] = aR0.y;
            As[nb][ac + 2][ar] = aR0.z; As[nb][ac + 3][ar] = aR0.w;
            As[nb][ac + 0][ar + 64] = aR1.x; As[nb][ac + 1][ar + 64] = aR1.y;
            As[nb][ac + 2][ar + 64] = aR1.z; As[nb][ac + 3][ar + 64] = aR1.w;
            *reinterpret_cast<float4*>(&Bs[nb][kr][bc])      = bR0;
            *reinterpret_cast<float4*>(&Bs[nb][kr][bc + 64]) = bR1;
        }
        __syncthreads();
        buf ^= 1;
    }

#pragma unroll
    for (int i = 0; i < 8; i++) {
        int row = rowBase + ty * 8 + i;
        if (row >= M) continue;
        int col = colBase + tx * 8;
        float4 o0, o1;
        o0.x = acc[i][0] + bias[col + 0]; o0.y = acc[i][1] + bias[col + 1];
        o0.z = acc[i][2] + bias[col + 2]; o0.w = acc[i][3] + bias[col + 3];
        o1.x = acc[i][4] + bias[col + 4]; o1.y = acc[i][5] + bias[col + 5];
        o1.z = acc[i][6] + bias[col + 6]; o1.w = acc[i][7] + bias[col + 7];
        *reinterpret_cast<float4*>(&X[(size_t)row * NC + col])     = o0;
        *reinterpret_cast<float4*>(&X[(size_t)row * NC + col + 4]) = o1;
    }
}

// ============================================================================
// GEMM2: 128x64 tile, BK=16, double-buffered, 8x4 micro. Ntot=64 (Wl32|Wr32).
// K = 256.
// ============================================================================
__global__ __launch_bounds__(256, 2)
void sgemm128x64_dual(const float* __restrict__ A,
                      const float* __restrict__ Wl, const float* __restrict__ bl,
                      const float* __restrict__ Wr, const float* __restrict__ br,
                      float* __restrict__ Xl, float* __restrict__ Xr)
{
    const int M = NN, K = C1, nc = HIDC;
    __shared__ float As[2][16][128 + 4];
    __shared__ float Bs[2][16][64];

    const int tid = threadIdx.x;
    const int tx = tid & 15;          // 4 cols each
    const int ty = tid >> 4;          // 8 rows each
    const int rowBase = blockIdx.x * 128;

    const int ar = tid >> 2;
    const int ac = (tid & 3) * 4;
    const int kr = tid >> 4;
    const int bc = (tid & 15) * 4;

    const int r0 = min(rowBase + ar,      M - 1);
    const int r1 = min(rowBase + ar + 64, M - 1);

    const float* Wsrc0 = (bc < nc) ? (Wl + bc) : (Wr + bc - nc);

    float4 aR0, aR1, bR0;

    aR0 = *reinterpret_cast<const float4*>(&A[(size_t)r0 * K + ac]);
    aR1 = *reinterpret_cast<const float4*>(&A[(size_t)r1 * K + ac]);
    bR0 = *reinterpret_cast<const float4*>(&Wsrc0[(size_t)kr * nc]);

    As[0][ac + 0][ar] = aR0.x; As[0][ac + 1][ar] = aR0.y;
    As[0][ac + 2][ar] = aR0.z; As[0][ac + 3][ar] = aR0.w;
    As[0][ac + 0][ar + 64] = aR1.x; As[0][ac + 1][ar + 64] = aR1.y;
    As[0][ac + 2][ar + 64] = aR1.z; As[0][ac + 3][ar + 64] = aR1.w;
    *reinterpret_cast<float4*>(&Bs[0][kr][bc]) = bR0;
    __syncthreads();

    float acc[8][4] = {};
    int buf = 0;

    for (int k0 = 0; k0 < K; k0 += 16) {
        const bool more = (k0 + 16 < K);
        if (more) {
            int kn = k0 + 16;
            aR0 = *reinterpret_cast<const float4*>(&A[(size_t)r0 * K + kn + ac]);
            aR1 = *reinterpret_cast<const float4*>(&A[(size_t)r1 * K + kn + ac]);
            bR0 = *reinterpret_cast<const float4*>(&Wsrc0[(size_t)(kn + kr) * nc]);
        }

#pragma unroll
        for (int kk = 0; kk < 16; kk++) {
            float4 a0 = *reinterpret_cast<const float4*>(&As[buf][kk][ty * 8]);
            float4 a1 = *reinterpret_cast<const float4*>(&As[buf][kk][ty * 8 + 4]);
            float4 b0 = *reinterpret_cast<const float4*>(&Bs[buf][kk][tx * 4]);
            float a[8] = {a0.x, a0.y, a0.z, a0.w, a1.x, a1.y, a1.z, a1.w};
            float b[4] = {b0.x, b0.y, b0.z, b0.w};
#pragma unroll
            for (int i = 0; i < 8; i++)
#pragma unroll
                for (int j = 0; j < 4; j++)
                    acc[i][j] = fmaf(a[i], b[j], acc[i][j]);
        }

        if (more) {
            int nb = buf ^ 1;
            As[nb][ac + 0][ar] = aR0.x; As[nb][ac + 1][ar] = aR0.y;
            As[nb][ac + 2][ar] = aR0.z; As[nb][ac + 3][ar] = aR0.w;
            As[nb][ac + 0][ar + 64] = aR1.x; As[nb][ac + 1][ar + 64] = aR1.y;
            As[nb][ac + 2][ar + 64] = aR1.z; As[nb][ac + 3][ar + 64] = aR1.w;
            *reinterpret_cast<float4*>(&Bs[nb][kr][bc]) = bR0;
        }
        __syncthreads();
        buf ^= 1;
    }

    const int col = tx * 4;
    const bool isL = (col < nc);
    float* X = isL ? Xl : Xr;
    const float* bias = isL ? bl : br;
    const int c = isL ? col : col - nc;
#pragma unroll
    for (int i = 0; i < 8; i++) {
        int row = rowBase + ty * 8 + i;
        if (row >= M) continue;
        float4 o;
        o.x = acc[i][0] + bias[c + 0]; o.y = acc[i][1] + bias[c + 1];
        o.z = acc[i][2] + bias[c + 2]; o.w = acc[i][3] + bias[c + 3];
        *reinterpret_cast<float4*>(&X[(size_t)row * nc + c]) = o;
    }
}

// ---------------- CSR construction ------------------------------------------
__global__ void zero_deg_k(int* __restrict__ deg)
{
    int i = blockIdx.x * blockDim.x + threadIdx.x;
    if (i < NN) deg[i] = 0;
}

__global__ void hist_k(const int* __restrict__ ei, int* __restrict__ deg)
{
    int e = blockIdx.x * blockDim.x + threadIdx.x;
    if (e < EE) atomicAdd(&deg[ei[EE + e]], 1);
}

__global__ void scan1_k(const int* __restrict__ deg, int* __restrict__ rowptr,
                        int* __restrict__ bsums)
{
    __shared__ int sh[256];
    int tid = threadIdx.x;
    int i = blockIdx.x * 256 + tid;
    int v = (i < NN) ? deg[i] : 0;
    sh[tid] = v;
    __syncthreads();
#pragma unroll
    for (int off = 1; off < 256; off <<= 1) {
        int t = (tid >= off) ? sh[tid - off] : 0;
        __syncthreads();
        sh[tid] += t;
        __syncthreads();
    }
    if (i < NN) rowptr[i] = sh[tid] - v;
    if (tid == 255) bsums[blockIdx.x] = sh[255];
}

__global__ void scan2_k(int* __restrict__ bsums, int nb)
{
    __shared__ int sh[256];
    int tid = threadIdx.x;
    int v = (tid < nb) ? bsums[tid] : 0;
    sh[tid] = v;
    __syncthreads();
#pragma unroll
    for (int off = 1; off < 256; off <<= 1) {
        int t = (tid >= off) ? sh[tid - off] : 0;
        __syncthreads();
        sh[tid] += t;
        __syncthreads();
    }
    if (tid < nb) bsums[tid] = sh[tid] - v;
}

__global__ void scan3_k(int* __restrict__ rowptr, const int* __restrict__ bsums,
                        int* __restrict__ cursor)
{
    int i = blockIdx.x * blockDim.x + threadIdx.x;
    if (i >= NN) return;
    int r = rowptr[i] + bsums[i >> 8];
    rowptr[i] = r;
    cursor[i] = r;
}

__global__ void scatter_k(const int* __restrict__ ei, int* __restrict__ cursor,
                          int* __restrict__ csrc)
{
    int e = blockIdx.x * blockDim.x + threadIdx.x;
    if (e >= EE) return;
    int d = ei[EE + e];
    int pos = atomicAdd(&cursor[d], 1);
    csrc[pos] = ei[e];
}

// ---------------- fused GATv2 edge phase, layer 1 ---------------------------
__global__ __launch_bounds__(256)
void edge_fused1_k(const int* __restrict__ rowptr, const int* __restrict__ deg,
                   const int* __restrict__ csrc,
                   const float* __restrict__ xl, const float* __restrict__ xr,
                   const float* __restrict__ att, const float* __restrict__ bias,
                   float* __restrict__ h1)
{
    int w = (blockIdx.x * blockDim.x + threadIdx.x) >> 5;
    if (w >= NN) return;
    int lane = threadIdx.x & 31;

    const float4* pb = reinterpret_cast<const float4*>(xr + (size_t)w * C1 + lane * 8);
    float4 b0 = pb[0], b1 = pb[1];
    const float4* pt = reinterpret_cast<const float4*>(att + lane * 8);
    float4 t0 = pt[0], t1 = pt[1];

    float acc[8] = {};
    float den = 0.f;

    int start = rowptr[w];
    int dg    = deg[w];

    int s = (dg > 0) ? csrc[start] : 0;
    const float4* pa = reinterpret_cast<const float4*>(xl + (size_t)s * C1 + lane * 8);
    float4 a0 = pa[0], a1 = pa[1];

    for (int i = 0; i < dg; i++) {
        int snext = (i + 1 < dg) ? csrc[start + i + 1] : s;
        const float4* pn = reinterpret_cast<const float4*>(
            xl + (size_t)snext * C1 + lane * 8);
        float4 n0 = pn[0], n1 = pn[1];

        float p = lrelu(a0.x + b0.x) * t0.x + lrelu(a0.y + b0.y) * t0.y
                + lrelu(a0.z + b0.z) * t0.z + lrelu(a0.w + b0.w) * t0.w
                + lrelu(a1.x + b1.x) * t1.x + lrelu(a1.y + b1.y) * t1.y
                + lrelu(a1.z + b1.z) * t1.z + lrelu(a1.w + b1.w) * t1.w;
        p += __shfl_xor_sync(0xffffffffu, p, 1);
        p += __shfl_xor_sync(0xffffffffu, p, 2);
        float ex = __expf(p);
        den += ex;
        acc[0] += ex * a0.x; acc[1] += ex * a0.y;
        acc[2] += ex * a0.z; acc[3] += ex * a0.w;
        acc[4] += ex * a1.x; acc[5] += ex * a1.y;
        acc[6] += ex * a1.z; acc[7] += ex * a1.w;

        a0 = n0; a1 = n1;
    }

    float inv = 1.f / (den + 1e-16f);
    const float* bi = bias + lane * 8;
    float4 o0, o1;
    o0.x = elu(acc[0] * inv + bi[0]); o0.y = elu(acc[1] * inv + bi[1]);
    o0.z = elu(acc[2] * inv + bi[2]); o0.w = elu(acc[3] * inv + bi[3]);
    o1.x = elu(acc[4] * inv + bi[4]); o1.y = elu(acc[5] * inv + bi[5]);
    o1.z = elu(acc[6] * inv + bi[6]); o1.w = elu(acc[7] * inv + bi[7]);
    float4* out = reinterpret_cast<float4*>(h1 + (size_t)w * C1 + lane * 8);
    out[0] = o0; out[1] = o1;
}

// ---------------- fused edge phase layer 2 + final linear head --------------
// warp per dst node. After computing h2[lane] in-register, do the 32x64 head
// matmul via shfl broadcast against smem-resident Wlin. Writes out[row, 0..63].
__global__ __launch_bounds__(256)
void edge_fused2_head_k(const int* __restrict__ rowptr, const int* __restrict__ deg,
                        const int* __restrict__ csrc,
                        const float* __restrict__ xl, const float* __restrict__ xr,
                        const float* __restrict__ att, const float* __restrict__ bias,
                        const float* __restrict__ Wlin, const float* __restrict__ blin,
                        float* __restrict__ out)
{
    __shared__ float Ws[HIDC][OUTDIM];      // 32x64 = 8 KB
    __shared__ float bs[OUTDIM];

    // cooperative load of Wlin / blin
    for (int i = threadIdx.x; i < HIDC * OUTDIM; i += blockDim.x)
        Ws[i >> 6][i & 63] = Wlin[i];
    if (threadIdx.x < OUTDIM) bs[threadIdx.x] = blin[threadIdx.x];
    __syncthreads();

    int w = (blockIdx.x * blockDim.x + threadIdx.x) >> 5;
    int lane = threadIdx.x & 31;
    if (w >= NN) return;

    float b = xr[(size_t)w * HIDC + lane];
    float t = att[lane];

    float acc = 0.f, den = 0.f;
    int start = rowptr[w];
    int dg    = deg[w];

    int s = (dg > 0) ? csrc[start] : 0;
    float a = xl[(size_t)s * HIDC + lane];

    for (int i = 0; i < dg; i++) {
        int snext = (i + 1 < dg) ? csrc[start + i + 1] : s;
        float n = xl[(size_t)snext * HIDC + lane];

        float p = lrelu(a + b) * t;
        p += __shfl_xor_sync(0xffffffffu, p, 16);
        p += __shfl_xor_sync(0xffffffffu, p, 8);
        p += __shfl_xor_sync(0xffffffffu, p, 4);
        p += __shfl_xor_sync(0xffffffffu, p, 2);
        p += __shfl_xor_sync(0xffffffffu, p, 1);
        float ex = __expf(p);
        den += ex;
        acc += ex * a;

        a = n;
    }
    float inv = 1.f / (den + 1e-16f);
    float hval = elu(acc * inv + bias[lane]);   // h2[w][lane]

    // head: out[w][c] = sum_k h2[k] * Ws[k][c] + blin[c]; lane -> cols {lane, lane+32}
    float o0 = bs[lane];
    float o1 = bs[lane + 32];
#pragma unroll
    for (int k = 0; k < HIDC; k++) {
        float v = __shfl_sync(0xffffffffu, hval, k);
        o0 = fmaf(v, Ws[k][lane],      o0);
        o1 = fmaf(v, Ws[k][lane + 32], o1);
    }
    out[(size_t)w * OUTDIM + lane]      = o0;
    out[(size_t)w * OUTDIM + lane + 32] = o1;
}

// ---------------- launch ------------------------------------------------------
extern "C" void kernel_launch(void* const* d_in, const int* in_sizes, int n_in,
                              void* d_out, int out_size)
{
    const float* x     = (const float*)d_in[0];
    const int*   ei    = (const int*)d_in[1];
    const float* W1l   = (const float*)d_in[2];
    const float* b1l   = (const float*)d_in[3];
    const float* W1r   = (const float*)d_in[4];
    const float* b1r   = (const float*)d_in[5];
    const float* att1  = (const float*)d_in[6];
    const float* bias1 = (const float*)d_in[7];
    const float* W2l   = (const float*)d_in[8];
    const float* b2l   = (const float*)d_in[9];
    const float* W2r   = (const float*)d_in[10];
    const float* b2r   = (const float*)d_in[11];
    const float* att2  = (const float*)d_in[12];
    const float* bias2 = (const float*)d_in[13];
    const float* Wlin  = (const float*)d_in[14];
    const float* blin  = (const float*)d_in[15];
    float* out = (float*)d_out;

    float *xl1, *xr1, *h1, *xl2, *xr2;
    int *deg, *rowptr, *cursor, *csrc, *bsums;
    cudaGetSymbolAddress((void**)&xl1, g_xl1);
    cudaGetSymbolAddress((void**)&xr1, g_xr1);
    cudaGetSymbolAddress((void**)&h1,  g_h1);
    cudaGetSymbolAddress((void**)&xl2, g_xl2);
    cudaGetSymbolAddress((void**)&xr2, g_xr2);
    cudaGetSymbolAddress((void**)&deg,    g_deg);
    cudaGetSymbolAddress((void**)&rowptr, g_rowptr);
    cudaGetSymbolAddress((void**)&cursor, g_cursor);
    cudaGetSymbolAddress((void**)&csrc,   g_csrc);
    cudaGetSymbolAddress((void**)&bsums,  g_bsums);

    const int TPB = 256;
    const int nScanBlocks = (NN + 255) / 256;       // 196

    // launch order puts sgemm128_dual at index 3 (ncu samples launch #4)
    zero_deg_k<<<(NN + TPB - 1) / TPB, TPB>>>(deg);                       // 0
    hist_k<<<(EE + TPB - 1) / TPB, TPB>>>(ei, deg);                       // 1
    scan1_k<<<nScanBlocks, 256>>>(deg, rowptr, bsums);                    // 2

    dim3 gg1(4, (NN + 127) / 128);
    sgemm128_dual<<<gg1, TPB>>>(x, W1l, b1l, W1r, b1r, xl1, xr1);         // 3

    scan2_k<<<1, 256>>>(bsums, nScanBlocks);                              // 4
    scan3_k<<<(NN + TPB - 1) / TPB, TPB>>>(rowptr, bsums, cursor);        // 5
    scatter_k<<<(EE + TPB - 1) / TPB, TPB>>>(ei, cursor, csrc);           // 6

    int eblocks = (NN * 32 + TPB - 1) / TPB;
    edge_fused1_k<<<eblocks, TPB>>>(rowptr, deg, csrc, xl1, xr1, att1, bias1, h1); // 7

    sgemm128x64_dual<<<(NN + 127) / 128, TPB>>>(h1, W2l, b2l, W2r, b2r, xl2, xr2); // 8

    edge_fused2_head_k<<<eblocks, TPB>>>(rowptr, deg, csrc, xl2, xr2,
                                         att2, bias2, Wlin, blin, out);   // 9
}

// round 6
// speedup vs baseline: 2.6359x; 1.0314x over previous
#include <cuda_runtime.h>

#define NN      50000
#define EE      800000
#define INDIM   256
#define HIDC    32
#define NHEADS  8
#define OUTDIM  64
#define C1      (NHEADS * HIDC)   // 256
#define NEGSLOPE 0.2f

typedef unsigned long long u64;

// ---------------- scratch (device globals) ---------------------------------
__device__ float g_xl1[(size_t)NN * C1];
__device__ float g_xr1[(size_t)NN * C1];
__device__ float g_h1 [(size_t)NN * C1];
__device__ float g_xl2[(size_t)NN * HIDC];
__device__ float g_xr2[(size_t)NN * HIDC];
__device__ int   g_deg   [NN];
__device__ int   g_rowptr[NN];
__device__ int   g_cursor[NN];
__device__ int   g_csrc  [EE];
__device__ int   g_bsums [256];

// ---------------- helpers ---------------------------------------------------
__device__ __forceinline__ float lrelu(float v) { return v > 0.f ? v : NEGSLOPE * v; }
__device__ __forceinline__ float elu(float v)   { return v > 0.f ? v : expm1f(v); }

// packed fp32x2 FMA (Blackwell FFMA2 path; ptxas never emits this from C++)
__device__ __forceinline__ u64 ffma2(u64 a, u64 b, u64 c)
{
    u64 d;
    asm("fma.rn.f32x2 %0, %1, %2, %3;" : "=l"(d) : "l"(a), "l"(b), "l"(c));
    return d;
}
__device__ __forceinline__ u64 pack2(float x, float y)
{
    u64 d;
    asm("mov.b64 %0, {%1, %2};" : "=l"(d) : "f"(x), "f"(y));
    return d;
}
__device__ __forceinline__ float2 unpack2(u64 v)
{
    float2 r;
    asm("mov.b64 {%0, %1}, %2;" : "=f"(r.x), "=f"(r.y) : "l"(v));
    return r;
}

// ============================================================================
// GEMM1: 128x128 tile, BK=16, double-buffered, 8x8 micro via FFMA2
// rows paired in 64-bit accumulators. Ntot=512 (Wl|Wr).
// ============================================================================
__global__ __launch_bounds__(256, 2)
void sgemm128_dual(const float* __restrict__ A,
                   const float* __restrict__ Wl, const float* __restrict__ bl,
                   const float* __restrict__ Wr, const float* __restrict__ br,
                   float* __restrict__ Xl, float* __restrict__ Xr)
{
    const int M = NN, K = INDIM, NC = C1;
    __shared__ float As[2][16][128 + 4];
    __shared__ float Bs[2][16][128];

    const int tid = threadIdx.x;
    const int tx = tid & 15;
    const int ty = tid >> 4;
    const int rowBase = blockIdx.y * 128;
    int colBase = blockIdx.x * 128;

    const float* W;  const float* bias;  float* X;
    if (colBase < NC) { W = Wl; bias = bl; X = Xl; }
    else              { W = Wr; bias = br; X = Xr; colBase -= NC; }

    const int ar = tid >> 2;
    const int ac = (tid & 3) * 4;
    const int kr = tid >> 4;
    const int bc = (tid & 15) * 4;

    const int r0 = min(rowBase + ar,      M - 1);
    const int r1 = min(rowBase + ar + 64, M - 1);

    float4 aR0, aR1, bR0, bR1;

    aR0 = *reinterpret_cast<const float4*>(&A[(size_t)r0 * K + ac]);
    aR1 = *reinterpret_cast<const float4*>(&A[(size_t)r1 * K + ac]);
    bR0 = *reinterpret_cast<const float4*>(&W[(size_t)kr * NC + colBase + bc]);
    bR1 = *reinterpret_cast<const float4*>(&W[(size_t)kr * NC + colBase + bc + 64]);

    As[0][ac + 0][ar] = aR0.x; As[0][ac + 1][ar] = aR0.y;
    As[0][ac + 2][ar] = aR0.z; As[0][ac + 3][ar] = aR0.w;
    As[0][ac + 0][ar + 64] = aR1.x; As[0][ac + 1][ar + 64] = aR1.y;
    As[0][ac + 2][ar + 64] = aR1.z; As[0][ac + 3][ar + 64] = aR1.w;
    *reinterpret_cast<float4*>(&Bs[0][kr][bc])      = bR0;
    *reinterpret_cast<float4*>(&Bs[0][kr][bc + 64]) = bR1;
    __syncthreads();

    u64 acc2[4][8];
#pragma unroll
    for (int i = 0; i < 4; i++)
#pragma unroll
        for (int j = 0; j < 8; j++) acc2[i][j] = 0ull;

    int buf = 0;

    for (int k0 = 0; k0 < K; k0 += 16) {
        const bool more = (k0 + 16 < K);
        if (more) {
            int kn = k0 + 16;
            aR0 = *reinterpret_cast<const float4*>(&A[(size_t)r0 * K + kn + ac]);
            aR1 = *reinterpret_cast<const float4*>(&A[(size_t)r1 * K + kn + ac]);
            bR0 = *reinterpret_cast<const float4*>(&W[(size_t)(kn + kr) * NC + colBase + bc]);
            bR1 = *reinterpret_cast<const float4*>(&W[(size_t)(kn + kr) * NC + colBase + bc + 64]);
        }

#pragma unroll
        for (int kk = 0; kk < 16; kk++) {
            // 4 row-pairs loaded directly as 64-bit words (16B-aligned)
            ulonglong2 aa0 = *reinterpret_cast<const ulonglong2*>(&As[buf][kk][ty * 8]);
            ulonglong2 aa1 = *reinterpret_cast<const ulonglong2*>(&As[buf][kk][ty * 8 + 4]);
            float4 b0 = *reinterpret_cast<const float4*>(&Bs[buf][kk][tx * 8]);
            float4 b1 = *reinterpret_cast<const float4*>(&Bs[buf][kk][tx * 8 + 4]);
            u64 a2[4] = {aa0.x, aa0.y, aa1.x, aa1.y};
            u64 bb[8];
            bb[0] = pack2(b0.x, b0.x); bb[1] = pack2(b0.y, b0.y);
            bb[2] = pack2(b0.z, b0.z); bb[3] = pack2(b0.w, b0.w);
            bb[4] = pack2(b1.x, b1.x); bb[5] = pack2(b1.y, b1.y);
            bb[6] = pack2(b1.z, b1.z); bb[7] = pack2(b1.w, b1.w);
#pragma unroll
            for (int i = 0; i < 4; i++)
#pragma unroll
                for (int j = 0; j < 8; j++)
                    acc2[i][j] = ffma2(a2[i], bb[j], acc2[i][j]);
        }

        if (more) {
            int nb = buf ^ 1;
            As[nb][ac + 0][ar] = aR0.x; As[nb][ac + 1][ar] = aR0.y;
            As[nb][ac + 2][ar] = aR0.z; As[nb][ac + 3][ar] = aR0.w;
            As[nb][ac + 0][ar + 64] = aR1.x; As[nb][ac + 1][ar + 64] = aR1.y;
            As[nb][ac + 2][ar + 64] = aR1.z; As[nb][ac + 3][ar + 64] = aR1.w;
            *reinterpret_cast<float4*>(&Bs[nb][kr][bc])      = bR0;
            *reinterpret_cast<float4*>(&Bs[nb][kr][bc + 64]) = bR1;
        }
        __syncthreads();
        buf ^= 1;
    }

    // epilogue: each acc2[i][j] holds rows (ty*8+2i, ty*8+2i+1), col tx*8+j
    const int col = colBase + tx * 8;
    float4 bv0, bv1;
    bv0.x = bias[col + 0]; bv0.y = bias[col + 1];
    bv0.z = bias[col + 2]; bv0.w = bias[col + 3];
    bv1.x = bias[col + 4]; bv1.y = bias[col + 5];
    bv1.z = bias[col + 6]; bv1.w = bias[col + 7];
#pragma unroll
    for (int i = 0; i < 4; i++) {
        float rA[8], rB[8];
#pragma unroll
        for (int j = 0; j < 8; j++) {
            float2 f = unpack2(acc2[i][j]);
            rA[j] = f.x; rB[j] = f.y;
        }
        int rowA = rowBase + ty * 8 + 2 * i;
        int rowB = rowA + 1;
        if (rowA < M) {
            float4 o0 = make_float4(rA[0] + bv0.x, rA[1] + bv0.y, rA[2] + bv0.z, rA[3] + bv0.w);
            float4 o1 = make_float4(rA[4] + bv1.x, rA[5] + bv1.y, rA[6] + bv1.z, rA[7] + bv1.w);
            *reinterpret_cast<float4*>(&X[(size_t)rowA * NC + col])     = o0;
            *reinterpret_cast<float4*>(&X[(size_t)rowA * NC + col + 4]) = o1;
        }
        if (rowB < M) {
            float4 o0 = make_float4(rB[0] + bv0.x, rB[1] + bv0.y, rB[2] + bv0.z, rB[3] + bv0.w);
            float4 o1 = make_float4(rB[4] + bv1.x, rB[5] + bv1.y, rB[6] + bv1.z, rB[7] + bv1.w);
            *reinterpret_cast<float4*>(&X[(size_t)rowB * NC + col])     = o0;
            *reinterpret_cast<float4*>(&X[(size_t)rowB * NC + col + 4]) = o1;
        }
    }
}

// ============================================================================
// GEMM2: 128x64 tile, BK=16, double-buffered, 8x4 micro via FFMA2. K=256.
// ============================================================================
__global__ __launch_bounds__(256, 2)
void sgemm128x64_dual(const float* __restrict__ A,
                      const float* __restrict__ Wl, const float* __restrict__ bl,
                      const float* __restrict__ Wr, const float* __restrict__ br,
                      float* __restrict__ Xl, float* __restrict__ Xr)
{
    const int M = NN, K = C1, nc = HIDC;
    __shared__ float As[2][16][128 + 4];
    __shared__ float Bs[2][16][64];

    const int tid = threadIdx.x;
    const int tx = tid & 15;
    const int ty = tid >> 4;
    const int rowBase = blockIdx.x * 128;

    const int ar = tid >> 2;
    const int ac = (tid & 3) * 4;
    const int kr = tid >> 4;
    const int bc = (tid & 15) * 4;

    const int r0 = min(rowBase + ar,      M - 1);
    const int r1 = min(rowBase + ar + 64, M - 1);

    const float* Wsrc0 = (bc < nc) ? (Wl + bc) : (Wr + bc - nc);

    float4 aR0, aR1, bR0;

    aR0 = *reinterpret_cast<const float4*>(&A[(size_t)r0 * K + ac]);
    aR1 = *reinterpret_cast<const float4*>(&A[(size_t)r1 * K + ac]);
    bR0 = *reinterpret_cast<const float4*>(&Wsrc0[(size_t)kr * nc]);

    As[0][ac + 0][ar] = aR0.x; As[0][ac + 1][ar] = aR0.y;
    As[0][ac + 2][ar] = aR0.z; As[0][ac + 3][ar] = aR0.w;
    As[0][ac + 0][ar + 64] = aR1.x; As[0][ac + 1][ar + 64] = aR1.y;
    As[0][ac + 2][ar + 64] = aR1.z; As[0][ac + 3][ar + 64] = aR1.w;
    *reinterpret_cast<float4*>(&Bs[0][kr][bc]) = bR0;
    __syncthreads();

    u64 acc2[4][4];
#pragma unroll
    for (int i = 0; i < 4; i++)
#pragma unroll
        for (int j = 0; j < 4; j++) acc2[i][j] = 0ull;

    int buf = 0;

    for (int k0 = 0; k0 < K; k0 += 16) {
        const bool more = (k0 + 16 < K);
        if (more) {
            int kn = k0 + 16;
            aR0 = *reinterpret_cast<const float4*>(&A[(size_t)r0 * K + kn + ac]);
            aR1 = *reinterpret_cast<const float4*>(&A[(size_t)r1 * K + kn + ac]);
            bR0 = *reinterpret_cast<const float4*>(&Wsrc0[(size_t)(kn + kr) * nc]);
        }

#pragma unroll
        for (int kk = 0; kk < 16; kk++) {
            ulonglong2 aa0 = *reinterpret_cast<const ulonglong2*>(&As[buf][kk][ty * 8]);
            ulonglong2 aa1 = *reinterpret_cast<const ulonglong2*>(&As[buf][kk][ty * 8 + 4]);
            float4 b0 = *reinterpret_cast<const float4*>(&Bs[buf][kk][tx * 4]);
            u64 a2[4] = {aa0.x, aa0.y, aa1.x, aa1.y};
            u64 bb[4];
            bb[0] = pack2(b0.x, b0.x); bb[1] = pack2(b0.y, b0.y);
            bb[2] = pack2(b0.z, b0.z); bb[3] = pack2(b0.w, b0.w);
#pragma unroll
            for (int i = 0; i < 4; i++)
#pragma unroll
                for (int j = 0; j < 4; j++)
                    acc2[i][j] = ffma2(a2[i], bb[j], acc2[i][j]);
        }

        if (more) {
            int nb = buf ^ 1;
            As[nb][ac + 0][ar] = aR0.x; As[nb][ac + 1][ar] = aR0.y;
            As[nb][ac + 2][ar] = aR0.z; As[nb][ac + 3][ar] = aR0.w;
            As[nb][ac + 0][ar + 64] = aR1.x; As[nb][ac + 1][ar + 64] = aR1.y;
            As[nb][ac + 2][ar + 64] = aR1.z; As[nb][ac + 3][ar + 64] = aR1.w;
            *reinterpret_cast<float4*>(&Bs[nb][kr][bc]) = bR0;
        }
        __syncthreads();
        buf ^= 1;
    }

    const int col = tx * 4;
    const bool isL = (col < nc);
    float* X = isL ? Xl : Xr;
    const float* bias = isL ? bl : br;
    const int c = isL ? col : col - nc;
    float4 bv = make_float4(bias[c + 0], bias[c + 1], bias[c + 2], bias[c + 3]);
#pragma unroll
    for (int i = 0; i < 4; i++) {
        float rA[4], rB[4];
#pragma unroll
        for (int j = 0; j < 4; j++) {
            float2 f = unpack2(acc2[i][j]);
            rA[j] = f.x; rB[j] = f.y;
        }
        int rowA = rowBase + ty * 8 + 2 * i;
        int rowB = rowA + 1;
        if (rowA < M) {
            float4 o = make_float4(rA[0] + bv.x, rA[1] + bv.y, rA[2] + bv.z, rA[3] + bv.w);
            *reinterpret_cast<float4*>(&X[(size_t)rowA * nc + c]) = o;
        }
        if (rowB < M) {
            float4 o = make_float4(rB[0] + bv.x, rB[1] + bv.y, rB[2] + bv.z, rB[3] + bv.w);
            *reinterpret_cast<float4*>(&X[(size_t)rowB * nc + c]) = o;
        }
    }
}

// ---------------- CSR construction ------------------------------------------
__global__ void zero_deg_k(int* __restrict__ deg)
{
    int i = blockIdx.x * blockDim.x + threadIdx.x;
    if (i < NN) deg[i] = 0;
}

__global__ void hist_k(const int* __restrict__ ei, int* __restrict__ deg)
{
    int e = blockIdx.x * blockDim.x + threadIdx.x;
    if (e < EE) atomicAdd(&deg[ei[EE + e]], 1);
}

__global__ void scan1_k(const int* __restrict__ deg, int* __restrict__ rowptr,
                        int* __restrict__ bsums)
{
    __shared__ int sh[256];
    int tid = threadIdx.x;
    int i = blockIdx.x * 256 + tid;
    int v = (i < NN) ? deg[i] : 0;
    sh[tid] = v;
    __syncthreads();
#pragma unroll
    for (int off = 1; off < 256; off <<= 1) {
        int t = (tid >= off) ? sh[tid - off] : 0;
        __syncthreads();
        sh[tid] += t;
        __syncthreads();
    }
    if (i < NN) rowptr[i] = sh[tid] - v;
    if (tid == 255) bsums[blockIdx.x] = sh[255];
}

__global__ void scan2_k(int* __restrict__ bsums, int nb)
{
    __shared__ int sh[256];
    int tid = threadIdx.x;
    int v = (tid < nb) ? bsums[tid] : 0;
    sh[tid] = v;
    __syncthreads();
#pragma unroll
    for (int off = 1; off < 256; off <<= 1) {
        int t = (tid >= off) ? sh[tid - off] : 0;
        __syncthreads();
        sh[tid] += t;
        __syncthreads();
    }
    if (tid < nb) bsums[tid] = sh[tid] - v;
}

__global__ void scan3_k(int* __restrict__ rowptr, const int* __restrict__ bsums,
                        int* __restrict__ cursor)
{
    int i = blockIdx.x * blockDim.x + threadIdx.x;
    if (i >= NN) return;
    int r = rowptr[i] + bsums[i >> 8];
    rowptr[i] = r;
    cursor[i] = r;
}

__global__ void scatter_k(const int* __restrict__ ei, int* __restrict__ cursor,
                          int* __restrict__ csrc)
{
    int e = blockIdx.x * blockDim.x + threadIdx.x;
    if (e >= EE) return;
    int d = ei[EE + e];
    int pos = atomicAdd(&cursor[d], 1);
    csrc[pos] = ei[e];
}

// ---------------- fused GATv2 edge phase, layer 1 ---------------------------
__global__ __launch_bounds__(256)
void edge_fused1_k(const int* __restrict__ rowptr, const int* __restrict__ deg,
                   const int* __restrict__ csrc,
                   const float* __restrict__ xl, const float* __restrict__ xr,
                   const float* __restrict__ att, const float* __restrict__ bias,
                   float* __restrict__ h1)
{
    int w = (blockIdx.x * blockDim.x + threadIdx.x) >> 5;
    if (w >= NN) return;
    int lane = threadIdx.x & 31;

    const float4* pb = reinterpret_cast<const float4*>(xr + (size_t)w * C1 + lane * 8);
    float4 b0 = pb[0], b1 = pb[1];
    const float4* pt = reinterpret_cast<const float4*>(att + lane * 8);
    float4 t0 = pt[0], t1 = pt[1];

    float acc[8] = {};
    float den = 0.f;

    int start = rowptr[w];
    int dg    = deg[w];

    int s = (dg > 0) ? csrc[start] : 0;
    const float4* pa = reinterpret_cast<const float4*>(xl + (size_t)s * C1 + lane * 8);
    float4 a0 = pa[0], a1 = pa[1];

    for (int i = 0; i < dg; i++) {
        int snext = (i + 1 < dg) ? csrc[start + i + 1] : s;
        const float4* pn = reinterpret_cast<const float4*>(
            xl + (size_t)snext * C1 + lane * 8);
        float4 n0 = pn[0], n1 = pn[1];

        float p = lrelu(a0.x + b0.x) * t0.x + lrelu(a0.y + b0.y) * t0.y
                + lrelu(a0.z + b0.z) * t0.z + lrelu(a0.w + b0.w) * t0.w
                + lrelu(a1.x + b1.x) * t1.x + lrelu(a1.y + b1.y) * t1.y
                + lrelu(a1.z + b1.z) * t1.z + lrelu(a1.w + b1.w) * t1.w;
        p += __shfl_xor_sync(0xffffffffu, p, 1);
        p += __shfl_xor_sync(0xffffffffu, p, 2);
        float ex = __expf(p);
        den += ex;
        acc[0] += ex * a0.x; acc[1] += ex * a0.y;
        acc[2] += ex * a0.z; acc[3] += ex * a0.w;
        acc[4] += ex * a1.x; acc[5] += ex * a1.y;
        acc[6] += ex * a1.z; acc[7] += ex * a1.w;

        a0 = n0; a1 = n1;
    }

    float inv = 1.f / (den + 1e-16f);
    const float* bi = bias + lane * 8;
    float4 o0, o1;
    o0.x = elu(acc[0] * inv + bi[0]); o0.y = elu(acc[1] * inv + bi[1]);
    o0.z = elu(acc[2] * inv + bi[2]); o0.w = elu(acc[3] * inv + bi[3]);
    o1.x = elu(acc[4] * inv + bi[4]); o1.y = elu(acc[5] * inv + bi[5]);
    o1.z = elu(acc[6] * inv + bi[6]); o1.w = elu(acc[7] * inv + bi[7]);
    float4* out = reinterpret_cast<float4*>(h1 + (size_t)w * C1 + lane * 8);
    out[0] = o0; out[1] = o1;
}

// ---------------- fused edge phase layer 2 + final linear head --------------
__global__ __launch_bounds__(256)
void edge_fused2_head_k(const int* __restrict__ rowptr, const int* __restrict__ deg,
                        const int* __restrict__ csrc,
                        const float* __restrict__ xl, const float* __restrict__ xr,
                        const float* __restrict__ att, const float* __restrict__ bias,
                        const float* __restrict__ Wlin, const float* __restrict__ blin,
                        float* __restrict__ out)
{
    __shared__ float Ws[HIDC][OUTDIM];      // 32x64 = 8 KB
    __shared__ float bs[OUTDIM];

    for (int i = threadIdx.x; i < HIDC * OUTDIM; i += blockDim.x)
        Ws[i >> 6][i & 63] = Wlin[i];
    if (threadIdx.x < OUTDIM) bs[threadIdx.x] = blin[threadIdx.x];
    __syncthreads();

    int w = (blockIdx.x * blockDim.x + threadIdx.x) >> 5;
    int lane = threadIdx.x & 31;
    if (w >= NN) return;

    float b = xr[(size_t)w * HIDC + lane];
    float t = att[lane];

    float acc = 0.f, den = 0.f;
    int start = rowptr[w];
    int dg    = deg[w];

    int s = (dg > 0) ? csrc[start] : 0;
    float a = xl[(size_t)s * HIDC + lane];

    for (int i = 0; i < dg; i++) {
        int snext = (i + 1 < dg) ? csrc[start + i + 1] : s;
        float n = xl[(size_t)snext * HIDC + lane];

        float p = lrelu(a + b) * t;
        p += __shfl_xor_sync(0xffffffffu, p, 16);
        p += __shfl_xor_sync(0xffffffffu, p, 8);
        p += __shfl_xor_sync(0xffffffffu, p, 4);
        p += __shfl_xor_sync(0xffffffffu, p, 2);
        p += __shfl_xor_sync(0xffffffffu, p, 1);
        float ex = __expf(p);
        den += ex;
        acc += ex * a;

        a = n;
    }
    float inv = 1.f / (den + 1e-16f);
    float hval = elu(acc * inv + bias[lane]);   // h2[w][lane]

    float o0 = bs[lane];
    float o1 = bs[lane + 32];
#pragma unroll
    for (int k = 0; k < HIDC; k++) {
        float v = __shfl_sync(0xffffffffu, hval, k);
        o0 = fmaf(v, Ws[k][lane],      o0);
        o1 = fmaf(v, Ws[k][lane + 32], o1);
    }
    out[(size_t)w * OUTDIM + lane]      = o0;
    out[(size_t)w * OUTDIM + lane + 32] = o1;
}

// ---------------- launch ------------------------------------------------------
extern "C" void kernel_launch(void* const* d_in, const int* in_sizes, int n_in,
                              void* d_out, int out_size)
{
    const float* x     = (const float*)d_in[0];
    const int*   ei    = (const int*)d_in[1];
    const float* W1l   = (const float*)d_in[2];
    const float* b1l   = (const float*)d_in[3];
    const float* W1r   = (const float*)d_in[4];
    const float* b1r   = (const float*)d_in[5];
    const float* att1  = (const float*)d_in[6];
    const float* bias1 = (const float*)d_in[7];
    const float* W2l   = (const float*)d_in[8];
    const float* b2l   = (const float*)d_in[9];
    const float* W2r   = (const float*)d_in[10];
    const float* b2r   = (const float*)d_in[11];
    const float* att2  = (const float*)d_in[12];
    const float* bias2 = (const float*)d_in[13];
    const float* Wlin  = (const float*)d_in[14];
    const float* blin  = (const float*)d_in[15];
    float* out = (float*)d_out;

    float *xl1, *xr1, *h1, *xl2, *xr2;
    int *deg, *rowptr, *cursor, *csrc, *bsums;
    cudaGetSymbolAddress((void**)&xl1, g_xl1);
    cudaGetSymbolAddress((void**)&xr1, g_xr1);
    cudaGetSymbolAddress((void**)&h1,  g_h1);
    cudaGetSymbolAddress((void**)&xl2, g_xl2);
    cudaGetSymbolAddress((void**)&xr2, g_xr2);
    cudaGetSymbolAddress((void**)&deg,    g_deg);
    cudaGetSymbolAddress((void**)&rowptr, g_rowptr);
    cudaGetSymbolAddress((void**)&cursor, g_cursor);
    cudaGetSymbolAddress((void**)&csrc,   g_csrc);
    cudaGetSymbolAddress((void**)&bsums,  g_bsums);

    const int TPB = 256;
    const int nScanBlocks = (NN + 255) / 256;       // 196

    // launch order keeps sgemm128_dual at index 3 (ncu samples launch #4)
    zero_deg_k<<<(NN + TPB - 1) / TPB, TPB>>>(deg);                       // 0
    hist_k<<<(EE + TPB - 1) / TPB, TPB>>>(ei, deg);                       // 1
    scan1_k<<<nScanBlocks, 256>>>(deg, rowptr, bsums);                    // 2

    dim3 gg1(4, (NN + 127) / 128);
    sgemm128_dual<<<gg1, TPB>>>(x, W1l, b1l, W1r, b1r, xl1, xr1);         // 3

    scan2_k<<<1, 256>>>(bsums, nScanBlocks);                              // 4
    scan3_k<<<(NN + TPB - 1) / TPB, TPB>>>(rowptr, bsums, cursor);        // 5
    scatter_k<<<(EE + TPB - 1) / TPB, TPB>>>(ei, cursor, csrc);           // 6

    int eblocks = (NN * 32 + TPB - 1) / TPB;
    edge_fused1_k<<<eblocks, TPB>>>(rowptr, deg, csrc, xl1, xr1, att1, bias1, h1); // 7

    sgemm128x64_dual<<<(NN + 127) / 128, TPB>>>(h1, W2l, b2l, W2r, b2r, xl2, xr2); // 8

    edge_fused2_head_k<<<eblocks, TPB>>>(rowptr, deg, csrc, xl2, xr2,
                                         att2, bias2, Wlin, blin, out);   // 9
}

// round 8
// speedup vs baseline: 3.2844x; 1.2460x over previous
#include <cuda_runtime.h>
#include <cuda_bf16.h>
#include <cstdint>

#define NN      50000
#define EE      800000
#define INDIM   256
#define HIDC    32
#define NHEADS  8
#define OUTDIM  64
#define C1      (NHEADS * HIDC)   // 256
#define NB      512               // total output cols of GEMM1 (Wl|Wr)
#define NEGSLOPE 0.2f

typedef unsigned long long u64;

// ---------------- scratch (device globals) ---------------------------------
__device__ float g_xl1[(size_t)NN * C1];
__device__ float g_xr1[(size_t)NN * C1];
__device__ float g_h1 [(size_t)NN * C1];
__device__ float g_xl2[(size_t)NN * HIDC];
__device__ float g_xr2[(size_t)NN * HIDC];
__device__ int   g_deg   [NN];
__device__ int   g_rowptr[NN];
__device__ int   g_cursor[NN];
__device__ int   g_csrc  [EE];
__device__ int   g_bsums [256];
// bf16 split operands for GEMM1
__device__ __align__(16) __nv_bfloat16 g_Ah[(size_t)NN * INDIM];
__device__ __align__(16) __nv_bfloat16 g_Al[(size_t)NN * INDIM];
__device__ __align__(16) __nv_bfloat16 g_Bh[(size_t)NB * INDIM];
__device__ __align__(16) __nv_bfloat16 g_Bl[(size_t)NB * INDIM];

// ---------------- helpers ---------------------------------------------------
__device__ __forceinline__ float lrelu(float v) { return v > 0.f ? v : NEGSLOPE * v; }
__device__ __forceinline__ float elu(float v)   { return v > 0.f ? v : expm1f(v); }

__device__ __forceinline__ u64 ffma2(u64 a, u64 b, u64 c)
{
    u64 d;
    asm("fma.rn.f32x2 %0, %1, %2, %3;" : "=l"(d) : "l"(a), "l"(b), "l"(c));
    return d;
}
__device__ __forceinline__ u64 pack2(float x, float y)
{
    u64 d;
    asm("mov.b64 %0, {%1, %2};" : "=l"(d) : "f"(x), "f"(y));
    return d;
}
__device__ __forceinline__ float2 unpack2(u64 v)
{
    float2 r;
    asm("mov.b64 {%0, %1}, %2;" : "=f"(r.x), "=f"(r.y) : "l"(v));
    return r;
}

// bf16 tensor-core mma (base-target instruction, sm_80+; OK on compute_103)
#define MMA_BF16(d, a0, a1, a2, a3, b0, b1)                                  \
    asm volatile(                                                            \
        "mma.sync.aligned.m16n8k16.row.col.f32.bf16.bf16.f32 "               \
        "{%0,%1,%2,%3}, {%4,%5,%6,%7}, {%8,%9}, {%0,%1,%2,%3};"              \
        : "+f"((d)[0]), "+f"((d)[1]), "+f"((d)[2]), "+f"((d)[3])             \
        : "r"(a0), "r"(a1), "r"(a2), "r"(a3), "r"(b0), "r"(b1))

// ---------------- conversion kernels -----------------------------------------
__global__ void conv_x_k(const float* __restrict__ x,
                         __nv_bfloat16* __restrict__ Ah,
                         __nv_bfloat16* __restrict__ Al)
{
    size_t i = (size_t)blockIdx.x * blockDim.x + threadIdx.x;
    if (i >= (size_t)NN * INDIM) return;
    float v = x[i];
    __nv_bfloat16 h = __float2bfloat16(v);
    Ah[i] = h;
    Al[i] = __float2bfloat16(v - __bfloat162float(h));
}

// B[n][k] = (n<256 ? W1l[k][n] : W1r[k][n-256]); B row-major [NB][INDIM]
__global__ void conv_w_k(const float* __restrict__ W1l, const float* __restrict__ W1r,
                         __nv_bfloat16* __restrict__ Bh, __nv_bfloat16* __restrict__ Bl)
{
    int i = blockIdx.x * blockDim.x + threadIdx.x;
    if (i >= NB * INDIM) return;
    int n = i >> 8;          // 0..511
    int k = i & 255;
    float v = (n < C1) ? W1l[(size_t)k * C1 + n] : W1r[(size_t)k * C1 + (n - C1)];
    __nv_bfloat16 h = __float2bfloat16(v);
    Bh[i] = h;
    Bl[i] = __float2bfloat16(v - __bfloat162float(h));
}

// ============================================================================
// GEMM1 via mma.sync bf16 3-product split.
// CTA tile 128(M) x 128(N), K chunked by 64. 8 warps = 2(M) x 4(N),
// warp tile 64x32. smem tiles padded to stride 72 bf16 (conflict-free frags).
// ============================================================================
#define PAD   72
#define TSZ   (128 * PAD)            // bf16 elements per tile
#define SMEM_BYTES (4 * TSZ * 2)     // Ah,Al,Bh,Bl = 73728 bytes

__global__ __launch_bounds__(256)
void gemm1_mma(const __nv_bfloat16* __restrict__ Ah, const __nv_bfloat16* __restrict__ Al,
               const __nv_bfloat16* __restrict__ Bh, const __nv_bfloat16* __restrict__ Bl,
               const float* __restrict__ bl1, const float* __restrict__ br1,
               float* __restrict__ Xl, float* __restrict__ Xr)
{
    extern __shared__ __nv_bfloat16 sm[];
    __nv_bfloat16* sAh = sm;
    __nv_bfloat16* sAl = sm + TSZ;
    __nv_bfloat16* sBh = sm + 2 * TSZ;
    __nv_bfloat16* sBl = sm + 3 * TSZ;

    const int tid  = threadIdx.x;
    const int wid  = tid >> 5;
    const int lane = tid & 31;
    const int wm   = wid & 1;        // 0..1  -> 64-row half
    const int wn   = wid >> 1;       // 0..3  -> 32-col quarter
    const int rowBase = blockIdx.y * 128;
    const int colBase = blockIdx.x * 128;

    const int lr = lane >> 2;        // 0..7
    const int lc = (lane & 3) * 2;   // 0,2,4,6

    float acc[4][4][4];
#pragma unroll
    for (int i = 0; i < 4; i++)
#pragma unroll
        for (int j = 0; j < 4; j++)
#pragma unroll
            for (int f = 0; f < 4; f++) acc[i][j][f] = 0.f;

    for (int kc = 0; kc < 4; kc++) {
        const int kOff = kc * 64;
        // ---- load A tiles (128 x 64 bf16, hi+lo) ----
        for (int idx = tid; idx < 1024; idx += 256) {
            int r  = idx >> 3;
            int k8 = (idx & 7) * 8;
            int grow = min(rowBase + r, NN - 1);
            *(uint4*)(sAh + r * PAD + k8) =
                *(const uint4*)(Ah + (size_t)grow * INDIM + kOff + k8);
            *(uint4*)(sAl + r * PAD + k8) =
                *(const uint4*)(Al + (size_t)grow * INDIM + kOff + k8);
        }
        // ---- load B tiles (128 x 64 bf16, hi+lo) ----
        for (int idx = tid; idx < 1024; idx += 256) {
            int r  = idx >> 3;
            int k8 = (idx & 7) * 8;
            *(uint4*)(sBh + r * PAD + k8) =
                *(const uint4*)(Bh + (size_t)(colBase + r) * INDIM + kOff + k8);
            *(uint4*)(sBl + r * PAD + k8) =
                *(const uint4*)(Bl + (size_t)(colBase + r) * INDIM + kOff + k8);
        }
        __syncthreads();

#pragma unroll
        for (int ks = 0; ks < 4; ks++) {
            const int k0 = ks * 16;
            uint32_t bh[4][2], bl_[4][2];
#pragma unroll
            for (int j = 0; j < 4; j++) {
                const __nv_bfloat16* p = sBh + (wn * 32 + j * 8 + lr) * PAD + k0 + lc;
                bh[j][0] = *(const uint32_t*)p;
                bh[j][1] = *(const uint32_t*)(p + 8);
                const __nv_bfloat16* q = sBl + (wn * 32 + j * 8 + lr) * PAD + k0 + lc;
                bl_[j][0] = *(const uint32_t*)q;
                bl_[j][1] = *(const uint32_t*)(q + 8);
            }
#pragma unroll
            for (int i = 0; i < 4; i++) {
                const __nv_bfloat16* p = sAh + (wm * 64 + i * 16 + lr) * PAD + k0 + lc;
                uint32_t ah0 = *(const uint32_t*)p;
                uint32_t ah1 = *(const uint32_t*)(p + 8 * PAD);
                uint32_t ah2 = *(const uint32_t*)(p + 8);
                uint32_t ah3 = *(const uint32_t*)(p + 8 * PAD + 8);
                const __nv_bfloat16* q = sAl + (wm * 64 + i * 16 + lr) * PAD + k0 + lc;
                uint32_t al0 = *(const uint32_t*)q;
                uint32_t al1 = *(const uint32_t*)(q + 8 * PAD);
                uint32_t al2 = *(const uint32_t*)(q + 8);
                uint32_t al3 = *(const uint32_t*)(q + 8 * PAD + 8);
#pragma unroll
                for (int j = 0; j < 4; j++) {
                    MMA_BF16(acc[i][j], ah0, ah1, ah2, ah3, bh[j][0], bh[j][1]);
                    MMA_BF16(acc[i][j], ah0, ah1, ah2, ah3, bl_[j][0], bl_[j][1]);
                    MMA_BF16(acc[i][j], al0, al1, al2, al3, bh[j][0], bh[j][1]);
                }
            }
        }
        __syncthreads();
    }

    // ---- epilogue ----
    const bool isL = (colBase < C1);
    float* X = isL ? Xl : Xr;
    const float* bs = isL ? bl1 : br1;
    const int cb = isL ? colBase : colBase - C1;
#pragma unroll
    for (int i = 0; i < 4; i++) {
        int r0 = rowBase + wm * 64 + i * 16 + lr;
#pragma unroll
        for (int j = 0; j < 4; j++) {
            int c = cb + wn * 32 + j * 8 + lc;
            float b0 = bs[c], b1 = bs[c + 1];
            if (r0 < NN) {
                float2 o = make_float2(acc[i][j][0] + b0, acc[i][j][1] + b1);
                *(float2*)(X + (size_t)r0 * C1 + c) = o;
            }
            if (r0 + 8 < NN) {
                float2 o = make_float2(acc[i][j][2] + b0, acc[i][j][3] + b1);
                *(float2*)(X + (size_t)(r0 + 8) * C1 + c) = o;
            }
        }
    }
}

// ============================================================================
// GEMM2: 128x64 tile, BK=16, double-buffered, 8x4 micro via FFMA2. K=256.
// ============================================================================
__global__ __launch_bounds__(256, 2)
void sgemm128x64_dual(const float* __restrict__ A,
                      const float* __restrict__ Wl, const float* __restrict__ bl,
                      const float* __restrict__ Wr, const float* __restrict__ br,
                      float* __restrict__ Xl, float* __restrict__ Xr)
{
    const int M = NN, K = C1, nc = HIDC;
    __shared__ float As[2][16][128 + 4];
    __shared__ float Bs[2][16][64];

    const int tid = threadIdx.x;
    const int tx = tid & 15;
    const int ty = tid >> 4;
    const int rowBase = blockIdx.x * 128;

    const int ar = tid >> 2;
    const int ac = (tid & 3) * 4;
    const int kr = tid >> 4;
    const int bc = (tid & 15) * 4;

    const int r0 = min(rowBase + ar,      M - 1);
    const int r1 = min(rowBase + ar + 64, M - 1);

    const float* Wsrc0 = (bc < nc) ? (Wl + bc) : (Wr + bc - nc);

    float4 aR0, aR1, bR0;

    aR0 = *reinterpret_cast<const float4*>(&A[(size_t)r0 * K + ac]);
    aR1 = *reinterpret_cast<const float4*>(&A[(size_t)r1 * K + ac]);
    bR0 = *reinterpret_cast<const float4*>(&Wsrc0[(size_t)kr * nc]);

    As[0][ac + 0][ar] = aR0.x; As[0][ac + 1][ar] = aR0.y;
    As[0][ac + 2][ar] = aR0.z; As[0][ac + 3][ar] = aR0.w;
    As[0][ac + 0][ar + 64] = aR1.x; As[0][ac + 1][ar + 64] = aR1.y;
    As[0][ac + 2][ar + 64] = aR1.z; As[0][ac + 3][ar + 64] = aR1.w;
    *reinterpret_cast<float4*>(&Bs[0][kr][bc]) = bR0;
    __syncthreads();

    u64 acc2[4][4];
#pragma unroll
    for (int i = 0; i < 4; i++)
#pragma unroll
        for (int j = 0; j < 4; j++) acc2[i][j] = 0ull;

    int buf = 0;

    for (int k0 = 0; k0 < K; k0 += 16) {
        const bool more = (k0 + 16 < K);
        if (more) {
            int kn = k0 + 16;
            aR0 = *reinterpret_cast<const float4*>(&A[(size_t)r0 * K + kn + ac]);
            aR1 = *reinterpret_cast<const float4*>(&A[(size_t)r1 * K + kn + ac]);
            bR0 = *reinterpret_cast<const float4*>(&Wsrc0[(size_t)(kn + kr) * nc]);
        }

#pragma unroll
        for (int kk = 0; kk < 16; kk++) {
            ulonglong2 aa0 = *reinterpret_cast<const ulonglong2*>(&As[buf][kk][ty * 8]);
            ulonglong2 aa1 = *reinterpret_cast<const ulonglong2*>(&As[buf][kk][ty * 8 + 4]);
            float4 b0 = *reinterpret_cast<const float4*>(&Bs[buf][kk][tx * 4]);
            u64 a2[4] = {aa0.x, aa0.y, aa1.x, aa1.y};
            u64 bb[4];
            bb[0] = pack2(b0.x, b0.x); bb[1] = pack2(b0.y, b0.y);
            bb[2] = pack2(b0.z, b0.z); bb[3] = pack2(b0.w, b0.w);
#pragma unroll
            for (int i = 0; i < 4; i++)
#pragma unroll
                for (int j = 0; j < 4; j++)
                    acc2[i][j] = ffma2(a2[i], bb[j], acc2[i][j]);
        }

        if (more) {
            int nb = buf ^ 1;
            As[nb][ac + 0][ar] = aR0.x; As[nb][ac + 1][ar] = aR0.y;
            As[nb][ac + 2][ar] = aR0.z; As[nb][ac + 3][ar] = aR0.w;
            As[nb][ac + 0][ar + 64] = aR1.x; As[nb][ac + 1][ar + 64] = aR1.y;
            As[nb][ac + 2][ar + 64] = aR1.z; As[nb][ac + 3][ar + 64] = aR1.w;
            *reinterpret_cast<float4*>(&Bs[nb][kr][bc]) = bR0;
        }
        __syncthreads();
        buf ^= 1;
    }

    const int col = tx * 4;
    const bool isL = (col < nc);
    float* X = isL ? Xl : Xr;
    const float* bias = isL ? bl : br;
    const int c = isL ? col : col - nc;
    float4 bv = make_float4(bias[c + 0], bias[c + 1], bias[c + 2], bias[c + 3]);
#pragma unroll
    for (int i = 0; i < 4; i++) {
        float rA[4], rB[4];
#pragma unroll
        for (int j = 0; j < 4; j++) {
            float2 f = unpack2(acc2[i][j]);
            rA[j] = f.x; rB[j] = f.y;
        }
        int rowA = rowBase + ty * 8 + 2 * i;
        int rowB = rowA + 1;
        if (rowA < M) {
            float4 o = make_float4(rA[0] + bv.x, rA[1] + bv.y, rA[2] + bv.z, rA[3] + bv.w);
            *reinterpret_cast<float4*>(&X[(size_t)rowA * nc + c]) = o;
        }
        if (rowB < M) {
            float4 o = make_float4(rB[0] + bv.x, rB[1] + bv.y, rB[2] + bv.z, rB[3] + bv.w);
            *reinterpret_cast<float4*>(&X[(size_t)rowB * nc + c]) = o;
        }
    }
}

// ---------------- CSR construction ------------------------------------------
__global__ void zero_deg_k(int* __restrict__ deg)
{
    int i = blockIdx.x * blockDim.x + threadIdx.x;
    if (i < NN) deg[i] = 0;
}

__global__ void hist_k(const int* __restrict__ ei, int* __restrict__ deg)
{
    int e = blockIdx.x * blockDim.x + threadIdx.x;
    if (e < EE) atomicAdd(&deg[ei[EE + e]], 1);
}

__global__ void scan1_k(const int* __restrict__ deg, int* __restrict__ rowptr,
                        int* __restrict__ bsums)
{
    __shared__ int sh[256];
    int tid = threadIdx.x;
    int i = blockIdx.x * 256 + tid;
    int v = (i < NN) ? deg[i] : 0;
    sh[tid] = v;
    __syncthreads();
#pragma unroll
    for (int off = 1; off < 256; off <<= 1) {
        int t = (tid >= off) ? sh[tid - off] : 0;
        __syncthreads();
        sh[tid] += t;
        __syncthreads();
    }
    if (i < NN) rowptr[i] = sh[tid] - v;
    if (tid == 255) bsums[blockIdx.x] = sh[255];
}

__global__ void scan2_k(int* __restrict__ bsums, int nb)
{
    __shared__ int sh[256];
    int tid = threadIdx.x;
    int v = (tid < nb) ? bsums[tid] : 0;
    sh[tid] = v;
    __syncthreads();
#pragma unroll
    for (int off = 1; off < 256; off <<= 1) {
        int t = (tid >= off) ? sh[tid - off] : 0;
        __syncthreads();
        sh[tid] += t;
        __syncthreads();
    }
    if (tid < nb) bsums[tid] = sh[tid] - v;
}

__global__ void scan3_k(int* __restrict__ rowptr, const int* __restrict__ bsums,
                        int* __restrict__ cursor)
{
    int i = blockIdx.x * blockDim.x + threadIdx.x;
    if (i >= NN) return;
    int r = rowptr[i] + bsums[i >> 8];
    rowptr[i] = r;
    cursor[i] = r;
}

__global__ void scatter_k(const int* __restrict__ ei, int* __restrict__ cursor,
                          int* __restrict__ csrc)
{
    int e = blockIdx.x * blockDim.x + threadIdx.x;
    if (e >= EE) return;
    int d = ei[EE + e];
    int pos = atomicAdd(&cursor[d], 1);
    csrc[pos] = ei[e];
}

// ---------------- fused GATv2 edge phase, layer 1 ---------------------------
__global__ __launch_bounds__(256)
void edge_fused1_k(const int* __restrict__ rowptr, const int* __restrict__ deg,
                   const int* __restrict__ csrc,
                   const float* __restrict__ xl, const float* __restrict__ xr,
                   const float* __restrict__ att, const float* __restrict__ bias,
                   float* __restrict__ h1)
{
    int w = (blockIdx.x * blockDim.x + threadIdx.x) >> 5;
    if (w >= NN) return;
    int lane = threadIdx.x & 31;

    const float4* pb = reinterpret_cast<const float4*>(xr + (size_t)w * C1 + lane * 8);
    float4 b0 = pb[0], b1 = pb[1];
    const float4* pt = reinterpret_cast<const float4*>(att + lane * 8);
    float4 t0 = pt[0], t1 = pt[1];

    float acc[8] = {};
    float den = 0.f;

    int start = rowptr[w];
    int dg    = deg[w];

    int s = (dg > 0) ? csrc[start] : 0;
    const float4* pa = reinterpret_cast<const float4*>(xl + (size_t)s * C1 + lane * 8);
    float4 a0 = pa[0], a1 = pa[1];

    for (int i = 0; i < dg; i++) {
        int snext = (i + 1 < dg) ? csrc[start + i + 1] : s;
        const float4* pn = reinterpret_cast<const float4*>(
            xl + (size_t)snext * C1 + lane * 8);
        float4 n0 = pn[0], n1 = pn[1];

        float p = lrelu(a0.x + b0.x) * t0.x + lrelu(a0.y + b0.y) * t0.y
                + lrelu(a0.z + b0.z) * t0.z + lrelu(a0.w + b0.w) * t0.w
                + lrelu(a1.x + b1.x) * t1.x + lrelu(a1.y + b1.y) * t1.y
                + lrelu(a1.z + b1.z) * t1.z + lrelu(a1.w + b1.w) * t1.w;
        p += __shfl_xor_sync(0xffffffffu, p, 1);
        p += __shfl_xor_sync(0xffffffffu, p, 2);
        float ex = __expf(p);
        den += ex;
        acc[0] += ex * a0.x; acc[1] += ex * a0.y;
        acc[2] += ex * a0.z; acc[3] += ex * a0.w;
        acc[4] += ex * a1.x; acc[5] += ex * a1.y;
        acc[6] += ex * a1.z; acc[7] += ex * a1.w;

        a0 = n0; a1 = n1;
    }

    float inv = 1.f / (den + 1e-16f);
    const float* bi = bias + lane * 8;
    float4 o0, o1;
    o0.x = elu(acc[0] * inv + bi[0]); o0.y = elu(acc[1] * inv + bi[1]);
    o0.z = elu(acc[2] * inv + bi[2]); o0.w = elu(acc[3] * inv + bi[3]);
    o1.x = elu(acc[4] * inv + bi[4]); o1.y = elu(acc[5] * inv + bi[5]);
    o1.z = elu(acc[6] * inv + bi[6]); o1.w = elu(acc[7] * inv + bi[7]);
    float4* out = reinterpret_cast<float4*>(h1 + (size_t)w * C1 + lane * 8);
    out[0] = o0; out[1] = o1;
}

// ---------------- fused edge phase layer 2 + final linear head --------------
__global__ __launch_bounds__(256)
void edge_fused2_head_k(const int* __restrict__ rowptr, const int* __restrict__ deg,
                        const int* __restrict__ csrc,
                        const float* __restrict__ xl, const float* __restrict__ xr,
                        const float* __restrict__ att, const float* __restrict__ bias,
                        const float* __restrict__ Wlin, const float* __restrict__ blin,
                        float* __restrict__ out)
{
    __shared__ float Ws[HIDC][OUTDIM];      // 32x64 = 8 KB
    __shared__ float bs[OUTDIM];

    for (int i = threadIdx.x; i < HIDC * OUTDIM; i += blockDim.x)
        Ws[i >> 6][i & 63] = Wlin[i];
    if (threadIdx.x < OUTDIM) bs[threadIdx.x] = blin[threadIdx.x];
    __syncthreads();

    int w = (blockIdx.x * blockDim.x + threadIdx.x) >> 5;
    int lane = threadIdx.x & 31;
    if (w >= NN) return;

    float b = xr[(size_t)w * HIDC + lane];
    float t = att[lane];

    float acc = 0.f, den = 0.f;
    int start = rowptr[w];
    int dg    = deg[w];

    int s = (dg > 0) ? csrc[start] : 0;
    float a = xl[(size_t)s * HIDC + lane];

    for (int i = 0; i < dg; i++) {
        int snext = (i + 1 < dg) ? csrc[start + i + 1] : s;
        float n = xl[(size_t)snext * HIDC + lane];

        float p = lrelu(a + b) * t;
        p += __shfl_xor_sync(0xffffffffu, p, 16);
        p += __shfl_xor_sync(0xffffffffu, p, 8);
        p += __shfl_xor_sync(0xffffffffu, p, 4);
        p += __shfl_xor_sync(0xffffffffu, p, 2);
        p += __shfl_xor_sync(0xffffffffu, p, 1);
        float ex = __expf(p);
        den += ex;
        acc += ex * a;

        a = n;
    }
    float inv = 1.f / (den + 1e-16f);
    float hval = elu(acc * inv + bias[lane]);   // h2[w][lane]

    float o0 = bs[lane];
    float o1 = bs[lane + 32];
#pragma unroll
    for (int k = 0; k < HIDC; k++) {
        float v = __shfl_sync(0xffffffffu, hval, k);
        o0 = fmaf(v, Ws[k][lane],      o0);
        o1 = fmaf(v, Ws[k][lane + 32], o1);
    }
    out[(size_t)w * OUTDIM + lane]      = o0;
    out[(size_t)w * OUTDIM + lane + 32] = o1;
}

// ---------------- launch ------------------------------------------------------
extern "C" void kernel_launch(void* const* d_in, const int* in_sizes, int n_in,
                              void* d_out, int out_size)
{
    const float* x     = (const float*)d_in[0];
    const int*   ei    = (const int*)d_in[1];
    const float* W1l   = (const float*)d_in[2];
    const float* b1l   = (const float*)d_in[3];
    const float* W1r   = (const float*)d_in[4];
    const float* b1r   = (const float*)d_in[5];
    const float* att1  = (const float*)d_in[6];
    const float* bias1 = (const float*)d_in[7];
    const float* W2l   = (const float*)d_in[8];
    const float* b2l   = (const float*)d_in[9];
    const float* W2r   = (const float*)d_in[10];
    const float* b2r   = (const float*)d_in[11];
    const float* att2  = (const float*)d_in[12];
    const float* bias2 = (const float*)d_in[13];
    const float* Wlin  = (const float*)d_in[14];
    const float* blin  = (const float*)d_in[15];
    float* out = (float*)d_out;

    float *xl1, *xr1, *h1, *xl2, *xr2;
    int *deg, *rowptr, *cursor, *csrc, *bsums;
    __nv_bfloat16 *Ah, *Al, *Bh, *Bl;
    cudaGetSymbolAddress((void**)&xl1, g_xl1);
    cudaGetSymbolAddress((void**)&xr1, g_xr1);
    cudaGetSymbolAddress((void**)&h1,  g_h1);
    cudaGetSymbolAddress((void**)&xl2, g_xl2);
    cudaGetSymbolAddress((void**)&xr2, g_xr2);
    cudaGetSymbolAddress((void**)&deg,    g_deg);
    cudaGetSymbolAddress((void**)&rowptr, g_rowptr);
    cudaGetSymbolAddress((void**)&cursor, g_cursor);
    cudaGetSymbolAddress((void**)&csrc,   g_csrc);
    cudaGetSymbolAddress((void**)&bsums,  g_bsums);
    cudaGetSymbolAddress((void**)&Ah, g_Ah);
    cudaGetSymbolAddress((void**)&Al, g_Al);
    cudaGetSymbolAddress((void**)&Bh, g_Bh);
    cudaGetSymbolAddress((void**)&Bl, g_Bl);

    cudaFuncSetAttribute(gemm1_mma, cudaFuncAttributeMaxDynamicSharedMemorySize,
                         SMEM_BYTES);

    const int TPB = 256;
    const int nScanBlocks = (NN + 255) / 256;       // 196

    conv_x_k<<<(NN * INDIM + TPB - 1) / TPB, TPB>>>(x, Ah, Al);           // 0
    conv_w_k<<<(NB * INDIM + TPB - 1) / TPB, TPB>>>(W1l, W1r, Bh, Bl);    // 1
    zero_deg_k<<<(NN + TPB - 1) / TPB, TPB>>>(deg);                       // 2

    dim3 gg1(4, (NN + 127) / 128);
    gemm1_mma<<<gg1, TPB, SMEM_BYTES>>>(Ah, Al, Bh, Bl,
                                        b1l, b1r, xl1, xr1);              // 3 (profiled)

    hist_k<<<(EE + TPB - 1) / TPB, TPB>>>(ei, deg);                       // 4
    scan1_k<<<nScanBlocks, 256>>>(deg, rowptr, bsums);                    // 5
    scan2_k<<<1, 256>>>(bsums, nScanBlocks);                              // 6
    scan3_k<<<(NN + TPB - 1) / TPB, TPB>>>(rowptr, bsums, cursor);        // 7
    scatter_k<<<(EE + TPB - 1) / TPB, TPB>>>(ei, cursor, csrc);           // 8

    int eblocks = (NN * 32 + TPB - 1) / TPB;
    edge_fused1_k<<<eblocks, TPB>>>(rowptr, deg, csrc, xl1, xr1, att1, bias1, h1); // 9

    sgemm128x64_dual<<<(NN + 127) / 128, TPB>>>(h1, W2l, b2l, W2r, b2r, xl2, xr2); // 10

    edge_fused2_head_k<<<eblocks, TPB>>>(rowptr, deg, csrc, xl2, xr2,
                                         att2, bias2, Wlin, blin, out);   // 11
}

// round 9
// speedup vs baseline: 3.3705x; 1.0262x over previous
#include <cuda_runtime.h>
#include <cuda_bf16.h>
#include <cstdint>

#define NN      50000
#define EE      800000
#define INDIM   256
#define HIDC    32
#define NHEADS  8
#define OUTDIM  64
#define C1      (NHEADS * HIDC)   // 256
#define NB      512               // total output cols of GEMM1 (Wl|Wr)
#define NEGSLOPE 0.2f

typedef unsigned long long u64;

// ---------------- scratch (device globals) ---------------------------------
__device__ float g_xl1[(size_t)NN * C1];
__device__ float g_xr1[(size_t)NN * C1];
__device__ float g_h1 [(size_t)NN * C1];
__device__ float g_xl2[(size_t)NN * HIDC];
__device__ float g_xr2[(size_t)NN * HIDC];
__device__ int   g_deg   [NN];
__device__ int   g_rowptr[NN];
__device__ int   g_cursor[NN];
__device__ int   g_csrc  [EE];
__device__ int   g_bsums [256];
// bf16 split operands for GEMM1
__device__ __align__(16) __nv_bfloat16 g_Ah[(size_t)NN * INDIM];
__device__ __align__(16) __nv_bfloat16 g_Al[(size_t)NN * INDIM];
__device__ __align__(16) __nv_bfloat16 g_Bh[(size_t)NB * INDIM];
__device__ __align__(16) __nv_bfloat16 g_Bl[(size_t)NB * INDIM];

// ---------------- helpers ---------------------------------------------------
__device__ __forceinline__ float lrelu(float v) { return v > 0.f ? v : NEGSLOPE * v; }
__device__ __forceinline__ float elu(float v)   { return v > 0.f ? v : expm1f(v); }

__device__ __forceinline__ u64 ffma2(u64 a, u64 b, u64 c)
{
    u64 d;
    asm("fma.rn.f32x2 %0, %1, %2, %3;" : "=l"(d) : "l"(a), "l"(b), "l"(c));
    return d;
}
__device__ __forceinline__ u64 pack2(float x, float y)
{
    u64 d;
    asm("mov.b64 %0, {%1, %2};" : "=l"(d) : "f"(x), "f"(y));
    return d;
}
__device__ __forceinline__ float2 unpack2(u64 v)
{
    float2 r;
    asm("mov.b64 {%0, %1}, %2;" : "=f"(r.x), "=f"(r.y) : "l"(v));
    return r;
}
__device__ __forceinline__ uint32_t smem_u32(const void* p)
{
    uint32_t a;
    asm("{ .reg .u64 t; cvta.to.shared.u64 t, %1; cvt.u32.u64 %0, t; }"
        : "=r"(a) : "l"(p));
    return a;
}

// bf16 tensor-core mma (base-target instruction, sm_80+)
#define MMA_BF16(d, a0, a1, a2, a3, b0, b1)                                  \
    asm volatile(                                                            \
        "mma.sync.aligned.m16n8k16.row.col.f32.bf16.bf16.f32 "               \
        "{%0,%1,%2,%3}, {%4,%5,%6,%7}, {%8,%9}, {%0,%1,%2,%3};"              \
        : "+f"((d)[0]), "+f"((d)[1]), "+f"((d)[2]), "+f"((d)[3])             \
        : "r"(a0), "r"(a1), "r"(a2), "r"(a3), "r"(b0), "r"(b1))

// cp.async (sm_80+ base)
#define CP16(dst_u32, src_ptr) \
    asm volatile("cp.async.cg.shared.global [%0], [%1], 16;" \
                 :: "r"(dst_u32), "l"(src_ptr))
#define CP_COMMIT() asm volatile("cp.async.commit_group;" ::: "memory")
#define CP_WAIT(n)  asm volatile("cp.async.wait_group %0;" :: "n"(n) : "memory")

// ---------------- conversion kernels -----------------------------------------
__global__ void conv_x_k(const float* __restrict__ x,
                         __nv_bfloat16* __restrict__ Ah,
                         __nv_bfloat16* __restrict__ Al)
{
    size_t i = (size_t)blockIdx.x * blockDim.x + threadIdx.x;
    if (i >= (size_t)NN * INDIM) return;
    float v = x[i];
    __nv_bfloat16 h = __float2bfloat16(v);
    Ah[i] = h;
    Al[i] = __float2bfloat16(v - __bfloat162float(h));
}

__global__ void conv_w_k(const float* __restrict__ W1l, const float* __restrict__ W1r,
                         __nv_bfloat16* __restrict__ Bh, __nv_bfloat16* __restrict__ Bl)
{
    int i = blockIdx.x * blockDim.x + threadIdx.x;
    if (i >= NB * INDIM) return;
    int n = i >> 8;          // 0..511
    int k = i & 255;
    float v = (n < C1) ? W1l[(size_t)k * C1 + n] : W1r[(size_t)k * C1 + (n - C1)];
    __nv_bfloat16 h = __float2bfloat16(v);
    Bh[i] = h;
    Bl[i] = __float2bfloat16(v - __bfloat162float(h));
}

// ============================================================================
// GEMM1 via mma.sync bf16 3-product split, cp.async double-buffered.
// CTA tile 128(M) x 128(N), K chunk 32, 8 chunks. 8 warps = 2(M) x 4(N),
// warp tile 64x32. smem tiles padded to stride 40 bf16 (conflict-free frags).
// Stage = Ah,Al,Bh,Bl 128x32 tiles = 4 * 128*40*2 B = 40960 B; 2 stages.
// ============================================================================
#define KCH    32
#define PAD2   40
#define T_ELEM (128 * PAD2)          // 5120 bf16 per tile
#define T_BYTE (T_ELEM * 2)          // 10240 bytes
#define STG_BYTE (4 * T_BYTE)        // 40960 bytes
#define SMEM_BYTES (2 * STG_BYTE)    // 81920 bytes

__global__ __launch_bounds__(256)
void gemm1_mma(const __nv_bfloat16* __restrict__ Ah, const __nv_bfloat16* __restrict__ Al,
               const __nv_bfloat16* __restrict__ Bh, const __nv_bfloat16* __restrict__ Bl,
               const float* __restrict__ bl1, const float* __restrict__ br1,
               float* __restrict__ Xl, float* __restrict__ Xr)
{
    extern __shared__ __nv_bfloat16 sm[];
    const uint32_t smb = smem_u32(sm);

    const int tid  = threadIdx.x;
    const int wid  = tid >> 5;
    const int lane = tid & 31;
    const int wm   = wid & 1;        // 0..1  -> 64-row half
    const int wn   = wid >> 1;       // 0..3  -> 32-col quarter
    const int rowBase = blockIdx.y * 128;
    const int colBase = blockIdx.x * 128;

    const int lr = lane >> 2;        // 0..7
    const int lc = (lane & 3) * 2;   // 0,2,4,6

    // per-thread load coords: idx in [0,512) per tile; 2 iterations
    // r = idx>>2 (row 0..127), k8 = (idx&3)*8 (bf16 col 0,8,16,24)
#define LOAD_STAGE(stg, kOff) do {                                            \
    uint32_t sb = smb + (stg) * STG_BYTE;                                     \
    for (int idx = tid; idx < 512; idx += 256) {                              \
        int r  = idx >> 2;                                                    \
        int k8 = (idx & 3) * 8;                                               \
        uint32_t soff = (uint32_t)(r * (PAD2 * 2) + k8 * 2);                  \
        int ga = min(rowBase + r, NN - 1);                                    \
        int gb = colBase + r;                                                 \
        CP16(sb + soff,              Ah + (size_t)ga * INDIM + (kOff) + k8);  \
        CP16(sb + T_BYTE + soff,     Al + (size_t)ga * INDIM + (kOff) + k8);  \
        CP16(sb + 2 * T_BYTE + soff, Bh + (size_t)gb * INDIM + (kOff) + k8);  \
        CP16(sb + 3 * T_BYTE + soff, Bl + (size_t)gb * INDIM + (kOff) + k8);  \
    }                                                                         \
} while (0)

    float acc[4][4][4];
#pragma unroll
    for (int i = 0; i < 4; i++)
#pragma unroll
        for (int j = 0; j < 4; j++)
#pragma unroll
            for (int f = 0; f < 4; f++) acc[i][j][f] = 0.f;

    LOAD_STAGE(0, 0);
    CP_COMMIT();

    for (int kc = 0; kc < 8; kc++) {
        const int stg = kc & 1;
        if (kc + 1 < 8) {
            LOAD_STAGE((kc + 1) & 1, (kc + 1) * KCH);
            CP_COMMIT();
            CP_WAIT(1);
        } else {
            CP_WAIT(0);
        }
        __syncthreads();

        const __nv_bfloat16* sAh = sm + stg * (STG_BYTE / 2);
        const __nv_bfloat16* sAl = sAh + T_ELEM;
        const __nv_bfloat16* sBh = sAh + 2 * T_ELEM;
        const __nv_bfloat16* sBl = sAh + 3 * T_ELEM;

#pragma unroll
        for (int ks = 0; ks < 2; ks++) {
            const int k0 = ks * 16;
            uint32_t bh[4][2], bl_[4][2];
#pragma unroll
            for (int j = 0; j < 4; j++) {
                const __nv_bfloat16* p = sBh + (wn * 32 + j * 8 + lr) * PAD2 + k0 + lc;
                bh[j][0] = *(const uint32_t*)p;
                bh[j][1] = *(const uint32_t*)(p + 8);
                const __nv_bfloat16* q = sBl + (wn * 32 + j * 8 + lr) * PAD2 + k0 + lc;
                bl_[j][0] = *(const uint32_t*)q;
                bl_[j][1] = *(const uint32_t*)(q + 8);
            }
#pragma unroll
            for (int i = 0; i < 4; i++) {
                const __nv_bfloat16* p = sAh + (wm * 64 + i * 16 + lr) * PAD2 + k0 + lc;
                uint32_t ah0 = *(const uint32_t*)p;
                uint32_t ah1 = *(const uint32_t*)(p + 8 * PAD2);
                uint32_t ah2 = *(const uint32_t*)(p + 8);
                uint32_t ah3 = *(const uint32_t*)(p + 8 * PAD2 + 8);
                const __nv_bfloat16* q = sAl + (wm * 64 + i * 16 + lr) * PAD2 + k0 + lc;
                uint32_t al0 = *(const uint32_t*)q;
                uint32_t al1 = *(const uint32_t*)(q + 8 * PAD2);
                uint32_t al2 = *(const uint32_t*)(q + 8);
                uint32_t al3 = *(const uint32_t*)(q + 8 * PAD2 + 8);
#pragma unroll
                for (int j = 0; j < 4; j++) {
                    MMA_BF16(acc[i][j], ah0, ah1, ah2, ah3, bh[j][0], bh[j][1]);
                    MMA_BF16(acc[i][j], ah0, ah1, ah2, ah3, bl_[j][0], bl_[j][1]);
                    MMA_BF16(acc[i][j], al0, al1, al2, al3, bh[j][0], bh[j][1]);
                }
            }
        }
        __syncthreads();
    }

    // ---- epilogue ----
    const bool isL = (colBase < C1);
    float* X = isL ? Xl : Xr;
    const float* bs = isL ? bl1 : br1;
    const int cb = isL ? colBase : colBase - C1;
#pragma unroll
    for (int i = 0; i < 4; i++) {
        int r0 = rowBase + wm * 64 + i * 16 + lr;
#pragma unroll
        for (int j = 0; j < 4; j++) {
            int c = cb + wn * 32 + j * 8 + lc;
            float b0 = bs[c], b1 = bs[c + 1];
            if (r0 < NN) {
                float2 o = make_float2(acc[i][j][0] + b0, acc[i][j][1] + b1);
                *(float2*)(X + (size_t)r0 * C1 + c) = o;
            }
            if (r0 + 8 < NN) {
                float2 o = make_float2(acc[i][j][2] + b0, acc[i][j][3] + b1);
                *(float2*)(X + (size_t)(r0 + 8) * C1 + c) = o;
            }
        }
    }
#undef LOAD_STAGE
}

// ============================================================================
// GEMM2: 128x64 tile, BK=16, double-buffered, 8x4 micro via FFMA2. K=256.
// ============================================================================
__global__ __launch_bounds__(256, 2)
void sgemm128x64_dual(const float* __restrict__ A,
                      const float* __restrict__ Wl, const float* __restrict__ bl,
                      const float* __restrict__ Wr, const float* __restrict__ br,
                      float* __restrict__ Xl, float* __restrict__ Xr)
{
    const int M = NN, K = C1, nc = HIDC;
    __shared__ float As[2][16][128 + 4];
    __shared__ float Bs[2][16][64];

    const int tid = threadIdx.x;
    const int tx = tid & 15;
    const int ty = tid >> 4;
    const int rowBase = blockIdx.x * 128;

    const int ar = tid >> 2;
    const int ac = (tid & 3) * 4;
    const int kr = tid >> 4;
    const int bc = (tid & 15) * 4;

    const int r0 = min(rowBase + ar,      M - 1);
    const int r1 = min(rowBase + ar + 64, M - 1);

    const float* Wsrc0 = (bc < nc) ? (Wl + bc) : (Wr + bc - nc);

    float4 aR0, aR1, bR0;

    aR0 = *reinterpret_cast<const float4*>(&A[(size_t)r0 * K + ac]);
    aR1 = *reinterpret_cast<const float4*>(&A[(size_t)r1 * K + ac]);
    bR0 = *reinterpret_cast<const float4*>(&Wsrc0[(size_t)kr * nc]);

    As[0][ac + 0][ar] = aR0.x; As[0][ac + 1][ar] = aR0.y;
    As[0][ac + 2][ar] = aR0.z; As[0][ac + 3][ar] = aR0.w;
    As[0][ac + 0][ar + 64] = aR1.x; As[0][ac + 1][ar + 64] = aR1.y;
    As[0][ac + 2][ar + 64] = aR1.z; As[0][ac + 3][ar + 64] = aR1.w;
    *reinterpret_cast<float4*>(&Bs[0][kr][bc]) = bR0;
    __syncthreads();

    u64 acc2[4][4];
#pragma unroll
    for (int i = 0; i < 4; i++)
#pragma unroll
        for (int j = 0; j < 4; j++) acc2[i][j] = 0ull;

    int buf = 0;

    for (int k0 = 0; k0 < K; k0 += 16) {
        const bool more = (k0 + 16 < K);
        if (more) {
            int kn = k0 + 16;
            aR0 = *reinterpret_cast<const float4*>(&A[(size_t)r0 * K + kn + ac]);
            aR1 = *reinterpret_cast<const float4*>(&A[(size_t)r1 * K + kn + ac]);
            bR0 = *reinterpret_cast<const float4*>(&Wsrc0[(size_t)(kn + kr) * nc]);
        }

#pragma unroll
        for (int kk = 0; kk < 16; kk++) {
            ulonglong2 aa0 = *reinterpret_cast<const ulonglong2*>(&As[buf][kk][ty * 8]);
            ulonglong2 aa1 = *reinterpret_cast<const ulonglong2*>(&As[buf][kk][ty * 8 + 4]);
            float4 b0 = *reinterpret_cast<const float4*>(&Bs[buf][kk][tx * 4]);
            u64 a2[4] = {aa0.x, aa0.y, aa1.x, aa1.y};
            u64 bb[4];
            bb[0] = pack2(b0.x, b0.x); bb[1] = pack2(b0.y, b0.y);
            bb[2] = pack2(b0.z, b0.z); bb[3] = pack2(b0.w, b0.w);
#pragma unroll
            for (int i = 0; i < 4; i++)
#pragma unroll
                for (int j = 0; j < 4; j++)
                    acc2[i][j] = ffma2(a2[i], bb[j], acc2[i][j]);
        }

        if (more) {
            int nb = buf ^ 1;
            As[nb][ac + 0][ar] = aR0.x; As[nb][ac + 1][ar] = aR0.y;
            As[nb][ac + 2][ar] = aR0.z; As[nb][ac + 3][ar] = aR0.w;
            As[nb][ac + 0][ar + 64] = aR1.x; As[nb][ac + 1][ar + 64] = aR1.y;
            As[nb][ac + 2][ar + 64] = aR1.z; As[nb][ac + 3][ar + 64] = aR1.w;
            *reinterpret_cast<float4*>(&Bs[nb][kr][bc]) = bR0;
        }
        __syncthreads();
        buf ^= 1;
    }

    const int col = tx * 4;
    const bool isL = (col < nc);
    float* X = isL ? Xl : Xr;
    const float* bias = isL ? bl : br;
    const int c = isL ? col : col - nc;
    float4 bv = make_float4(bias[c + 0], bias[c + 1], bias[c + 2], bias[c + 3]);
#pragma unroll
    for (int i = 0; i < 4; i++) {
        float rA[4], rB[4];
#pragma unroll
        for (int j = 0; j < 4; j++) {
            float2 f = unpack2(acc2[i][j]);
            rA[j] = f.x; rB[j] = f.y;
        }
        int rowA = rowBase + ty * 8 + 2 * i;
        int rowB = rowA + 1;
        if (rowA < M) {
            float4 o = make_float4(rA[0] + bv.x, rA[1] + bv.y, rA[2] + bv.z, rA[3] + bv.w);
            *reinterpret_cast<float4*>(&X[(size_t)rowA * nc + c]) = o;
        }
        if (rowB < M) {
            float4 o = make_float4(rB[0] + bv.x, rB[1] + bv.y, rB[2] + bv.z, rB[3] + bv.w);
            *reinterpret_cast<float4*>(&X[(size_t)rowB * nc + c]) = o;
        }
    }
}

// ---------------- CSR construction ------------------------------------------
__global__ void zero_deg_k(int* __restrict__ deg)
{
    int i = blockIdx.x * blockDim.x + threadIdx.x;
    if (i < NN) deg[i] = 0;
}

__global__ void hist_k(const int* __restrict__ ei, int* __restrict__ deg)
{
    int e = blockIdx.x * blockDim.x + threadIdx.x;
    if (e < EE) atomicAdd(&deg[ei[EE + e]], 1);
}

__global__ void scan1_k(const int* __restrict__ deg, int* __restrict__ rowptr,
                        int* __restrict__ bsums)
{
    __shared__ int sh[256];
    int tid = threadIdx.x;
    int i = blockIdx.x * 256 + tid;
    int v = (i < NN) ? deg[i] : 0;
    sh[tid] = v;
    __syncthreads();
#pragma unroll
    for (int off = 1; off < 256; off <<= 1) {
        int t = (tid >= off) ? sh[tid - off] : 0;
        __syncthreads();
        sh[tid] += t;
        __syncthreads();
    }
    if (i < NN) rowptr[i] = sh[tid] - v;
    if (tid == 255) bsums[blockIdx.x] = sh[255];
}

__global__ void scan2_k(int* __restrict__ bsums, int nb)
{
    __shared__ int sh[256];
    int tid = threadIdx.x;
    int v = (tid < nb) ? bsums[tid] : 0;
    sh[tid] = v;
    __syncthreads();
#pragma unroll
    for (int off = 1; off < 256; off <<= 1) {
        int t = (tid >= off) ? sh[tid - off] : 0;
        __syncthreads();
        sh[tid] += t;
        __syncthreads();
    }
    if (tid < nb) bsums[tid] = sh[tid] - v;
}

__global__ void scan3_k(int* __restrict__ rowptr, const int* __restrict__ bsums,
                        int* __restrict__ cursor)
{
    int i = blockIdx.x * blockDim.x + threadIdx.x;
    if (i >= NN) return;
    int r = rowptr[i] + bsums[i >> 8];
    rowptr[i] = r;
    cursor[i] = r;
}

__global__ void scatter_k(const int* __restrict__ ei, int* __restrict__ cursor,
                          int* __restrict__ csrc)
{
    int e = blockIdx.x * blockDim.x + threadIdx.x;
    if (e >= EE) return;
    int d = ei[EE + e];
    int pos = atomicAdd(&cursor[d], 1);
    csrc[pos] = ei[e];
}

// ---------------- fused GATv2 edge phase, layer 1 ---------------------------
__global__ __launch_bounds__(256)
void edge_fused1_k(const int* __restrict__ rowptr, const int* __restrict__ deg,
                   const int* __restrict__ csrc,
                   const float* __restrict__ xl, const float* __restrict__ xr,
                   const float* __restrict__ att, const float* __restrict__ bias,
                   float* __restrict__ h1)
{
    int w = (blockIdx.x * blockDim.x + threadIdx.x) >> 5;
    if (w >= NN) return;
    int lane = threadIdx.x & 31;

    const float4* pb = reinterpret_cast<const float4*>(xr + (size_t)w * C1 + lane * 8);
    float4 b0 = pb[0], b1 = pb[1];
    const float4* pt = reinterpret_cast<const float4*>(att + lane * 8);
    float4 t0 = pt[0], t1 = pt[1];

    float acc[8] = {};
    float den = 0.f;

    int start = rowptr[w];
    int dg    = deg[w];

    int s = (dg > 0) ? csrc[start] : 0;
    const float4* pa = reinterpret_cast<const float4*>(xl + (size_t)s * C1 + lane * 8);
    float4 a0 = pa[0], a1 = pa[1];

    for (int i = 0; i < dg; i++) {
        int snext = (i + 1 < dg) ? csrc[start + i + 1] : s;
        const float4* pn = reinterpret_cast<const float4*>(
            xl + (size_t)snext * C1 + lane * 8);
        float4 n0 = pn[0], n1 = pn[1];

        float p = lrelu(a0.x + b0.x) * t0.x + lrelu(a0.y + b0.y) * t0.y
                + lrelu(a0.z + b0.z) * t0.z + lrelu(a0.w + b0.w) * t0.w
                + lrelu(a1.x + b1.x) * t1.x + lrelu(a1.y + b1.y) * t1.y
                + lrelu(a1.z + b1.z) * t1.z + lrelu(a1.w + b1.w) * t1.w;
        p += __shfl_xor_sync(0xffffffffu, p, 1);
        p += __shfl_xor_sync(0xffffffffu, p, 2);
        float ex = __expf(p);
        den += ex;
        acc[0] += ex * a0.x; acc[1] += ex * a0.y;
        acc[2] += ex * a0.z; acc[3] += ex * a0.w;
        acc[4] += ex * a1.x; acc[5] += ex * a1.y;
        acc[6] += ex * a1.z; acc[7] += ex * a1.w;

        a0 = n0; a1 = n1;
    }

    float inv = 1.f / (den + 1e-16f);
    const float* bi = bias + lane * 8;
    float4 o0, o1;
    o0.x = elu(acc[0] * inv + bi[0]); o0.y = elu(acc[1] * inv + bi[1]);
    o0.z = elu(acc[2] * inv + bi[2]); o0.w = elu(acc[3] * inv + bi[3]);
    o1.x = elu(acc[4] * inv + bi[4]); o1.y = elu(acc[5] * inv + bi[5]);
    o1.z = elu(acc[6] * inv + bi[6]); o1.w = elu(acc[7] * inv + bi[7]);
    float4* out = reinterpret_cast<float4*>(h1 + (size_t)w * C1 + lane * 8);
    out[0] = o0; out[1] = o1;
}

// ---------------- fused edge phase layer 2 + final linear head --------------
__global__ __launch_bounds__(256)
void edge_fused2_head_k(const int* __restrict__ rowptr, const int* __restrict__ deg,
                        const int* __restrict__ csrc,
                        const float* __restrict__ xl, const float* __restrict__ xr,
                        const float* __restrict__ att, const float* __restrict__ bias,
                        const float* __restrict__ Wlin, const float* __restrict__ blin,
                        float* __restrict__ out)
{
    __shared__ float Ws[HIDC][OUTDIM];      // 32x64 = 8 KB
    __shared__ float bs[OUTDIM];

    for (int i = threadIdx.x; i < HIDC * OUTDIM; i += blockDim.x)
        Ws[i >> 6][i & 63] = Wlin[i];
    if (threadIdx.x < OUTDIM) bs[threadIdx.x] = blin[threadIdx.x];
    __syncthreads();

    int w = (blockIdx.x * blockDim.x + threadIdx.x) >> 5;
    int lane = threadIdx.x & 31;
    if (w >= NN) return;

    float b = xr[(size_t)w * HIDC + lane];
    float t = att[lane];

    float acc = 0.f, den = 0.f;
    int start = rowptr[w];
    int dg    = deg[w];

    int s = (dg > 0) ? csrc[start] : 0;
    float a = xl[(size_t)s * HIDC + lane];

    for (int i = 0; i < dg; i++) {
        int snext = (i + 1 < dg) ? csrc[start + i + 1] : s;
        float n = xl[(size_t)snext * HIDC + lane];

        float p = lrelu(a + b) * t;
        p += __shfl_xor_sync(0xffffffffu, p, 16);
        p += __shfl_xor_sync(0xffffffffu, p, 8);
        p += __shfl_xor_sync(0xffffffffu, p, 4);
        p += __shfl_xor_sync(0xffffffffu, p, 2);
        p += __shfl_xor_sync(0xffffffffu, p, 1);
        float ex = __expf(p);
        den += ex;
        acc += ex * a;

        a = n;
    }
    float inv = 1.f / (den + 1e-16f);
    float hval = elu(acc * inv + bias[lane]);   // h2[w][lane]

    float o0 = bs[lane];
    float o1 = bs[lane + 32];
#pragma unroll
    for (int k = 0; k < HIDC; k++) {
        float v = __shfl_sync(0xffffffffu, hval, k);
        o0 = fmaf(v, Ws[k][lane],      o0);
        o1 = fmaf(v, Ws[k][lane + 32], o1);
    }
    out[(size_t)w * OUTDIM + lane]      = o0;
    out[(size_t)w * OUTDIM + lane + 32] = o1;
}

// ---------------- launch ------------------------------------------------------
extern "C" void kernel_launch(void* const* d_in, const int* in_sizes, int n_in,
                              void* d_out, int out_size)
{
    const float* x     = (const float*)d_in[0];
    const int*   ei    = (const int*)d_in[1];
    const float* W1l   = (const float*)d_in[2];
    const float* b1l   = (const float*)d_in[3];
    const float* W1r   = (const float*)d_in[4];
    const float* b1r   = (const float*)d_in[5];
    const float* att1  = (const float*)d_in[6];
    const float* bias1 = (const float*)d_in[7];
    const float* W2l   = (const float*)d_in[8];
    const float* b2l   = (const float*)d_in[9];
    const float* W2r   = (const float*)d_in[10];
    const float* b2r   = (const float*)d_in[11];
    const float* att2  = (const float*)d_in[12];
    const float* bias2 = (const float*)d_in[13];
    const float* Wlin  = (const float*)d_in[14];
    const float* blin  = (const float*)d_in[15];
    float* out = (float*)d_out;

    float *xl1, *xr1, *h1, *xl2, *xr2;
    int *deg, *rowptr, *cursor, *csrc, *bsums;
    __nv_bfloat16 *Ah, *Al, *Bh, *Bl;
    cudaGetSymbolAddress((void**)&xl1, g_xl1);
    cudaGetSymbolAddress((void**)&xr1, g_xr1);
    cudaGetSymbolAddress((void**)&h1,  g_h1);
    cudaGetSymbolAddress((void**)&xl2, g_xl2);
    cudaGetSymbolAddress((void**)&xr2, g_xr2);
    cudaGetSymbolAddress((void**)&deg,    g_deg);
    cudaGetSymbolAddress((void**)&rowptr, g_rowptr);
    cudaGetSymbolAddress((void**)&cursor, g_cursor);
    cudaGetSymbolAddress((void**)&csrc,   g_csrc);
    cudaGetSymbolAddress((void**)&bsums,  g_bsums);
    cudaGetSymbolAddress((void**)&Ah, g_Ah);
    cudaGetSymbolAddress((void**)&Al, g_Al);
    cudaGetSymbolAddress((void**)&Bh, g_Bh);
    cudaGetSymbolAddress((void**)&Bl, g_Bl);

    cudaFuncSetAttribute(gemm1_mma, cudaFuncAttributeMaxDynamicSharedMemorySize,
                         SMEM_BYTES);

    const int TPB = 256;
    const int nScanBlocks = (NN + 255) / 256;       // 196

    conv_x_k<<<(NN * INDIM + TPB - 1) / TPB, TPB>>>(x, Ah, Al);           // 0
    conv_w_k<<<(NB * INDIM + TPB - 1) / TPB, TPB>>>(W1l, W1r, Bh, Bl);    // 1
    zero_deg_k<<<(NN + TPB - 1) / TPB, TPB>>>(deg);                       // 2

    dim3 gg1(4, (NN + 127) / 128);
    gemm1_mma<<<gg1, TPB, SMEM_BYTES>>>(Ah, Al, Bh, Bl,
                                        b1l, b1r, xl1, xr1);              // 3 (profiled)

    hist_k<<<(EE + TPB - 1) / TPB, TPB>>>(ei, deg);                       // 4
    scan1_k<<<nScanBlocks, 256>>>(deg, rowptr, bsums);                    // 5
    scan2_k<<<1, 256>>>(bsums, nScanBlocks);                              // 6
    scan3_k<<<(NN + TPB - 1) / TPB, TPB>>>(rowptr, bsums, cursor);        // 7
    scatter_k<<<(EE + TPB - 1) / TPB, TPB>>>(ei, cursor, csrc);           // 8

    int eblocks = (NN * 32 + TPB - 1) / TPB;
    edge_fused1_k<<<eblocks, TPB>>>(rowptr, deg, csrc, xl1, xr1, att1, bias1, h1); // 9

    sgemm128x64_dual<<<(NN + 127) / 128, TPB>>>(h1, W2l, b2l, W2r, b2r, xl2, xr2); // 10

    edge_fused2_head_k<<<eblocks, TPB>>>(rowptr, deg, csrc, xl2, xr2,
                                         att2, bias2, Wlin, blin, out);   // 11
}

// round 10
// speedup vs baseline: 3.3864x; 1.0047x over previous
#include <cuda_runtime.h>
#include <cuda_bf16.h>
#include <cstdint>

#define NN      50000
#define EE      800000
#define INDIM   256
#define HIDC    32
#define NHEADS  8
#define OUTDIM  64
#define C1      (NHEADS * HIDC)   // 256
#define NB      512               // total output cols of GEMM1 (Wl|Wr)
#define NEGSLOPE 0.2f

typedef unsigned long long u64;

// ---------------- scratch (device globals) ---------------------------------
__device__ float g_xl1[(size_t)NN * C1];
__device__ float g_xr1[(size_t)NN * C1];
__device__ float g_h1 [(size_t)NN * C1];
__device__ float g_xl2[(size_t)NN * HIDC];
__device__ float g_xr2[(size_t)NN * HIDC];
__device__ int   g_deg   [NN];
__device__ int   g_rowptr[NN];
__device__ int   g_cursor[NN];
__device__ int   g_csrc  [EE];
__device__ int   g_bsums [256];
// bf16 split operands for GEMM1
__device__ __align__(16) __nv_bfloat16 g_Ah[(size_t)NN * INDIM];
__device__ __align__(16) __nv_bfloat16 g_Al[(size_t)NN * INDIM];
__device__ __align__(16) __nv_bfloat16 g_Bh[(size_t)NB * INDIM];
__device__ __align__(16) __nv_bfloat16 g_Bl[(size_t)NB * INDIM];

// ---------------- helpers ---------------------------------------------------
__device__ __forceinline__ float lrelu(float v) { return v > 0.f ? v : NEGSLOPE * v; }
__device__ __forceinline__ float elu(float v)   { return v > 0.f ? v : expm1f(v); }

__device__ __forceinline__ u64 ffma2(u64 a, u64 b, u64 c)
{
    u64 d;
    asm("fma.rn.f32x2 %0, %1, %2, %3;" : "=l"(d) : "l"(a), "l"(b), "l"(c));
    return d;
}
__device__ __forceinline__ u64 pack2(float x, float y)
{
    u64 d;
    asm("mov.b64 %0, {%1, %2};" : "=l"(d) : "f"(x), "f"(y));
    return d;
}
__device__ __forceinline__ float2 unpack2(u64 v)
{
    float2 r;
    asm("mov.b64 {%0, %1}, %2;" : "=f"(r.x), "=f"(r.y) : "l"(v));
    return r;
}
__device__ __forceinline__ uint32_t smem_u32(const void* p)
{
    uint32_t a;
    asm("{ .reg .u64 t; cvta.to.shared.u64 t, %1; cvt.u32.u64 %0, t; }"
        : "=r"(a) : "l"(p));
    return a;
}

// bf16 tensor-core mma (base-target instruction, sm_80+)
#define MMA_BF16(d, a0, a1, a2, a3, b0, b1)                                  \
    asm volatile(                                                            \
        "mma.sync.aligned.m16n8k16.row.col.f32.bf16.bf16.f32 "               \
        "{%0,%1,%2,%3}, {%4,%5,%6,%7}, {%8,%9}, {%0,%1,%2,%3};"              \
        : "+f"((d)[0]), "+f"((d)[1]), "+f"((d)[2]), "+f"((d)[3])             \
        : "r"(a0), "r"(a1), "r"(a2), "r"(a3), "r"(b0), "r"(b1))

// cp.async (sm_80+ base)
#define CP16(dst_u32, src_ptr) \
    asm volatile("cp.async.cg.shared.global [%0], [%1], 16;" \
                 :: "r"(dst_u32), "l"(src_ptr))
#define CP_COMMIT() asm volatile("cp.async.commit_group;" ::: "memory")
#define CP_WAIT(n)  asm volatile("cp.async.wait_group %0;" :: "n"(n) : "memory")

// ---------------- conversion kernels -----------------------------------------
__global__ void conv_x_k(const float* __restrict__ x,
                         __nv_bfloat16* __restrict__ Ah,
                         __nv_bfloat16* __restrict__ Al)
{
    size_t i = (size_t)blockIdx.x * blockDim.x + threadIdx.x;
    if (i >= (size_t)NN * INDIM) return;
    float v = x[i];
    __nv_bfloat16 h = __float2bfloat16(v);
    Ah[i] = h;
    Al[i] = __float2bfloat16(v - __bfloat162float(h));
}

__global__ void conv_w_k(const float* __restrict__ W1l, const float* __restrict__ W1r,
                         __nv_bfloat16* __restrict__ Bh, __nv_bfloat16* __restrict__ Bl)
{
    int i = blockIdx.x * blockDim.x + threadIdx.x;
    if (i >= NB * INDIM) return;
    int n = i >> 8;          // 0..511
    int k = i & 255;
    float v = (n < C1) ? W1l[(size_t)k * C1 + n] : W1r[(size_t)k * C1 + (n - C1)];
    __nv_bfloat16 h = __float2bfloat16(v);
    Bh[i] = h;
    Bl[i] = __float2bfloat16(v - __bfloat162float(h));
}

// ============================================================================
// GEMM1 via mma.sync bf16 3-product split, cp.async double-buffered.
// CTA tile 128(M) x 128(N), K chunk 32, 8 chunks. 8 warps = 2(M) x 4(N),
// warp tile 64x32. smem tiles padded to stride 40 bf16 (conflict-free frags).
// MMA issue order: per i, three j-sweeps (acc dependency distance = 4).
// ============================================================================
#define KCH    32
#define PAD2   40
#define T_ELEM (128 * PAD2)          // 5120 bf16 per tile
#define T_BYTE (T_ELEM * 2)          // 10240 bytes
#define STG_BYTE (4 * T_BYTE)        // 40960 bytes
#define SMEM_BYTES (2 * STG_BYTE)    // 81920 bytes

__global__ __launch_bounds__(256)
void gemm1_mma(const __nv_bfloat16* __restrict__ Ah, const __nv_bfloat16* __restrict__ Al,
               const __nv_bfloat16* __restrict__ Bh, const __nv_bfloat16* __restrict__ Bl,
               const float* __restrict__ bl1, const float* __restrict__ br1,
               float* __restrict__ Xl, float* __restrict__ Xr)
{
    extern __shared__ __nv_bfloat16 sm[];
    const uint32_t smb = smem_u32(sm);

    const int tid  = threadIdx.x;
    const int wid  = tid >> 5;
    const int lane = tid & 31;
    const int wm   = wid & 1;        // 0..1  -> 64-row half
    const int wn   = wid >> 1;       // 0..3  -> 32-col quarter
    const int rowBase = blockIdx.y * 128;
    const int colBase = blockIdx.x * 128;

    const int lr = lane >> 2;        // 0..7
    const int lc = (lane & 3) * 2;   // 0,2,4,6

#define LOAD_STAGE(stg, kOff) do {                                            \
    uint32_t sb = smb + (stg) * STG_BYTE;                                     \
    for (int idx = tid; idx < 512; idx += 256) {                              \
        int r  = idx >> 2;                                                    \
        int k8 = (idx & 3) * 8;                                               \
        uint32_t soff = (uint32_t)(r * (PAD2 * 2) + k8 * 2);                  \
        int ga = min(rowBase + r, NN - 1);                                    \
        int gb = colBase + r;                                                 \
        CP16(sb + soff,              Ah + (size_t)ga * INDIM + (kOff) + k8);  \
        CP16(sb + T_BYTE + soff,     Al + (size_t)ga * INDIM + (kOff) + k8);  \
        CP16(sb + 2 * T_BYTE + soff, Bh + (size_t)gb * INDIM + (kOff) + k8);  \
        CP16(sb + 3 * T_BYTE + soff, Bl + (size_t)gb * INDIM + (kOff) + k8);  \
    }                                                                         \
} while (0)

    float acc[4][4][4];
#pragma unroll
    for (int i = 0; i < 4; i++)
#pragma unroll
        for (int j = 0; j < 4; j++)
#pragma unroll
            for (int f = 0; f < 4; f++) acc[i][j][f] = 0.f;

    LOAD_STAGE(0, 0);
    CP_COMMIT();

    for (int kc = 0; kc < 8; kc++) {
        const int stg = kc & 1;
        if (kc + 1 < 8) {
            LOAD_STAGE((kc + 1) & 1, (kc + 1) * KCH);
            CP_COMMIT();
            CP_WAIT(1);
        } else {
            CP_WAIT(0);
        }
        __syncthreads();

        const __nv_bfloat16* sAh = sm + stg * (STG_BYTE / 2);
        const __nv_bfloat16* sAl = sAh + T_ELEM;
        const __nv_bfloat16* sBh = sAh + 2 * T_ELEM;
        const __nv_bfloat16* sBl = sAh + 3 * T_ELEM;

#pragma unroll
        for (int ks = 0; ks < 2; ks++) {
            const int k0 = ks * 16;
            uint32_t bh[4][2], bl_[4][2];
#pragma unroll
            for (int j = 0; j < 4; j++) {
                const __nv_bfloat16* p = sBh + (wn * 32 + j * 8 + lr) * PAD2 + k0 + lc;
                bh[j][0] = *(const uint32_t*)p;
                bh[j][1] = *(const uint32_t*)(p + 8);
                const __nv_bfloat16* q = sBl + (wn * 32 + j * 8 + lr) * PAD2 + k0 + lc;
                bl_[j][0] = *(const uint32_t*)q;
                bl_[j][1] = *(const uint32_t*)(q + 8);
            }
#pragma unroll
            for (int i = 0; i < 4; i++) {
                const __nv_bfloat16* p = sAh + (wm * 64 + i * 16 + lr) * PAD2 + k0 + lc;
                uint32_t ah0 = *(const uint32_t*)p;
                uint32_t ah1 = *(const uint32_t*)(p + 8 * PAD2);
                uint32_t ah2 = *(const uint32_t*)(p + 8);
                uint32_t ah3 = *(const uint32_t*)(p + 8 * PAD2 + 8);
                const __nv_bfloat16* q = sAl + (wm * 64 + i * 16 + lr) * PAD2 + k0 + lc;
                uint32_t al0 = *(const uint32_t*)q;
                uint32_t al1 = *(const uint32_t*)(q + 8 * PAD2);
                uint32_t al2 = *(const uint32_t*)(q + 8);
                uint32_t al3 = *(const uint32_t*)(q + 8 * PAD2 + 8);
                // three separate j-sweeps: same-acc reuse distance = 4 MMAs
#pragma unroll
                for (int j = 0; j < 4; j++)
                    MMA_BF16(acc[i][j], ah0, ah1, ah2, ah3, bh[j][0], bh[j][1]);
#pragma unroll
                for (int j = 0; j < 4; j++)
                    MMA_BF16(acc[i][j], ah0, ah1, ah2, ah3, bl_[j][0], bl_[j][1]);
#pragma unroll
                for (int j = 0; j < 4; j++)
                    MMA_BF16(acc[i][j], al0, al1, al2, al3, bh[j][0], bh[j][1]);
            }
        }
        __syncthreads();
    }

    // ---- epilogue ----
    const bool isL = (colBase < C1);
    float* X = isL ? Xl : Xr;
    const float* bs = isL ? bl1 : br1;
    const int cb = isL ? colBase : colBase - C1;
#pragma unroll
    for (int i = 0; i < 4; i++) {
        int r0 = rowBase + wm * 64 + i * 16 + lr;
#pragma unroll
        for (int j = 0; j < 4; j++) {
            int c = cb + wn * 32 + j * 8 + lc;
            float b0 = bs[c], b1 = bs[c + 1];
            if (r0 < NN) {
                float2 o = make_float2(acc[i][j][0] + b0, acc[i][j][1] + b1);
                *(float2*)(X + (size_t)r0 * C1 + c) = o;
            }
            if (r0 + 8 < NN) {
                float2 o = make_float2(acc[i][j][2] + b0, acc[i][j][3] + b1);
                *(float2*)(X + (size_t)(r0 + 8) * C1 + c) = o;
            }
        }
    }
#undef LOAD_STAGE
}

// ============================================================================
// GEMM2: 128x64 tile, BK=16, double-buffered, 8x4 micro via FFMA2. K=256.
// ============================================================================
__global__ __launch_bounds__(256, 2)
void sgemm128x64_dual(const float* __restrict__ A,
                      const float* __restrict__ Wl, const float* __restrict__ bl,
                      const float* __restrict__ Wr, const float* __restrict__ br,
                      float* __restrict__ Xl, float* __restrict__ Xr)
{
    const int M = NN, K = C1, nc = HIDC;
    __shared__ float As[2][16][128 + 4];
    __shared__ float Bs[2][16][64];

    const int tid = threadIdx.x;
    const int tx = tid & 15;
    const int ty = tid >> 4;
    const int rowBase = blockIdx.x * 128;

    const int ar = tid >> 2;
    const int ac = (tid & 3) * 4;
    const int kr = tid >> 4;
    const int bc = (tid & 15) * 4;

    const int r0 = min(rowBase + ar,      M - 1);
    const int r1 = min(rowBase + ar + 64, M - 1);

    const float* Wsrc0 = (bc < nc) ? (Wl + bc) : (Wr + bc - nc);

    float4 aR0, aR1, bR0;

    aR0 = *reinterpret_cast<const float4*>(&A[(size_t)r0 * K + ac]);
    aR1 = *reinterpret_cast<const float4*>(&A[(size_t)r1 * K + ac]);
    bR0 = *reinterpret_cast<const float4*>(&Wsrc0[(size_t)kr * nc]);

    As[0][ac + 0][ar] = aR0.x; As[0][ac + 1][ar] = aR0.y;
    As[0][ac + 2][ar] = aR0.z; As[0][ac + 3][ar] = aR0.w;
    As[0][ac + 0][ar + 64] = aR1.x; As[0][ac + 1][ar + 64] = aR1.y;
    As[0][ac + 2][ar + 64] = aR1.z; As[0][ac + 3][ar + 64] = aR1.w;
    *reinterpret_cast<float4*>(&Bs[0][kr][bc]) = bR0;
    __syncthreads();

    u64 acc2[4][4];
#pragma unroll
    for (int i = 0; i < 4; i++)
#pragma unroll
        for (int j = 0; j < 4; j++) acc2[i][j] = 0ull;

    int buf = 0;

    for (int k0 = 0; k0 < K; k0 += 16) {
        const bool more = (k0 + 16 < K);
        if (more) {
            int kn = k0 + 16;
            aR0 = *reinterpret_cast<const float4*>(&A[(size_t)r0 * K + kn + ac]);
            aR1 = *reinterpret_cast<const float4*>(&A[(size_t)r1 * K + kn + ac]);
            bR0 = *reinterpret_cast<const float4*>(&Wsrc0[(size_t)(kn + kr) * nc]);
        }

#pragma unroll
        for (int kk = 0; kk < 16; kk++) {
            ulonglong2 aa0 = *reinterpret_cast<const ulonglong2*>(&As[buf][kk][ty * 8]);
            ulonglong2 aa1 = *reinterpret_cast<const ulonglong2*>(&As[buf][kk][ty * 8 + 4]);
            float4 b0 = *reinterpret_cast<const float4*>(&Bs[buf][kk][tx * 4]);
            u64 a2[4] = {aa0.x, aa0.y, aa1.x, aa1.y};
            u64 bb[4];
            bb[0] = pack2(b0.x, b0.x); bb[1] = pack2(b0.y, b0.y);
            bb[2] = pack2(b0.z, b0.z); bb[3] = pack2(b0.w, b0.w);
#pragma unroll
            for (int i = 0; i < 4; i++)
#pragma unroll
                for (int j = 0; j < 4; j++)
                    acc2[i][j] = ffma2(a2[i], bb[j], acc2[i][j]);
        }

        if (more) {
            int nb = buf ^ 1;
            As[nb][ac + 0][ar] = aR0.x; As[nb][ac + 1][ar] = aR0.y;
            As[nb][ac + 2][ar] = aR0.z; As[nb][ac + 3][ar] = aR0.w;
            As[nb][ac + 0][ar + 64] = aR1.x; As[nb][ac + 1][ar + 64] = aR1.y;
            As[nb][ac + 2][ar + 64] = aR1.z; As[nb][ac + 3][ar + 64] = aR1.w;
            *reinterpret_cast<float4*>(&Bs[nb][kr][bc]) = bR0;
        }
        __syncthreads();
        buf ^= 1;
    }

    const int col = tx * 4;
    const bool isL = (col < nc);
    float* X = isL ? Xl : Xr;
    const float* bias = isL ? bl : br;
    const int c = isL ? col : col - nc;
    float4 bv = make_float4(bias[c + 0], bias[c + 1], bias[c + 2], bias[c + 3]);
#pragma unroll
    for (int i = 0; i < 4; i++) {
        float rA[4], rB[4];
#pragma unroll
        for (int j = 0; j < 4; j++) {
            float2 f = unpack2(acc2[i][j]);
            rA[j] = f.x; rB[j] = f.y;
        }
        int rowA = rowBase + ty * 8 + 2 * i;
        int rowB = rowA + 1;
        if (rowA < M) {
            float4 o = make_float4(rA[0] + bv.x, rA[1] + bv.y, rA[2] + bv.z, rA[3] + bv.w);
            *reinterpret_cast<float4*>(&X[(size_t)rowA * nc + c]) = o;
        }
        if (rowB < M) {
            float4 o = make_float4(rB[0] + bv.x, rB[1] + bv.y, rB[2] + bv.z, rB[3] + bv.w);
            *reinterpret_cast<float4*>(&X[(size_t)rowB * nc + c]) = o;
        }
    }
}

// ---------------- CSR construction ------------------------------------------
__global__ void zero_deg_k(int* __restrict__ deg)
{
    int i = blockIdx.x * blockDim.x + threadIdx.x;
    if (i < NN) deg[i] = 0;
}

__global__ void hist_k(const int* __restrict__ ei, int* __restrict__ deg)
{
    int e = blockIdx.x * blockDim.x + threadIdx.x;
    if (e < EE) atomicAdd(&deg[ei[EE + e]], 1);
}

__global__ void scan1_k(const int* __restrict__ deg, int* __restrict__ rowptr,
                        int* __restrict__ bsums)
{
    __shared__ int sh[256];
    int tid = threadIdx.x;
    int i = blockIdx.x * 256 + tid;
    int v = (i < NN) ? deg[i] : 0;
    sh[tid] = v;
    __syncthreads();
#pragma unroll
    for (int off = 1; off < 256; off <<= 1) {
        int t = (tid >= off) ? sh[tid - off] : 0;
        __syncthreads();
        sh[tid] += t;
        __syncthreads();
    }
    if (i < NN) rowptr[i] = sh[tid] - v;
    if (tid == 255) bsums[blockIdx.x] = sh[255];
}

__global__ void scan2_k(int* __restrict__ bsums, int nb)
{
    __shared__ int sh[256];
    int tid = threadIdx.x;
    int v = (tid < nb) ? bsums[tid] : 0;
    sh[tid] = v;
    __syncthreads();
#pragma unroll
    for (int off = 1; off < 256; off <<= 1) {
        int t = (tid >= off) ? sh[tid - off] : 0;
        __syncthreads();
        sh[tid] += t;
        __syncthreads();
    }
    if (tid < nb) bsums[tid] = sh[tid] - v;
}

__global__ void scan3_k(int* __restrict__ rowptr, const int* __restrict__ bsums,
                        int* __restrict__ cursor)
{
    int i = blockIdx.x * blockDim.x + threadIdx.x;
    if (i >= NN) return;
    int r = rowptr[i] + bsums[i >> 8];
    rowptr[i] = r;
    cursor[i] = r;
}

__global__ void scatter_k(const int* __restrict__ ei, int* __restrict__ cursor,
                          int* __restrict__ csrc)
{
    int e = blockIdx.x * blockDim.x + threadIdx.x;
    if (e >= EE) return;
    int d = ei[EE + e];
    int pos = atomicAdd(&cursor[d], 1);
    csrc[pos] = ei[e];
}

// ---------------- fused GATv2 edge phase, layer 1 ---------------------------
__global__ __launch_bounds__(256)
void edge_fused1_k(const int* __restrict__ rowptr, const int* __restrict__ deg,
                   const int* __restrict__ csrc,
                   const float* __restrict__ xl, const float* __restrict__ xr,
                   const float* __restrict__ att, const float* __restrict__ bias,
                   float* __restrict__ h1)
{
    int w = (blockIdx.x * blockDim.x + threadIdx.x) >> 5;
    if (w >= NN) return;
    int lane = threadIdx.x & 31;

    const float4* pb = reinterpret_cast<const float4*>(xr + (size_t)w * C1 + lane * 8);
    float4 b0 = pb[0], b1 = pb[1];
    const float4* pt = reinterpret_cast<const float4*>(att + lane * 8);
    float4 t0 = pt[0], t1 = pt[1];

    float acc[8] = {};
    float den = 0.f;

    int start = rowptr[w];
    int dg    = deg[w];

    int s = (dg > 0) ? csrc[start] : 0;
    const float4* pa = reinterpret_cast<const float4*>(xl + (size_t)s * C1 + lane * 8);
    float4 a0 = pa[0], a1 = pa[1];

    for (int i = 0; i < dg; i++) {
        int snext = (i + 1 < dg) ? csrc[start + i + 1] : s;
        const float4* pn = reinterpret_cast<const float4*>(
            xl + (size_t)snext * C1 + lane * 8);
        float4 n0 = pn[0], n1 = pn[1];

        float p = lrelu(a0.x + b0.x) * t0.x + lrelu(a0.y + b0.y) * t0.y
                + lrelu(a0.z + b0.z) * t0.z + lrelu(a0.w + b0.w) * t0.w
                + lrelu(a1.x + b1.x) * t1.x + lrelu(a1.y + b1.y) * t1.y
                + lrelu(a1.z + b1.z) * t1.z + lrelu(a1.w + b1.w) * t1.w;
        p += __shfl_xor_sync(0xffffffffu, p, 1);
        p += __shfl_xor_sync(0xffffffffu, p, 2);
        float ex = __expf(p);
        den += ex;
        acc[0] += ex * a0.x; acc[1] += ex * a0.y;
        acc[2] += ex * a0.z; acc[3] += ex * a0.w;
        acc[4] += ex * a1.x; acc[5] += ex * a1.y;
        acc[6] += ex * a1.z; acc[7] += ex * a1.w;

        a0 = n0; a1 = n1;
    }

    float inv = 1.f / (den + 1e-16f);
    const float* bi = bias + lane * 8;
    float4 o0, o1;
    o0.x = elu(acc[0] * inv + bi[0]); o0.y = elu(acc[1] * inv + bi[1]);
    o0.z = elu(acc[2] * inv + bi[2]); o0.w = elu(acc[3] * inv + bi[3]);
    o1.x = elu(acc[4] * inv + bi[4]); o1.y = elu(acc[5] * inv + bi[5]);
    o1.z = elu(acc[6] * inv + bi[6]); o1.w = elu(acc[7] * inv + bi[7]);
    float4* out = reinterpret_cast<float4*>(h1 + (size_t)w * C1 + lane * 8);
    out[0] = o0; out[1] = o1;
}

// ---------------- fused edge phase layer 2 + final linear head --------------
__global__ __launch_bounds__(256)
void edge_fused2_head_k(const int* __restrict__ rowptr, const int* __restrict__ deg,
                        const int* __restrict__ csrc,
                        const float* __restrict__ xl, const float* __restrict__ xr,
                        const float* __restrict__ att, const float* __restrict__ bias,
                        const float* __restrict__ Wlin, const float* __restrict__ blin,
                        float* __restrict__ out)
{
    __shared__ float Ws[HIDC][OUTDIM];      // 32x64 = 8 KB
    __shared__ float bs[OUTDIM];

    for (int i = threadIdx.x; i < HIDC * OUTDIM; i += blockDim.x)
        Ws[i >> 6][i & 63] = Wlin[i];
    if (threadIdx.x < OUTDIM) bs[threadIdx.x] = blin[threadIdx.x];
    __syncthreads();

    int w = (blockIdx.x * blockDim.x + threadIdx.x) >> 5;
    int lane = threadIdx.x & 31;
    if (w >= NN) return;

    float b = xr[(size_t)w * HIDC + lane];
    float t = att[lane];

    float acc = 0.f, den = 0.f;
    int start = rowptr[w];
    int dg    = deg[w];

    int s = (dg > 0) ? csrc[start] : 0;
    float a = xl[(size_t)s * HIDC + lane];

    for (int i = 0; i < dg; i++) {
        int snext = (i + 1 < dg) ? csrc[start + i + 1] : s;
        float n = xl[(size_t)snext * HIDC + lane];

        float p = lrelu(a + b) * t;
        p += __shfl_xor_sync(0xffffffffu, p, 16);
        p += __shfl_xor_sync(0xffffffffu, p, 8);
        p += __shfl_xor_sync(0xffffffffu, p, 4);
        p += __shfl_xor_sync(0xffffffffu, p, 2);
        p += __shfl_xor_sync(0xffffffffu, p, 1);
        float ex = __expf(p);
        den += ex;
        acc += ex * a;

        a = n;
    }
    float inv = 1.f / (den + 1e-16f);
    float hval = elu(acc * inv + bias[lane]);   // h2[w][lane]

    float o0 = bs[lane];
    float o1 = bs[lane + 32];
#pragma unroll
    for (int k = 0; k < HIDC; k++) {
        float v = __shfl_sync(0xffffffffu, hval, k);
        o0 = fmaf(v, Ws[k][lane],      o0);
        o1 = fmaf(v, Ws[k][lane + 32], o1);
    }
    out[(size_t)w * OUTDIM + lane]      = o0;
    out[(size_t)w * OUTDIM + lane + 32] = o1;
}

// ---------------- launch ------------------------------------------------------
extern "C" void kernel_launch(void* const* d_in, const int* in_sizes, int n_in,
                              void* d_out, int out_size)
{
    const float* x     = (const float*)d_in[0];
    const int*   ei    = (const int*)d_in[1];
    const float* W1l   = (const float*)d_in[2];
    const float* b1l   = (const float*)d_in[3];
    const float* W1r   = (const float*)d_in[4];
    const float* b1r   = (const float*)d_in[5];
    const float* att1  = (const float*)d_in[6];
    const float* bias1 = (const float*)d_in[7];
    const float* W2l   = (const float*)d_in[8];
    const float* b2l   = (const float*)d_in[9];
    const float* W2r   = (const float*)d_in[10];
    const float* b2r   = (const float*)d_in[11];
    const float* att2  = (const float*)d_in[12];
    const float* bias2 = (const float*)d_in[13];
    const float* Wlin  = (const float*)d_in[14];
    const float* blin  = (const float*)d_in[15];
    float* out = (float*)d_out;

    float *xl1, *xr1, *h1, *xl2, *xr2;
    int *deg, *rowptr, *cursor, *csrc, *bsums;
    __nv_bfloat16 *Ah, *Al, *Bh, *Bl;
    cudaGetSymbolAddress((void**)&xl1, g_xl1);
    cudaGetSymbolAddress((void**)&xr1, g_xr1);
    cudaGetSymbolAddress((void**)&h1,  g_h1);
    cudaGetSymbolAddress((void**)&xl2, g_xl2);
    cudaGetSymbolAddress((void**)&xr2, g_xr2);
    cudaGetSymbolAddress((void**)&deg,    g_deg);
    cudaGetSymbolAddress((void**)&rowptr, g_rowptr);
    cudaGetSymbolAddress((void**)&cursor, g_cursor);
    cudaGetSymbolAddress((void**)&csrc,   g_csrc);
    cudaGetSymbolAddress((void**)&bsums,  g_bsums);
    cudaGetSymbolAddress((void**)&Ah, g_Ah);
    cudaGetSymbolAddress((void**)&Al, g_Al);
    cudaGetSymbolAddress((void**)&Bh, g_Bh);
    cudaGetSymbolAddress((void**)&Bl, g_Bl);

    cudaFuncSetAttribute(gemm1_mma, cudaFuncAttributeMaxDynamicSharedMemorySize,
                         SMEM_BYTES);

    const int TPB = 256;
    const int nScanBlocks = (NN + 255) / 256;       // 196

    conv_x_k<<<(NN * INDIM + TPB - 1) / TPB, TPB>>>(x, Ah, Al);           // 0
    conv_w_k<<<(NB * INDIM + TPB - 1) / TPB, TPB>>>(W1l, W1r, Bh, Bl);    // 1
    zero_deg_k<<<(NN + TPB - 1) / TPB, TPB>>>(deg);                       // 2

    dim3 gg1(4, (NN + 127) / 128);
    gemm1_mma<<<gg1, TPB, SMEM_BYTES>>>(Ah, Al, Bh, Bl,
                                        b1l, b1r, xl1, xr1);              // 3 (profiled)

    hist_k<<<(EE + TPB - 1) / TPB, TPB>>>(ei, deg);                       // 4
    scan1_k<<<nScanBlocks, 256>>>(deg, rowptr, bsums);                    // 5
    scan2_k<<<1, 256>>>(bsums, nScanBlocks);                              // 6
    scan3_k<<<(NN + TPB - 1) / TPB, TPB>>>(rowptr, bsums, cursor);        // 7
    scatter_k<<<(EE + TPB - 1) / TPB, TPB>>>(ei, cursor, csrc);           // 8

    int eblocks = (NN * 32 + TPB - 1) / TPB;
    edge_fused1_k<<<eblocks, TPB>>>(rowptr, deg, csrc, xl1, xr1, att1, bias1, h1); // 9

    sgemm128x64_dual<<<(NN + 127) / 128, TPB>>>(h1, W2l, b2l, W2r, b2r, xl2, xr2); // 10

    edge_fused2_head_k<<<eblocks, TPB>>>(rowptr, deg, csrc, xl2, xr2,
                                         att2, bias2, Wlin, blin, out);   // 11
}

// round 11
// speedup vs baseline: 3.5353x; 1.0440x over previous
#include <cuda_runtime.h>
#include <cuda_bf16.h>
#include <cstdint>

#define NN      50000
#define EE      800000
#define INDIM   256
#define HIDC    32
#define NHEADS  8
#define OUTDIM  64
#define C1      (NHEADS * HIDC)   // 256
#define NB      512               // total output cols of GEMM1 (Wl|Wr)
#define NB2     64                // total output cols of GEMM2 (W2l|W2r)
#define NEGSLOPE 0.2f

typedef unsigned long long u64;

// ---------------- scratch (device globals) ---------------------------------
__device__ float g_xl1[(size_t)NN * C1];
__device__ float g_xr1[(size_t)NN * C1];
__device__ float g_xl2[(size_t)NN * HIDC];
__device__ float g_xr2[(size_t)NN * HIDC];
__device__ int   g_deg   [NN];
__device__ int   g_rowptr[NN];
__device__ int   g_cursor[NN];
__device__ int   g_csrc  [EE];
__device__ int   g_bsums [256];
// bf16 split operands
__device__ __align__(16) __nv_bfloat16 g_Ah[(size_t)NN * INDIM];
__device__ __align__(16) __nv_bfloat16 g_Al[(size_t)NN * INDIM];
__device__ __align__(16) __nv_bfloat16 g_Bh[(size_t)NB * INDIM];
__device__ __align__(16) __nv_bfloat16 g_Bl[(size_t)NB * INDIM];
__device__ __align__(16) __nv_bfloat16 g_H1h[(size_t)NN * C1];   // h1 hi
__device__ __align__(16) __nv_bfloat16 g_H1l[(size_t)NN * C1];   // h1 lo
__device__ __align__(16) __nv_bfloat16 g_B2h[(size_t)NB2 * C1];
__device__ __align__(16) __nv_bfloat16 g_B2l[(size_t)NB2 * C1];

// ---------------- helpers ---------------------------------------------------
__device__ __forceinline__ float lrelu(float v) { return v > 0.f ? v : NEGSLOPE * v; }
__device__ __forceinline__ float elu(float v)   { return v > 0.f ? v : expm1f(v); }

__device__ __forceinline__ uint32_t smem_u32(const void* p)
{
    uint32_t a;
    asm("{ .reg .u64 t; cvta.to.shared.u64 t, %1; cvt.u32.u64 %0, t; }"
        : "=r"(a) : "l"(p));
    return a;
}

// bf16 tensor-core mma (sm_80+ base)
#define MMA_BF16(d, a0, a1, a2, a3, b0, b1)                                  \
    asm volatile(                                                            \
        "mma.sync.aligned.m16n8k16.row.col.f32.bf16.bf16.f32 "               \
        "{%0,%1,%2,%3}, {%4,%5,%6,%7}, {%8,%9}, {%0,%1,%2,%3};"              \
        : "+f"((d)[0]), "+f"((d)[1]), "+f"((d)[2]), "+f"((d)[3])             \
        : "r"(a0), "r"(a1), "r"(a2), "r"(a3), "r"(b0), "r"(b1))

// ldmatrix (sm_75+ base)
#define LDSM_X4(r0, r1, r2, r3, addr)                                        \
    asm volatile("ldmatrix.sync.aligned.m8n8.x4.shared.b16 {%0,%1,%2,%3}, [%4];" \
                 : "=r"(r0), "=r"(r1), "=r"(r2), "=r"(r3) : "r"(addr))

// cp.async (sm_80+ base)
#define CP16(dst_u32, src_ptr) \
    asm volatile("cp.async.cg.shared.global [%0], [%1], 16;" \
                 :: "r"(dst_u32), "l"(src_ptr))
#define CP_COMMIT() asm volatile("cp.async.commit_group;" ::: "memory")
#define CP_WAIT(n)  asm volatile("cp.async.wait_group %0;" :: "n"(n) : "memory")

// ---------------- conversion kernels -----------------------------------------
__global__ void conv_x_k(const float* __restrict__ x,
                         __nv_bfloat16* __restrict__ Ah,
                         __nv_bfloat16* __restrict__ Al)
{
    size_t i = (size_t)blockIdx.x * blockDim.x + threadIdx.x;
    if (i >= (size_t)NN * INDIM) return;
    float v = x[i];
    __nv_bfloat16 h = __float2bfloat16(v);
    Ah[i] = h;
    Al[i] = __float2bfloat16(v - __bfloat162float(h));
}

__global__ void conv_w_k(const float* __restrict__ W1l, const float* __restrict__ W1r,
                         __nv_bfloat16* __restrict__ Bh, __nv_bfloat16* __restrict__ Bl)
{
    int i = blockIdx.x * blockDim.x + threadIdx.x;
    if (i >= NB * INDIM) return;
    int n = i >> 8;
    int k = i & 255;
    float v = (n < C1) ? W1l[(size_t)k * C1 + n] : W1r[(size_t)k * C1 + (n - C1)];
    __nv_bfloat16 h = __float2bfloat16(v);
    Bh[i] = h;
    Bl[i] = __float2bfloat16(v - __bfloat162float(h));
}

__global__ void conv_w2_k(const float* __restrict__ W2l, const float* __restrict__ W2r,
                          __nv_bfloat16* __restrict__ B2h, __nv_bfloat16* __restrict__ B2l)
{
    int i = blockIdx.x * blockDim.x + threadIdx.x;
    if (i >= NB2 * C1) return;
    int n = i >> 8;          // 0..63
    int k = i & 255;
    float v = (n < HIDC) ? W2l[(size_t)k * HIDC + n]
                         : W2r[(size_t)k * HIDC + (n - HIDC)];
    __nv_bfloat16 h = __float2bfloat16(v);
    B2h[i] = h;
    B2l[i] = __float2bfloat16(v - __bfloat162float(h));
}

// ============================================================================
// GEMM1 via mma.sync bf16 3-product split, cp.async double-buffered, ldmatrix.
// CTA 128(M) x 128(N), K chunk 32. 8 warps = 2(M) x 4(N), warp tile 64x32.
// smem rows padded to 40 bf16 (conflict-free for both cp.async and ldmatrix).
// ============================================================================
#define KCH    32
#define PAD2   40
#define T_ELEM (128 * PAD2)
#define T_BYTE (T_ELEM * 2)          // 10240
#define STG_BYTE (4 * T_BYTE)        // 40960
#define SMEM_BYTES (2 * STG_BYTE)    // 81920

__global__ __launch_bounds__(256)
void gemm1_mma(const __nv_bfloat16* __restrict__ Ah, const __nv_bfloat16* __restrict__ Al,
               const __nv_bfloat16* __restrict__ Bh, const __nv_bfloat16* __restrict__ Bl,
               const float* __restrict__ bl1, const float* __restrict__ br1,
               float* __restrict__ Xl, float* __restrict__ Xr)
{
    extern __shared__ __nv_bfloat16 sm[];
    const uint32_t smb = smem_u32(sm);

    const int tid  = threadIdx.x;
    const int wid  = tid >> 5;
    const int lane = tid & 31;
    const int wm   = wid & 1;
    const int wn   = wid >> 1;
    const int rowBase = blockIdx.y * 128;
    const int colBase = blockIdx.x * 128;

    const int lr = lane >> 2;
    const int lc = (lane & 3) * 2;

    // ldmatrix lane-derived offsets
    const int aRowOff = lane & 15;              // + wm*64 + i*16
    const int aKOff   = (lane >> 4) * 8;        // + k0
    const int bGrp    = lane >> 3;
    const int bRowOff = (lane & 7) + (bGrp >> 1) * 8;  // + wn*32 + jp*8
    const int bKOff   = (bGrp & 1) * 8;         // + k0

#define LOAD_STAGE(stg, kOff) do {                                            \
    uint32_t sb = smb + (stg) * STG_BYTE;                                     \
    for (int idx = tid; idx < 512; idx += 256) {                              \
        int r  = idx >> 2;                                                    \
        int k8 = (idx & 3) * 8;                                               \
        uint32_t soff = (uint32_t)(r * (PAD2 * 2) + k8 * 2);                  \
        int ga = min(rowBase + r, NN - 1);                                    \
        int gb = colBase + r;                                                 \
        CP16(sb + soff,              Ah + (size_t)ga * INDIM + (kOff) + k8);  \
        CP16(sb + T_BYTE + soff,     Al + (size_t)ga * INDIM + (kOff) + k8);  \
        CP16(sb + 2 * T_BYTE + soff, Bh + (size_t)gb * INDIM + (kOff) + k8);  \
        CP16(sb + 3 * T_BYTE + soff, Bl + (size_t)gb * INDIM + (kOff) + k8);  \
    }                                                                         \
} while (0)

    float acc[4][4][4];
#pragma unroll
    for (int i = 0; i < 4; i++)
#pragma unroll
        for (int j = 0; j < 4; j++)
#pragma unroll
            for (int f = 0; f < 4; f++) acc[i][j][f] = 0.f;

    LOAD_STAGE(0, 0);
    CP_COMMIT();

    for (int kc = 0; kc < 8; kc++) {
        const int stg = kc & 1;
        if (kc + 1 < 8) {
            LOAD_STAGE((kc + 1) & 1, (kc + 1) * KCH);
            CP_COMMIT();
            CP_WAIT(1);
        } else {
            CP_WAIT(0);
        }
        __syncthreads();

        const uint32_t sAh_u = smb + stg * STG_BYTE;
        const uint32_t sAl_u = sAh_u + T_BYTE;
        const uint32_t sBh_u = sAh_u + 2 * T_BYTE;
        const uint32_t sBl_u = sAh_u + 3 * T_BYTE;

#pragma unroll
        for (int ks = 0; ks < 2; ks++) {
            const int k0 = ks * 16;
            // B fragments: 2 x4 per (h,l), tile order [jp,k0][jp,k8][jp+1,k0][jp+1,k8]
            uint32_t bh[4][2], bl_[4][2];
#pragma unroll
            for (int jp = 0; jp < 4; jp += 2) {
                uint32_t baddr = (uint32_t)(((wn * 32 + jp * 8 + bRowOff) * PAD2
                                            + k0 + bKOff) * 2);
                LDSM_X4(bh[jp][0], bh[jp][1], bh[jp + 1][0], bh[jp + 1][1],
                        sBh_u + baddr);
                LDSM_X4(bl_[jp][0], bl_[jp][1], bl_[jp + 1][0], bl_[jp + 1][1],
                        sBl_u + baddr);
            }
#pragma unroll
            for (int i = 0; i < 4; i++) {
                uint32_t aaddr = (uint32_t)(((wm * 64 + i * 16 + aRowOff) * PAD2
                                            + k0 + aKOff) * 2);
                uint32_t ah0, ah1, ah2, ah3, al0, al1, al2, al3;
                LDSM_X4(ah0, ah1, ah2, ah3, sAh_u + aaddr);
                LDSM_X4(al0, al1, al2, al3, sAl_u + aaddr);
#pragma unroll
                for (int j = 0; j < 4; j++)
                    MMA_BF16(acc[i][j], ah0, ah1, ah2, ah3, bh[j][0], bh[j][1]);
#pragma unroll
                for (int j = 0; j < 4; j++)
                    MMA_BF16(acc[i][j], ah0, ah1, ah2, ah3, bl_[j][0], bl_[j][1]);
#pragma unroll
                for (int j = 0; j < 4; j++)
                    MMA_BF16(acc[i][j], al0, al1, al2, al3, bh[j][0], bh[j][1]);
            }
        }
        __syncthreads();
    }

    // ---- epilogue ----
    const bool isL = (colBase < C1);
    float* X = isL ? Xl : Xr;
    const float* bs = isL ? bl1 : br1;
    const int cb = isL ? colBase : colBase - C1;
#pragma unroll
    for (int i = 0; i < 4; i++) {
        int r0 = rowBase + wm * 64 + i * 16 + lr;
#pragma unroll
        for (int j = 0; j < 4; j++) {
            int c = cb + wn * 32 + j * 8 + lc;
            float b0 = bs[c], b1 = bs[c + 1];
            if (r0 < NN) {
                float2 o = make_float2(acc[i][j][0] + b0, acc[i][j][1] + b1);
                *(float2*)(X + (size_t)r0 * C1 + c) = o;
            }
            if (r0 + 8 < NN) {
                float2 o = make_float2(acc[i][j][2] + b0, acc[i][j][3] + b1);
                *(float2*)(X + (size_t)(r0 + 8) * C1 + c) = o;
            }
        }
    }
#undef LOAD_STAGE
}

// ============================================================================
// GEMM2 via mma.sync bf16 3-product split. CTA 128(M) x 64(N), K=256 chunk 32.
// 8 warps = 2(M) x 4(N), warp tile 64x16 (j loop = 2).
// Outputs split into Xl (cols 0-31) / Xr (cols 32-63), +bias.
// ============================================================================
#define B2_ROWS  64
#define B2_ELEM  (B2_ROWS * PAD2)     // 2560
#define B2_BYTE  (B2_ELEM * 2)        // 5120
#define STG2_BYTE (2 * T_BYTE + 2 * B2_BYTE)   // 30720
#define SMEM2_BYTES (2 * STG2_BYTE)            // 61440

__global__ __launch_bounds__(256)
void gemm2_mma(const __nv_bfloat16* __restrict__ Ah, const __nv_bfloat16* __restrict__ Al,
               const __nv_bfloat16* __restrict__ Bh, const __nv_bfloat16* __restrict__ Bl,
               const float* __restrict__ bl2, const float* __restrict__ br2,
               float* __restrict__ Xl, float* __restrict__ Xr)
{
    extern __shared__ __nv_bfloat16 sm[];
    const uint32_t smb = smem_u32(sm);

    const int tid  = threadIdx.x;
    const int wid  = tid >> 5;
    const int lane = tid & 31;
    const int wm   = wid & 1;
    const int wn   = wid >> 1;       // 0..3 -> 16-col slice
    const int rowBase = blockIdx.x * 128;

    const int lr = lane >> 2;
    const int lc = (lane & 3) * 2;

    const int aRowOff = lane & 15;
    const int aKOff   = (lane >> 4) * 8;
    const int bGrp    = lane >> 3;
    const int bRowOff = (lane & 7) + (bGrp >> 1) * 8;   // + wn*16
    const int bKOff   = (bGrp & 1) * 8;

#define LOAD_STAGE2(stg, kOff) do {                                           \
    uint32_t sb = smb + (stg) * STG2_BYTE;                                    \
    for (int idx = tid; idx < 512; idx += 256) {                              \
        int r  = idx >> 2;                                                    \
        int k8 = (idx & 3) * 8;                                               \
        uint32_t soff = (uint32_t)(r * (PAD2 * 2) + k8 * 2);                  \
        int ga = min(rowBase + r, NN - 1);                                    \
        CP16(sb + soff,          Ah + (size_t)ga * C1 + (kOff) + k8);         \
        CP16(sb + T_BYTE + soff, Al + (size_t)ga * C1 + (kOff) + k8);         \
    }                                                                         \
    {                                                                         \
        int r  = tid >> 2;       /* 0..63 */                                  \
        int k8 = (tid & 3) * 8;                                               \
        uint32_t soff = (uint32_t)(r * (PAD2 * 2) + k8 * 2);                  \
        CP16(sb + 2 * T_BYTE + soff,           Bh + (size_t)r * C1 + (kOff) + k8); \
        CP16(sb + 2 * T_BYTE + B2_BYTE + soff, Bl + (size_t)r * C1 + (kOff) + k8); \
    }                                                                         \
} while (0)

    float acc[4][2][4];
#pragma unroll
    for (int i = 0; i < 4; i++)
#pragma unroll
        for (int j = 0; j < 2; j++)
#pragma unroll
            for (int f = 0; f < 4; f++) acc[i][j][f] = 0.f;

    LOAD_STAGE2(0, 0);
    CP_COMMIT();

    for (int kc = 0; kc < 8; kc++) {
        const int stg = kc & 1;
        if (kc + 1 < 8) {
            LOAD_STAGE2((kc + 1) & 1, (kc + 1) * KCH);
            CP_COMMIT();
            CP_WAIT(1);
        } else {
            CP_WAIT(0);
        }
        __syncthreads();

        const uint32_t sAh_u = smb + stg * STG2_BYTE;
        const uint32_t sAl_u = sAh_u + T_BYTE;
        const uint32_t sBh_u = sAh_u + 2 * T_BYTE;
        const uint32_t sBl_u = sBh_u + B2_BYTE;

#pragma unroll
        for (int ks = 0; ks < 2; ks++) {
            const int k0 = ks * 16;
            uint32_t bh[2][2], bl_[2][2];
            {
                uint32_t baddr = (uint32_t)(((wn * 16 + bRowOff) * PAD2
                                            + k0 + bKOff) * 2);
                LDSM_X4(bh[0][0], bh[0][1], bh[1][0], bh[1][1], sBh_u + baddr);
                LDSM_X4(bl_[0][0], bl_[0][1], bl_[1][0], bl_[1][1], sBl_u + baddr);
            }
#pragma unroll
            for (int i = 0; i < 4; i++) {
                uint32_t aaddr = (uint32_t)(((wm * 64 + i * 16 + aRowOff) * PAD2
                                            + k0 + aKOff) * 2);
                uint32_t ah0, ah1, ah2, ah3, al0, al1, al2, al3;
                LDSM_X4(ah0, ah1, ah2, ah3, sAh_u + aaddr);
                LDSM_X4(al0, al1, al2, al3, sAl_u + aaddr);
#pragma unroll
                for (int j = 0; j < 2; j++)
                    MMA_BF16(acc[i][j], ah0, ah1, ah2, ah3, bh[j][0], bh[j][1]);
#pragma unroll
                for (int j = 0; j < 2; j++)
                    MMA_BF16(acc[i][j], ah0, ah1, ah2, ah3, bl_[j][0], bl_[j][1]);
#pragma unroll
                for (int j = 0; j < 2; j++)
                    MMA_BF16(acc[i][j], al0, al1, al2, al3, bh[j][0], bh[j][1]);
            }
        }
        __syncthreads();
    }

    // ---- epilogue: warp cols wn*16 + j*8 + lc (each warp entirely Xl or Xr) ----
    const bool isL = (wn < 2);
    float* X = isL ? Xl : Xr;
    const float* bs = isL ? bl2 : br2;
    const int cb = isL ? wn * 16 : wn * 16 - HIDC;
#pragma unroll
    for (int i = 0; i < 4; i++) {
        int r0 = rowBase + wm * 64 + i * 16 + lr;
#pragma unroll
        for (int j = 0; j < 2; j++) {
            int c = cb + j * 8 + lc;
            float b0 = bs[c], b1 = bs[c + 1];
            if (r0 < NN) {
                float2 o = make_float2(acc[i][j][0] + b0, acc[i][j][1] + b1);
                *(float2*)(X + (size_t)r0 * HIDC + c) = o;
            }
            if (r0 + 8 < NN) {
                float2 o = make_float2(acc[i][j][2] + b0, acc[i][j][3] + b1);
                *(float2*)(X + (size_t)(r0 + 8) * HIDC + c) = o;
            }
        }
    }
#undef LOAD_STAGE2
}

// ---------------- CSR construction ------------------------------------------
__global__ void zero_deg_k(int* __restrict__ deg)
{
    int i = blockIdx.x * blockDim.x + threadIdx.x;
    if (i < NN) deg[i] = 0;
}

__global__ void hist_k(const int* __restrict__ ei, int* __restrict__ deg)
{
    int e = blockIdx.x * blockDim.x + threadIdx.x;
    if (e < EE) atomicAdd(&deg[ei[EE + e]], 1);
}

__global__ void scan1_k(const int* __restrict__ deg, int* __restrict__ rowptr,
                        int* __restrict__ bsums)
{
    __shared__ int sh[256];
    int tid = threadIdx.x;
    int i = blockIdx.x * 256 + tid;
    int v = (i < NN) ? deg[i] : 0;
    sh[tid] = v;
    __syncthreads();
#pragma unroll
    for (int off = 1; off < 256; off <<= 1) {
        int t = (tid >= off) ? sh[tid - off] : 0;
        __syncthreads();
        sh[tid] += t;
        __syncthreads();
    }
    if (i < NN) rowptr[i] = sh[tid] - v;
    if (tid == 255) bsums[blockIdx.x] = sh[255];
}

__global__ void scan2_k(int* __restrict__ bsums, int nb)
{
    __shared__ int sh[256];
    int tid = threadIdx.x;
    int v = (tid < nb) ? bsums[tid] : 0;
    sh[tid] = v;
    __syncthreads();
#pragma unroll
    for (int off = 1; off < 256; off <<= 1) {
        int t = (tid >= off) ? sh[tid - off] : 0;
        __syncthreads();
        sh[tid] += t;
        __syncthreads();
    }
    if (tid < nb) bsums[tid] = sh[tid] - v;
}

__global__ void scan3_k(int* __restrict__ rowptr, const int* __restrict__ bsums,
                        int* __restrict__ cursor)
{
    int i = blockIdx.x * blockDim.x + threadIdx.x;
    if (i >= NN) return;
    int r = rowptr[i] + bsums[i >> 8];
    rowptr[i] = r;
    cursor[i] = r;
}

__global__ void scatter_k(const int* __restrict__ ei, int* __restrict__ cursor,
                          int* __restrict__ csrc)
{
    int e = blockIdx.x * blockDim.x + threadIdx.x;
    if (e >= EE) return;
    int d = ei[EE + e];
    int pos = atomicAdd(&cursor[d], 1);
    csrc[pos] = ei[e];
}

// ---------------- fused GATv2 edge phase, layer 1 ---------------------------
// outputs h1 directly as bf16 hi/lo split (consumed by gemm2_mma)
__global__ __launch_bounds__(256)
void edge_fused1_k(const int* __restrict__ rowptr, const int* __restrict__ deg,
                   const int* __restrict__ csrc,
                   const float* __restrict__ xl, const float* __restrict__ xr,
                   const float* __restrict__ att, const float* __restrict__ bias,
                   __nv_bfloat16* __restrict__ h1h, __nv_bfloat16* __restrict__ h1l)
{
    int w = (blockIdx.x * blockDim.x + threadIdx.x) >> 5;
    if (w >= NN) return;
    int lane = threadIdx.x & 31;

    const float4* pb = reinterpret_cast<const float4*>(xr + (size_t)w * C1 + lane * 8);
    float4 b0 = pb[0], b1 = pb[1];
    const float4* pt = reinterpret_cast<const float4*>(att + lane * 8);
    float4 t0 = pt[0], t1 = pt[1];

    float acc[8] = {};
    float den = 0.f;

    int start = rowptr[w];
    int dg    = deg[w];

    int s = (dg > 0) ? csrc[start] : 0;
    const float4* pa = reinterpret_cast<const float4*>(xl + (size_t)s * C1 + lane * 8);
    float4 a0 = pa[0], a1 = pa[1];

    for (int i = 0; i < dg; i++) {
        int snext = (i + 1 < dg) ? csrc[start + i + 1] : s;
        const float4* pn = reinterpret_cast<const float4*>(
            xl + (size_t)snext * C1 + lane * 8);
        float4 n0 = pn[0], n1 = pn[1];

        float p = lrelu(a0.x + b0.x) * t0.x + lrelu(a0.y + b0.y) * t0.y
                + lrelu(a0.z + b0.z) * t0.z + lrelu(a0.w + b0.w) * t0.w
                + lrelu(a1.x + b1.x) * t1.x + lrelu(a1.y + b1.y) * t1.y
                + lrelu(a1.z + b1.z) * t1.z + lrelu(a1.w + b1.w) * t1.w;
        p += __shfl_xor_sync(0xffffffffu, p, 1);
        p += __shfl_xor_sync(0xffffffffu, p, 2);
        float ex = __expf(p);
        den += ex;
        acc[0] += ex * a0.x; acc[1] += ex * a0.y;
        acc[2] += ex * a0.z; acc[3] += ex * a0.w;
        acc[4] += ex * a1.x; acc[5] += ex * a1.y;
        acc[6] += ex * a1.z; acc[7] += ex * a1.w;

        a0 = n0; a1 = n1;
    }

    float inv = 1.f / (den + 1e-16f);
    const float* bi = bias + lane * 8;
    __nv_bfloat16 hh[8], ll[8];
#pragma unroll
    for (int j = 0; j < 8; j++) {
        float v = elu(acc[j] * inv + bi[j]);
        __nv_bfloat16 h = __float2bfloat16(v);
        hh[j] = h;
        ll[j] = __float2bfloat16(v - __bfloat162float(h));
    }
    *(uint4*)(h1h + (size_t)w * C1 + lane * 8) = *(const uint4*)hh;
    *(uint4*)(h1l + (size_t)w * C1 + lane * 8) = *(const uint4*)ll;
}

// ---------------- fused edge phase layer 2 + final linear head --------------
__global__ __launch_bounds__(256)
void edge_fused2_head_k(const int* __restrict__ rowptr, const int* __restrict__ deg,
                        const int* __restrict__ csrc,
                        const float* __restrict__ xl, const float* __restrict__ xr,
                        const float* __restrict__ att, const float* __restrict__ bias,
                        const float* __restrict__ Wlin, const float* __restrict__ blin,
                        float* __restrict__ out)
{
    __shared__ float Ws[HIDC][OUTDIM];      // 32x64 = 8 KB
    __shared__ float bs[OUTDIM];

    for (int i = threadIdx.x; i < HIDC * OUTDIM; i += blockDim.x)
        Ws[i >> 6][i & 63] = Wlin[i];
    if (threadIdx.x < OUTDIM) bs[threadIdx.x] = blin[threadIdx.x];
    __syncthreads();

    int w = (blockIdx.x * blockDim.x + threadIdx.x) >> 5;
    int lane = threadIdx.x & 31;
    if (w >= NN) return;

    float b = xr[(size_t)w * HIDC + lane];
    float t = att[lane];

    float acc = 0.f, den = 0.f;
    int start = rowptr[w];
    int dg    = deg[w];

    int s = (dg > 0) ? csrc[start] : 0;
    float a = xl[(size_t)s * HIDC + lane];

    for (int i = 0; i < dg; i++) {
        int snext = (i + 1 < dg) ? csrc[start + i + 1] : s;
        float n = xl[(size_t)snext * HIDC + lane];

        float p = lrelu(a + b) * t;
        p += __shfl_xor_sync(0xffffffffu, p, 16);
        p += __shfl_xor_sync(0xffffffffu, p, 8);
        p += __shfl_xor_sync(0xffffffffu, p, 4);
        p += __shfl_xor_sync(0xffffffffu, p, 2);
        p += __shfl_xor_sync(0xffffffffu, p, 1);
        float ex = __expf(p);
        den += ex;
        acc += ex * a;

        a = n;
    }
    float inv = 1.f / (den + 1e-16f);
    float hval = elu(acc * inv + bias[lane]);   // h2[w][lane]

    float o0 = bs[lane];
    float o1 = bs[lane + 32];
#pragma unroll
    for (int k = 0; k < HIDC; k++) {
        float v = __shfl_sync(0xffffffffu, hval, k);
        o0 = fmaf(v, Ws[k][lane],      o0);
        o1 = fmaf(v, Ws[k][lane + 32], o1);
    }
    out[(size_t)w * OUTDIM + lane]      = o0;
    out[(size_t)w * OUTDIM + lane + 32] = o1;
}

// ---------------- launch ------------------------------------------------------
extern "C" void kernel_launch(void* const* d_in, const int* in_sizes, int n_in,
                              void* d_out, int out_size)
{
    const float* x     = (const float*)d_in[0];
    const int*   ei    = (const int*)d_in[1];
    const float* W1l   = (const float*)d_in[2];
    const float* b1l   = (const float*)d_in[3];
    const float* W1r   = (const float*)d_in[4];
    const float* b1r   = (const float*)d_in[5];
    const float* att1  = (const float*)d_in[6];
    const float* bias1 = (const float*)d_in[7];
    const float* W2l   = (const float*)d_in[8];
    const float* b2l   = (const float*)d_in[9];
    const float* W2r   = (const float*)d_in[10];
    const float* b2r   = (const float*)d_in[11];
    const float* att2  = (const float*)d_in[12];
    const float* bias2 = (const float*)d_in[13];
    const float* Wlin  = (const float*)d_in[14];
    const float* blin  = (const float*)d_in[15];
    float* out = (float*)d_out;

    float *xl1, *xr1, *xl2, *xr2;
    int *deg, *rowptr, *cursor, *csrc, *bsums;
    __nv_bfloat16 *Ah, *Al, *Bh, *Bl, *H1h, *H1l, *B2h, *B2l;
    cudaGetSymbolAddress((void**)&xl1, g_xl1);
    cudaGetSymbolAddress((void**)&xr1, g_xr1);
    cudaGetSymbolAddress((void**)&xl2, g_xl2);
    cudaGetSymbolAddress((void**)&xr2, g_xr2);
    cudaGetSymbolAddress((void**)&deg,    g_deg);
    cudaGetSymbolAddress((void**)&rowptr, g_rowptr);
    cudaGetSymbolAddress((void**)&cursor, g_cursor);
    cudaGetSymbolAddress((void**)&csrc,   g_csrc);
    cudaGetSymbolAddress((void**)&bsums,  g_bsums);
    cudaGetSymbolAddress((void**)&Ah,  g_Ah);
    cudaGetSymbolAddress((void**)&Al,  g_Al);
    cudaGetSymbolAddress((void**)&Bh,  g_Bh);
    cudaGetSymbolAddress((void**)&Bl,  g_Bl);
    cudaGetSymbolAddress((void**)&H1h, g_H1h);
    cudaGetSymbolAddress((void**)&H1l, g_H1l);
    cudaGetSymbolAddress((void**)&B2h, g_B2h);
    cudaGetSymbolAddress((void**)&B2l, g_B2l);

    cudaFuncSetAttribute(gemm1_mma, cudaFuncAttributeMaxDynamicSharedMemorySize,
                         SMEM_BYTES);
    cudaFuncSetAttribute(gemm2_mma, cudaFuncAttributeMaxDynamicSharedMemorySize,
                         SMEM2_BYTES);

    const int TPB = 256;
    const int nScanBlocks = (NN + 255) / 256;       // 196

    conv_x_k<<<(NN * INDIM + TPB - 1) / TPB, TPB>>>(x, Ah, Al);           // 0
    conv_w_k<<<(NB * INDIM + TPB - 1) / TPB, TPB>>>(W1l, W1r, Bh, Bl);    // 1
    zero_deg_k<<<(NN + TPB - 1) / TPB, TPB>>>(deg);                       // 2

    dim3 gg1(4, (NN + 127) / 128);
    gemm1_mma<<<gg1, TPB, SMEM_BYTES>>>(Ah, Al, Bh, Bl,
                                        b1l, b1r, xl1, xr1);              // 3 (profiled)

    conv_w2_k<<<(NB2 * C1 + TPB - 1) / TPB, TPB>>>(W2l, W2r, B2h, B2l);   // 4
    hist_k<<<(EE + TPB - 1) / TPB, TPB>>>(ei, deg);                       // 5
    scan1_k<<<nScanBlocks, 256>>>(deg, rowptr, bsums);                    // 6
    scan2_k<<<1, 256>>>(bsums, nScanBlocks);                              // 7
    scan3_k<<<(NN + TPB - 1) / TPB, TPB>>>(rowptr, bsums, cursor);        // 8
    scatter_k<<<(EE + TPB - 1) / TPB, TPB>>>(ei, cursor, csrc);           // 9

    int eblocks = (NN * 32 + TPB - 1) / TPB;
    edge_fused1_k<<<eblocks, TPB>>>(rowptr, deg, csrc, xl1, xr1,
                                    att1, bias1, H1h, H1l);               // 10

    gemm2_mma<<<(NN + 127) / 128, TPB, SMEM2_BYTES>>>(H1h, H1l, B2h, B2l,
                                                      b2l, b2r, xl2, xr2); // 11

    edge_fused2_head_k<<<eblocks, TPB>>>(rowptr, deg, csrc, xl2, xr2,
                                         att2, bias2, Wlin, blin, out);   // 12
}

// round 12
// speedup vs baseline: 3.7295x; 1.0549x over previous
#include <cuda_runtime.h>
#include <cuda_bf16.h>
#include <cstdint>

#define NN      50000
#define EE      800000
#define INDIM   256
#define HIDC    32
#define NHEADS  8
#define OUTDIM  64
#define C1      (NHEADS * HIDC)   // 256
#define NB      512               // total output cols of GEMM1 (Wl|Wr)
#define NB2     64                // total output cols of GEMM2 (W2l|W2r)
#define NEGSLOPE 0.2f

typedef unsigned long long u64;

// ---------------- scratch (device globals) ---------------------------------
__device__ float g_xl1[(size_t)NN * C1];
__device__ float g_xr1[(size_t)NN * C1];
__device__ float g_xl2[(size_t)NN * HIDC];
__device__ float g_xr2[(size_t)NN * HIDC];
__device__ int   g_deg   [NN];
__device__ int   g_rowptr[NN];
__device__ int   g_cursor[NN];
__device__ int   g_csrc  [EE];
__device__ int   g_bsums [256];
// bf16 split operands
__device__ __align__(16) __nv_bfloat16 g_Ah[(size_t)NN * INDIM];
__device__ __align__(16) __nv_bfloat16 g_Al[(size_t)NN * INDIM];
__device__ __align__(16) __nv_bfloat16 g_Bh[(size_t)NB * INDIM];
__device__ __align__(16) __nv_bfloat16 g_Bl[(size_t)NB * INDIM];
__device__ __align__(16) __nv_bfloat16 g_H1h[(size_t)NN * C1];   // h1 hi
__device__ __align__(16) __nv_bfloat16 g_H1l[(size_t)NN * C1];   // h1 lo
__device__ __align__(16) __nv_bfloat16 g_B2h[(size_t)NB2 * C1];
__device__ __align__(16) __nv_bfloat16 g_B2l[(size_t)NB2 * C1];

// ---------------- helpers ---------------------------------------------------
__device__ __forceinline__ float lrelu(float v) { return v > 0.f ? v : NEGSLOPE * v; }
__device__ __forceinline__ float elu(float v)   { return v > 0.f ? v : expm1f(v); }

__device__ __forceinline__ uint32_t smem_u32(const void* p)
{
    uint32_t a;
    asm("{ .reg .u64 t; cvta.to.shared.u64 t, %1; cvt.u32.u64 %0, t; }"
        : "=r"(a) : "l"(p));
    return a;
}

// bf16 tensor-core mma (sm_80+ base)
#define MMA_BF16(d, a0, a1, a2, a3, b0, b1)                                  \
    asm volatile(                                                            \
        "mma.sync.aligned.m16n8k16.row.col.f32.bf16.bf16.f32 "               \
        "{%0,%1,%2,%3}, {%4,%5,%6,%7}, {%8,%9}, {%0,%1,%2,%3};"              \
        : "+f"((d)[0]), "+f"((d)[1]), "+f"((d)[2]), "+f"((d)[3])             \
        : "r"(a0), "r"(a1), "r"(a2), "r"(a3), "r"(b0), "r"(b1))

// ldmatrix (sm_75+ base)
#define LDSM_X4(r0, r1, r2, r3, addr)                                        \
    asm volatile("ldmatrix.sync.aligned.m8n8.x4.shared.b16 {%0,%1,%2,%3}, [%4];" \
                 : "=r"(r0), "=r"(r1), "=r"(r2), "=r"(r3) : "r"(addr))

// cp.async (sm_80+ base)
#define CP16(dst_u32, src_ptr) \
    asm volatile("cp.async.cg.shared.global [%0], [%1], 16;" \
                 :: "r"(dst_u32), "l"(src_ptr))
#define CP_COMMIT() asm volatile("cp.async.commit_group;" ::: "memory")
#define CP_WAIT(n)  asm volatile("cp.async.wait_group %0;" :: "n"(n) : "memory")

// ---------------- conversion kernels -----------------------------------------
__global__ void conv_x_k(const float* __restrict__ x,
                         __nv_bfloat16* __restrict__ Ah,
                         __nv_bfloat16* __restrict__ Al)
{
    size_t i = (size_t)blockIdx.x * blockDim.x + threadIdx.x;
    if (i >= (size_t)NN * INDIM) return;
    float v = x[i];
    __nv_bfloat16 h = __float2bfloat16(v);
    Ah[i] = h;
    Al[i] = __float2bfloat16(v - __bfloat162float(h));
}

__global__ void conv_w_k(const float* __restrict__ W1l, const float* __restrict__ W1r,
                         __nv_bfloat16* __restrict__ Bh, __nv_bfloat16* __restrict__ Bl)
{
    int i = blockIdx.x * blockDim.x + threadIdx.x;
    if (i >= NB * INDIM) return;
    int n = i >> 8;
    int k = i & 255;
    float v = (n < C1) ? W1l[(size_t)k * C1 + n] : W1r[(size_t)k * C1 + (n - C1)];
    __nv_bfloat16 h = __float2bfloat16(v);
    Bh[i] = h;
    Bl[i] = __float2bfloat16(v - __bfloat162float(h));
}

__global__ void conv_w2_k(const float* __restrict__ W2l, const float* __restrict__ W2r,
                          __nv_bfloat16* __restrict__ B2h, __nv_bfloat16* __restrict__ B2l)
{
    int i = blockIdx.x * blockDim.x + threadIdx.x;
    if (i >= NB2 * C1) return;
    int n = i >> 8;          // 0..63
    int k = i & 255;
    float v = (n < HIDC) ? W2l[(size_t)k * HIDC + n]
                         : W2r[(size_t)k * HIDC + (n - HIDC)];
    __nv_bfloat16 h = __float2bfloat16(v);
    B2h[i] = h;
    B2l[i] = __float2bfloat16(v - __bfloat162float(h));
}

// ============================================================================
// GEMM1 via mma.sync bf16 3-product split, cp.async double-buffered, ldmatrix.
// CTA 128(M) x 128(N), K chunk 32. 8 warps = 2(M) x 4(N), warp tile 64x32.
// ============================================================================
#define KCH    32
#define PAD2   40
#define T_ELEM (128 * PAD2)
#define T_BYTE (T_ELEM * 2)          // 10240
#define STG_BYTE (4 * T_BYTE)        // 40960
#define SMEM_BYTES (2 * STG_BYTE)    // 81920

__global__ __launch_bounds__(256)
void gemm1_mma(const __nv_bfloat16* __restrict__ Ah, const __nv_bfloat16* __restrict__ Al,
               const __nv_bfloat16* __restrict__ Bh, const __nv_bfloat16* __restrict__ Bl,
               const float* __restrict__ bl1, const float* __restrict__ br1,
               float* __restrict__ Xl, float* __restrict__ Xr)
{
    extern __shared__ __nv_bfloat16 sm[];
    const uint32_t smb = smem_u32(sm);

    const int tid  = threadIdx.x;
    const int wid  = tid >> 5;
    const int lane = tid & 31;
    const int wm   = wid & 1;
    const int wn   = wid >> 1;
    const int rowBase = blockIdx.y * 128;
    const int colBase = blockIdx.x * 128;

    const int lr = lane >> 2;
    const int lc = (lane & 3) * 2;

    const int aRowOff = lane & 15;
    const int aKOff   = (lane >> 4) * 8;
    const int bGrp    = lane >> 3;
    const int bRowOff = (lane & 7) + (bGrp >> 1) * 8;
    const int bKOff   = (bGrp & 1) * 8;

#define LOAD_STAGE(stg, kOff) do {                                            \
    uint32_t sb = smb + (stg) * STG_BYTE;                                     \
    for (int idx = tid; idx < 512; idx += 256) {                              \
        int r  = idx >> 2;                                                    \
        int k8 = (idx & 3) * 8;                                               \
        uint32_t soff = (uint32_t)(r * (PAD2 * 2) + k8 * 2);                  \
        int ga = min(rowBase + r, NN - 1);                                    \
        int gb = colBase + r;                                                 \
        CP16(sb + soff,              Ah + (size_t)ga * INDIM + (kOff) + k8);  \
        CP16(sb + T_BYTE + soff,     Al + (size_t)ga * INDIM + (kOff) + k8);  \
        CP16(sb + 2 * T_BYTE + soff, Bh + (size_t)gb * INDIM + (kOff) + k8);  \
        CP16(sb + 3 * T_BYTE + soff, Bl + (size_t)gb * INDIM + (kOff) + k8);  \
    }                                                                         \
} while (0)

    float acc[4][4][4];
#pragma unroll
    for (int i = 0; i < 4; i++)
#pragma unroll
        for (int j = 0; j < 4; j++)
#pragma unroll
            for (int f = 0; f < 4; f++) acc[i][j][f] = 0.f;

    LOAD_STAGE(0, 0);
    CP_COMMIT();

    for (int kc = 0; kc < 8; kc++) {
        const int stg = kc & 1;
        if (kc + 1 < 8) {
            LOAD_STAGE((kc + 1) & 1, (kc + 1) * KCH);
            CP_COMMIT();
            CP_WAIT(1);
        } else {
            CP_WAIT(0);
        }
        __syncthreads();

        const uint32_t sAh_u = smb + stg * STG_BYTE;
        const uint32_t sAl_u = sAh_u + T_BYTE;
        const uint32_t sBh_u = sAh_u + 2 * T_BYTE;
        const uint32_t sBl_u = sAh_u + 3 * T_BYTE;

#pragma unroll
        for (int ks = 0; ks < 2; ks++) {
            const int k0 = ks * 16;
            uint32_t bh[4][2], bl_[4][2];
#pragma unroll
            for (int jp = 0; jp < 4; jp += 2) {
                uint32_t baddr = (uint32_t)(((wn * 32 + jp * 8 + bRowOff) * PAD2
                                            + k0 + bKOff) * 2);
                LDSM_X4(bh[jp][0], bh[jp][1], bh[jp + 1][0], bh[jp + 1][1],
                        sBh_u + baddr);
                LDSM_X4(bl_[jp][0], bl_[jp][1], bl_[jp + 1][0], bl_[jp + 1][1],
                        sBl_u + baddr);
            }
#pragma unroll
            for (int i = 0; i < 4; i++) {
                uint32_t aaddr = (uint32_t)(((wm * 64 + i * 16 + aRowOff) * PAD2
                                            + k0 + aKOff) * 2);
                uint32_t ah0, ah1, ah2, ah3, al0, al1, al2, al3;
                LDSM_X4(ah0, ah1, ah2, ah3, sAh_u + aaddr);
                LDSM_X4(al0, al1, al2, al3, sAl_u + aaddr);
#pragma unroll
                for (int j = 0; j < 4; j++)
                    MMA_BF16(acc[i][j], ah0, ah1, ah2, ah3, bh[j][0], bh[j][1]);
#pragma unroll
                for (int j = 0; j < 4; j++)
                    MMA_BF16(acc[i][j], ah0, ah1, ah2, ah3, bl_[j][0], bl_[j][1]);
#pragma unroll
                for (int j = 0; j < 4; j++)
                    MMA_BF16(acc[i][j], al0, al1, al2, al3, bh[j][0], bh[j][1]);
            }
        }
        __syncthreads();
    }

    // ---- epilogue ----
    const bool isL = (colBase < C1);
    float* X = isL ? Xl : Xr;
    const float* bs = isL ? bl1 : br1;
    const int cb = isL ? colBase : colBase - C1;
#pragma unroll
    for (int i = 0; i < 4; i++) {
        int r0 = rowBase + wm * 64 + i * 16 + lr;
#pragma unroll
        for (int j = 0; j < 4; j++) {
            int c = cb + wn * 32 + j * 8 + lc;
            float b0 = bs[c], b1 = bs[c + 1];
            if (r0 < NN) {
                float2 o = make_float2(acc[i][j][0] + b0, acc[i][j][1] + b1);
                *(float2*)(X + (size_t)r0 * C1 + c) = o;
            }
            if (r0 + 8 < NN) {
                float2 o = make_float2(acc[i][j][2] + b0, acc[i][j][3] + b1);
                *(float2*)(X + (size_t)(r0 + 8) * C1 + c) = o;
            }
        }
    }
#undef LOAD_STAGE
}

// ============================================================================
// GEMM2 via mma.sync bf16 3-product split. CTA 128(M) x 64(N), K=256 chunk 32.
// ============================================================================
#define B2_ROWS  64
#define B2_ELEM  (B2_ROWS * PAD2)     // 2560
#define B2_BYTE  (B2_ELEM * 2)        // 5120
#define STG2_BYTE (2 * T_BYTE + 2 * B2_BYTE)   // 30720
#define SMEM2_BYTES (2 * STG2_BYTE)            // 61440

__global__ __launch_bounds__(256)
void gemm2_mma(const __nv_bfloat16* __restrict__ Ah, const __nv_bfloat16* __restrict__ Al,
               const __nv_bfloat16* __restrict__ Bh, const __nv_bfloat16* __restrict__ Bl,
               const float* __restrict__ bl2, const float* __restrict__ br2,
               float* __restrict__ Xl, float* __restrict__ Xr)
{
    extern __shared__ __nv_bfloat16 sm[];
    const uint32_t smb = smem_u32(sm);

    const int tid  = threadIdx.x;
    const int wid  = tid >> 5;
    const int lane = tid & 31;
    const int wm   = wid & 1;
    const int wn   = wid >> 1;
    const int rowBase = blockIdx.x * 128;

    const int lr = lane >> 2;
    const int lc = (lane & 3) * 2;

    const int aRowOff = lane & 15;
    const int aKOff   = (lane >> 4) * 8;
    const int bGrp    = lane >> 3;
    const int bRowOff = (lane & 7) + (bGrp >> 1) * 8;
    const int bKOff   = (bGrp & 1) * 8;

#define LOAD_STAGE2(stg, kOff) do {                                           \
    uint32_t sb = smb + (stg) * STG2_BYTE;                                    \
    for (int idx = tid; idx < 512; idx += 256) {                              \
        int r  = idx >> 2;                                                    \
        int k8 = (idx & 3) * 8;                                               \
        uint32_t soff = (uint32_t)(r * (PAD2 * 2) + k8 * 2);                  \
        int ga = min(rowBase + r, NN - 1);                                    \
        CP16(sb + soff,          Ah + (size_t)ga * C1 + (kOff) + k8);         \
        CP16(sb + T_BYTE + soff, Al + (size_t)ga * C1 + (kOff) + k8);         \
    }                                                                         \
    {                                                                         \
        int r  = tid >> 2;                                                    \
        int k8 = (tid & 3) * 8;                                               \
        uint32_t soff = (uint32_t)(r * (PAD2 * 2) + k8 * 2);                  \
        CP16(sb + 2 * T_BYTE + soff,           Bh + (size_t)r * C1 + (kOff) + k8); \
        CP16(sb + 2 * T_BYTE + B2_BYTE + soff, Bl + (size_t)r * C1 + (kOff) + k8); \
    }                                                                         \
} while (0)

    float acc[4][2][4];
#pragma unroll
    for (int i = 0; i < 4; i++)
#pragma unroll
        for (int j = 0; j < 2; j++)
#pragma unroll
            for (int f = 0; f < 4; f++) acc[i][j][f] = 0.f;

    LOAD_STAGE2(0, 0);
    CP_COMMIT();

    for (int kc = 0; kc < 8; kc++) {
        const int stg = kc & 1;
        if (kc + 1 < 8) {
            LOAD_STAGE2((kc + 1) & 1, (kc + 1) * KCH);
            CP_COMMIT();
            CP_WAIT(1);
        } else {
            CP_WAIT(0);
        }
        __syncthreads();

        const uint32_t sAh_u = smb + stg * STG2_BYTE;
        const uint32_t sAl_u = sAh_u + T_BYTE;
        const uint32_t sBh_u = sAh_u + 2 * T_BYTE;
        const uint32_t sBl_u = sBh_u + B2_BYTE;

#pragma unroll
        for (int ks = 0; ks < 2; ks++) {
            const int k0 = ks * 16;
            uint32_t bh[2][2], bl_[2][2];
            {
                uint32_t baddr = (uint32_t)(((wn * 16 + bRowOff) * PAD2
                                            + k0 + bKOff) * 2);
                LDSM_X4(bh[0][0], bh[0][1], bh[1][0], bh[1][1], sBh_u + baddr);
                LDSM_X4(bl_[0][0], bl_[0][1], bl_[1][0], bl_[1][1], sBl_u + baddr);
            }
#pragma unroll
            for (int i = 0; i < 4; i++) {
                uint32_t aaddr = (uint32_t)(((wm * 64 + i * 16 + aRowOff) * PAD2
                                            + k0 + aKOff) * 2);
                uint32_t ah0, ah1, ah2, ah3, al0, al1, al2, al3;
                LDSM_X4(ah0, ah1, ah2, ah3, sAh_u + aaddr);
                LDSM_X4(al0, al1, al2, al3, sAl_u + aaddr);
#pragma unroll
                for (int j = 0; j < 2; j++)
                    MMA_BF16(acc[i][j], ah0, ah1, ah2, ah3, bh[j][0], bh[j][1]);
#pragma unroll
                for (int j = 0; j < 2; j++)
                    MMA_BF16(acc[i][j], ah0, ah1, ah2, ah3, bl_[j][0], bl_[j][1]);
#pragma unroll
                for (int j = 0; j < 2; j++)
                    MMA_BF16(acc[i][j], al0, al1, al2, al3, bh[j][0], bh[j][1]);
            }
        }
        __syncthreads();
    }

    const bool isL = (wn < 2);
    float* X = isL ? Xl : Xr;
    const float* bs = isL ? bl2 : br2;
    const int cb = isL ? wn * 16 : wn * 16 - HIDC;
#pragma unroll
    for (int i = 0; i < 4; i++) {
        int r0 = rowBase + wm * 64 + i * 16 + lr;
#pragma unroll
        for (int j = 0; j < 2; j++) {
            int c = cb + j * 8 + lc;
            float b0 = bs[c], b1 = bs[c + 1];
            if (r0 < NN) {
                float2 o = make_float2(acc[i][j][0] + b0, acc[i][j][1] + b1);
                *(float2*)(X + (size_t)r0 * HIDC + c) = o;
            }
            if (r0 + 8 < NN) {
                float2 o = make_float2(acc[i][j][2] + b0, acc[i][j][3] + b1);
                *(float2*)(X + (size_t)(r0 + 8) * HIDC + c) = o;
            }
        }
    }
#undef LOAD_STAGE2
}

// ---------------- CSR construction ------------------------------------------
__global__ void zero_deg_k(int* __restrict__ deg)
{
    int i = blockIdx.x * blockDim.x + threadIdx.x;
    if (i < NN) deg[i] = 0;
}

__global__ void hist_k(const int* __restrict__ ei, int* __restrict__ deg)
{
    int e = blockIdx.x * blockDim.x + threadIdx.x;
    if (e < EE) atomicAdd(&deg[ei[EE + e]], 1);
}

__global__ void scan1_k(const int* __restrict__ deg, int* __restrict__ rowptr,
                        int* __restrict__ bsums)
{
    __shared__ int sh[256];
    int tid = threadIdx.x;
    int i = blockIdx.x * 256 + tid;
    int v = (i < NN) ? deg[i] : 0;
    sh[tid] = v;
    __syncthreads();
#pragma unroll
    for (int off = 1; off < 256; off <<= 1) {
        int t = (tid >= off) ? sh[tid - off] : 0;
        __syncthreads();
        sh[tid] += t;
        __syncthreads();
    }
    if (i < NN) rowptr[i] = sh[tid] - v;
    if (tid == 255) bsums[blockIdx.x] = sh[255];
}

__global__ void scan2_k(int* __restrict__ bsums, int nb)
{
    __shared__ int sh[256];
    int tid = threadIdx.x;
    int v = (tid < nb) ? bsums[tid] : 0;
    sh[tid] = v;
    __syncthreads();
#pragma unroll
    for (int off = 1; off < 256; off <<= 1) {
        int t = (tid >= off) ? sh[tid - off] : 0;
        __syncthreads();
        sh[tid] += t;
        __syncthreads();
    }
    if (tid < nb) bsums[tid] = sh[tid] - v;
}

__global__ void scan3_k(int* __restrict__ rowptr, const int* __restrict__ bsums,
                        int* __restrict__ cursor)
{
    int i = blockIdx.x * blockDim.x + threadIdx.x;
    if (i >= NN) return;
    int r = rowptr[i] + bsums[i >> 8];
    rowptr[i] = r;
    cursor[i] = r;
}

__global__ void scatter_k(const int* __restrict__ ei, int* __restrict__ cursor,
                          int* __restrict__ csrc)
{
    int e = blockIdx.x * blockDim.x + threadIdx.x;
    if (e >= EE) return;
    int d = ei[EE + e];
    int pos = atomicAdd(&cursor[d], 1);
    csrc[pos] = ei[e];
}

// ---------------- fused GATv2 edge phase, layer 1 ---------------------------
__global__ __launch_bounds__(256)
void edge_fused1_k(const int* __restrict__ rowptr, const int* __restrict__ deg,
                   const int* __restrict__ csrc,
                   const float* __restrict__ xl, const float* __restrict__ xr,
                   const float* __restrict__ att, const float* __restrict__ bias,
                   __nv_bfloat16* __restrict__ h1h, __nv_bfloat16* __restrict__ h1l)
{
    int w = (blockIdx.x * blockDim.x + threadIdx.x) >> 5;
    if (w >= NN) return;
    int lane = threadIdx.x & 31;

    const float4* pb = reinterpret_cast<const float4*>(xr + (size_t)w * C1 + lane * 8);
    float4 b0 = pb[0], b1 = pb[1];
    const float4* pt = reinterpret_cast<const float4*>(att + lane * 8);
    float4 t0 = pt[0], t1 = pt[1];

    float acc[8] = {};
    float den = 0.f;

    int start = rowptr[w];
    int dg    = deg[w];

    int s = (dg > 0) ? csrc[start] : 0;
    const float4* pa = reinterpret_cast<const float4*>(xl + (size_t)s * C1 + lane * 8);
    float4 a0 = pa[0], a1 = pa[1];

    for (int i = 0; i < dg; i++) {
        int snext = (i + 1 < dg) ? csrc[start + i + 1] : s;
        const float4* pn = reinterpret_cast<const float4*>(
            xl + (size_t)snext * C1 + lane * 8);
        float4 n0 = pn[0], n1 = pn[1];

        float p = lrelu(a0.x + b0.x) * t0.x + lrelu(a0.y + b0.y) * t0.y
                + lrelu(a0.z + b0.z) * t0.z + lrelu(a0.w + b0.w) * t0.w
                + lrelu(a1.x + b1.x) * t1.x + lrelu(a1.y + b1.y) * t1.y
                + lrelu(a1.z + b1.z) * t1.z + lrelu(a1.w + b1.w) * t1.w;
        p += __shfl_xor_sync(0xffffffffu, p, 1);
        p += __shfl_xor_sync(0xffffffffu, p, 2);
        float ex = __expf(p);
        den += ex;
        acc[0] += ex * a0.x; acc[1] += ex * a0.y;
        acc[2] += ex * a0.z; acc[3] += ex * a0.w;
        acc[4] += ex * a1.x; acc[5] += ex * a1.y;
        acc[6] += ex * a1.z; acc[7] += ex * a1.w;

        a0 = n0; a1 = n1;
    }

    float inv = 1.f / (den + 1e-16f);
    const float* bi = bias + lane * 8;
    __nv_bfloat16 hh[8], ll[8];
#pragma unroll
    for (int j = 0; j < 8; j++) {
        float v = elu(acc[j] * inv + bi[j]);
        __nv_bfloat16 h = __float2bfloat16(v);
        hh[j] = h;
        ll[j] = __float2bfloat16(v - __bfloat162float(h));
    }
    *(uint4*)(h1h + (size_t)w * C1 + lane * 8) = *(const uint4*)hh;
    *(uint4*)(h1l + (size_t)w * C1 + lane * 8) = *(const uint4*)ll;
}

// ---------------- fused edge phase layer 2 + final linear head --------------
__global__ __launch_bounds__(256)
void edge_fused2_head_k(const int* __restrict__ rowptr, const int* __restrict__ deg,
                        const int* __restrict__ csrc,
                        const float* __restrict__ xl, const float* __restrict__ xr,
                        const float* __restrict__ att, const float* __restrict__ bias,
                        const float* __restrict__ Wlin, const float* __restrict__ blin,
                        float* __restrict__ out)
{
    __shared__ float Ws[HIDC][OUTDIM];      // 32x64 = 8 KB
    __shared__ float bs[OUTDIM];

    for (int i = threadIdx.x; i < HIDC * OUTDIM; i += blockDim.x)
        Ws[i >> 6][i & 63] = Wlin[i];
    if (threadIdx.x < OUTDIM) bs[threadIdx.x] = blin[threadIdx.x];
    __syncthreads();

    int w = (blockIdx.x * blockDim.x + threadIdx.x) >> 5;
    int lane = threadIdx.x & 31;
    if (w >= NN) return;

    float b = xr[(size_t)w * HIDC + lane];
    float t = att[lane];

    float acc = 0.f, den = 0.f;
    int start = rowptr[w];
    int dg    = deg[w];

    int s = (dg > 0) ? csrc[start] : 0;
    float a = xl[(size_t)s * HIDC + lane];

    for (int i = 0; i < dg; i++) {
        int snext = (i + 1 < dg) ? csrc[start + i + 1] : s;
        float n = xl[(size_t)snext * HIDC + lane];

        float p = lrelu(a + b) * t;
        p += __shfl_xor_sync(0xffffffffu, p, 16);
        p += __shfl_xor_sync(0xffffffffu, p, 8);
        p += __shfl_xor_sync(0xffffffffu, p, 4);
        p += __shfl_xor_sync(0xffffffffu, p, 2);
        p += __shfl_xor_sync(0xffffffffu, p, 1);
        float ex = __expf(p);
        den += ex;
        acc += ex * a;

        a = n;
    }
    float inv = 1.f / (den + 1e-16f);
    float hval = elu(acc * inv + bias[lane]);   // h2[w][lane]

    float o0 = bs[lane];
    float o1 = bs[lane + 32];
#pragma unroll
    for (int k = 0; k < HIDC; k++) {
        float v = __shfl_sync(0xffffffffu, hval, k);
        o0 = fmaf(v, Ws[k][lane],      o0);
        o1 = fmaf(v, Ws[k][lane + 32], o1);
    }
    out[(size_t)w * OUTDIM + lane]      = o0;
    out[(size_t)w * OUTDIM + lane + 32] = o1;
}

// ---------------- launch ------------------------------------------------------
extern "C" void kernel_launch(void* const* d_in, const int* in_sizes, int n_in,
                              void* d_out, int out_size)
{
    const float* x     = (const float*)d_in[0];
    const int*   ei    = (const int*)d_in[1];
    const float* W1l   = (const float*)d_in[2];
    const float* b1l   = (const float*)d_in[3];
    const float* W1r   = (const float*)d_in[4];
    const float* b1r   = (const float*)d_in[5];
    const float* att1  = (const float*)d_in[6];
    const float* bias1 = (const float*)d_in[7];
    const float* W2l   = (const float*)d_in[8];
    const float* b2l   = (const float*)d_in[9];
    const float* W2r   = (const float*)d_in[10];
    const float* b2r   = (const float*)d_in[11];
    const float* att2  = (const float*)d_in[12];
    const float* bias2 = (const float*)d_in[13];
    const float* Wlin  = (const float*)d_in[14];
    const float* blin  = (const float*)d_in[15];
    float* out = (float*)d_out;

    float *xl1, *xr1, *xl2, *xr2;
    int *deg, *rowptr, *cursor, *csrc, *bsums;
    __nv_bfloat16 *Ah, *Al, *Bh, *Bl, *H1h, *H1l, *B2h, *B2l;
    cudaGetSymbolAddress((void**)&xl1, g_xl1);
    cudaGetSymbolAddress((void**)&xr1, g_xr1);
    cudaGetSymbolAddress((void**)&xl2, g_xl2);
    cudaGetSymbolAddress((void**)&xr2, g_xr2);
    cudaGetSymbolAddress((void**)&deg,    g_deg);
    cudaGetSymbolAddress((void**)&rowptr, g_rowptr);
    cudaGetSymbolAddress((void**)&cursor, g_cursor);
    cudaGetSymbolAddress((void**)&csrc,   g_csrc);
    cudaGetSymbolAddress((void**)&bsums,  g_bsums);
    cudaGetSymbolAddress((void**)&Ah,  g_Ah);
    cudaGetSymbolAddress((void**)&Al,  g_Al);
    cudaGetSymbolAddress((void**)&Bh,  g_Bh);
    cudaGetSymbolAddress((void**)&Bl,  g_Bl);
    cudaGetSymbolAddress((void**)&H1h, g_H1h);
    cudaGetSymbolAddress((void**)&H1l, g_H1l);
    cudaGetSymbolAddress((void**)&B2h, g_B2h);
    cudaGetSymbolAddress((void**)&B2l, g_B2l);

    cudaFuncSetAttribute(gemm1_mma, cudaFuncAttributeMaxDynamicSharedMemorySize,
                         SMEM_BYTES);
    cudaFuncSetAttribute(gemm2_mma, cudaFuncAttributeMaxDynamicSharedMemorySize,
                         SMEM2_BYTES);

    const int TPB = 256;
    const int nScanBlocks = (NN + 255) / 256;       // 196

    // ---- stream fork: CSR build runs concurrently with conv + GEMM1 ----
    cudaStream_t s2;
    cudaStreamCreateWithFlags(&s2, cudaStreamNonBlocking);
    cudaEvent_t e1, e2;
    cudaEventCreateWithFlags(&e1, cudaEventDisableTiming);
    cudaEventCreateWithFlags(&e2, cudaEventDisableTiming);

    cudaEventRecord(e1, 0);
    cudaStreamWaitEvent(s2, e1, 0);

    // side stream: CSR pipeline + W2 conversion (independent of GEMM1 chain)
    zero_deg_k<<<(NN + TPB - 1) / TPB, TPB, 0, s2>>>(deg);
    hist_k<<<(EE + TPB - 1) / TPB, TPB, 0, s2>>>(ei, deg);
    scan1_k<<<nScanBlocks, 256, 0, s2>>>(deg, rowptr, bsums);
    scan2_k<<<1, 256, 0, s2>>>(bsums, nScanBlocks);
    scan3_k<<<(NN + TPB - 1) / TPB, TPB, 0, s2>>>(rowptr, bsums, cursor);
    scatter_k<<<(EE + TPB - 1) / TPB, TPB, 0, s2>>>(ei, cursor, csrc);
    conv_w2_k<<<(NB2 * C1 + TPB - 1) / TPB, TPB, 0, s2>>>(W2l, W2r, B2h, B2l);
    cudaEventRecord(e2, s2);

    // main stream: conversions + GEMM1
    conv_x_k<<<(NN * INDIM + TPB - 1) / TPB, TPB>>>(x, Ah, Al);
    conv_w_k<<<(NB * INDIM + TPB - 1) / TPB, TPB>>>(W1l, W1r, Bh, Bl);

    dim3 gg1(4, (NN + 127) / 128);
    gemm1_mma<<<gg1, TPB, SMEM_BYTES>>>(Ah, Al, Bh, Bl, b1l, b1r, xl1, xr1);

    // join: edge phase needs both GEMM1 outputs and CSR
    cudaStreamWaitEvent(0, e2, 0);

    int eblocks = (NN * 32 + TPB - 1) / TPB;
    edge_fused1_k<<<eblocks, TPB>>>(rowptr, deg, csrc, xl1, xr1,
                                    att1, bias1, H1h, H1l);

    gemm2_mma<<<(NN + 127) / 128, TPB, SMEM2_BYTES>>>(H1h, H1l, B2h, B2l,
                                                      b2l, b2r, xl2, xr2);

    edge_fused2_head_k<<<eblocks, TPB>>>(rowptr, deg, csrc, xl2, xr2,
                                         att2, bias2, Wlin, blin, out);
}